// round 1
// baseline (speedup 1.0000x reference)
#include <cuda_runtime.h>
#include <math.h>

#define BATCH   32
#define SEQ     512
#define NHEADS  8
#define HID     64
#define INDIM   256
#define HDIM    512               // NHEADS*HID
#define MTOK    (BATCH*SEQ)       // 16384

// ---------------- scratch (device globals; no allocation allowed) ----------
__device__ float g_qkv[(size_t)MTOK * 3 * HDIM];   // [tok][1536] = Q|K|V, col = h*64+d
__device__ float g_upd[(size_t)MTOK * HDIM];       // [tok][512]  head-major
__device__ float g_h1 [(size_t)MTOK * 128];
__device__ float g_h2 [(size_t)MTOK * 64];

// ---------------- generic 64x64 tiled fp32 GEMM, optional bias+SiLU --------
// C[M,N] = act(A[M,K] @ B[K,N] (+bias)); M,N multiples of 64, K multiple of 16.
template<bool BIAS, bool SILU>
__global__ __launch_bounds__(256)
void gemm64(const float* __restrict__ A, const float* __restrict__ Bm,
            const float* __restrict__ bias, float* __restrict__ C,
            int K, int lda, int ldb, int ldc) {
    __shared__ float As[16][64];   // [k][row]
    __shared__ float Bs[16][64];   // [k][col]
    const int t  = threadIdx.x;
    const int bm = blockIdx.y * 64, bn = blockIdx.x * 64;
    const int ty = t >> 4, tx = t & 15;
    const int arow = t >> 2,  akq = (t & 3) * 4;
    const int brow = t >> 4,  bcq = (t & 15) * 4;
    const float* Ap = A  + (size_t)(bm + arow) * lda + akq;
    const float* Bp = Bm + (size_t)brow * ldb + bn + bcq;

    float acc[4][4] = {};
    for (int kt = 0; kt < K; kt += 16) {
        float4 a4 = *(const float4*)(Ap + kt);
        float4 b4 = *(const float4*)(Bp + (size_t)kt * ldb);
        As[akq+0][arow] = a4.x;
        As[akq+1][arow] = a4.y;
        As[akq+2][arow] = a4.z;
        As[akq+3][arow] = a4.w;
        *(float4*)&Bs[brow][bcq] = b4;
        __syncthreads();
        #pragma unroll
        for (int kk = 0; kk < 16; kk++) {
            float4 av = *(const float4*)&As[kk][ty*4];
            float4 bv = *(const float4*)&Bs[kk][tx*4];
            acc[0][0] += av.x*bv.x; acc[0][1] += av.x*bv.y; acc[0][2] += av.x*bv.z; acc[0][3] += av.x*bv.w;
            acc[1][0] += av.y*bv.x; acc[1][1] += av.y*bv.y; acc[1][2] += av.y*bv.z; acc[1][3] += av.y*bv.w;
            acc[2][0] += av.z*bv.x; acc[2][1] += av.z*bv.y; acc[2][2] += av.z*bv.z; acc[2][3] += av.z*bv.w;
            acc[3][0] += av.w*bv.x; acc[3][1] += av.w*bv.y; acc[3][2] += av.w*bv.z; acc[3][3] += av.w*bv.w;
        }
        __syncthreads();
    }

    float4 bb = make_float4(0.f, 0.f, 0.f, 0.f);
    if (BIAS) bb = *(const float4*)&bias[bn + tx*4];
    #pragma unroll
    for (int i = 0; i < 4; i++) {
        float4 v = make_float4(acc[i][0], acc[i][1], acc[i][2], acc[i][3]);
        if (BIAS) { v.x += bb.x; v.y += bb.y; v.z += bb.z; v.w += bb.w; }
        if (SILU) {
            v.x = v.x / (1.f + __expf(-v.x));
            v.y = v.y / (1.f + __expf(-v.y));
            v.z = v.z / (1.f + __expf(-v.z));
            v.w = v.w / (1.f + __expf(-v.w));
        }
        *(float4*)&C[(size_t)(bm + ty*4 + i) * ldc + bn + tx*4] = v;
    }
}

// ---------------- fused attention --------------------------------------
// grid: (qtile=16, h=8, b=32), 256 threads. 32 queries x 512 keys per block.
// att = dist*sqrt(2) + (Q.K)/(8*sqrt(2)); softmax over keys; O = P.V
#define SC_STRIDE 520          // 512 + 8: conflict-free softmax scan
#define ATT_SMEM_FLOATS (32*SC_STRIDE + 32*65 + 64*68 + SEQ*3)

__global__ __launch_bounds__(256, 2)
void attn_kernel(const float* __restrict__ pos, const float* __restrict__ qkv,
                 float* __restrict__ upd) {
    extern __shared__ float sm[];
    float* sc = sm;                    // [32][520]  scores -> probabilities
    float* Qs = sm + 32*SC_STRIDE;     // [32][65]
    float* KV = Qs + 32*65;            // KsT: [d][68] then Vs: [k][68]
    float* pk = KV + 64*68;            // [512][3]

    const int t  = threadIdx.x;
    const int qt = blockIdx.x, h = blockIdx.y, b = blockIdx.z;
    const int q0g = qt * 32;
    const int tokbase = b * SEQ;
    const int ty = t >> 4, tx = t & 15;
    const int q0 = ty * 2, k0 = tx * 4;

    for (int i = t; i < SEQ*3; i += 256) pk[i] = pos[(size_t)tokbase*3 + i];
    for (int i = t; i < 32*64; i += 256) {
        int q = i >> 6, d = i & 63;
        Qs[q*65 + d] = qkv[(size_t)(tokbase + q0g + q)*1536 + h*64 + d];
    }
    __syncthreads();

    // distance term into sc
    for (int i = t; i < 32*512; i += 256) {
        int q = i >> 9, k = i & 511;
        float dx = pk[(q0g+q)*3+0] - pk[k*3+0];
        float dy = pk[(q0g+q)*3+1] - pk[k*3+1];
        float dz = pk[(q0g+q)*3+2] - pk[k*3+2];
        float d2 = dx*dx + dy*dy + dz*dz;
        sc[q*SC_STRIDE + k] = (d2 > 0.f) ? sqrtf(d2) * 1.4142135623730951f : 0.f;
    }

    // S = Q K^T, accumulated into sc (on top of distance term)
    for (int kt = 0; kt < 8; kt++) {
        __syncthreads();
        for (int i = t; i < 64*64; i += 256) {          // K tile, transposed: KsT[d][k]
            int k = i >> 6, d = i & 63;
            KV[d*68 + k] = qkv[(size_t)(tokbase + kt*64 + k)*1536 + 512 + h*64 + d];
        }
        __syncthreads();
        float acc[2][4] = {};
        #pragma unroll 8
        for (int d = 0; d < 64; d++) {
            float a0 = Qs[q0*65 + d];
            float a1 = Qs[(q0+1)*65 + d];
            float4 kv = *(const float4*)&KV[d*68 + k0];
            acc[0][0] += a0*kv.x; acc[0][1] += a0*kv.y; acc[0][2] += a0*kv.z; acc[0][3] += a0*kv.w;
            acc[1][0] += a1*kv.x; acc[1][1] += a1*kv.y; acc[1][2] += a1*kv.z; acc[1][3] += a1*kv.w;
        }
        const float s = 0.08838834764831845f;   // 1/(8*sqrt(2))
        #pragma unroll
        for (int i = 0; i < 2; i++) {
            float4* dst = (float4*)&sc[(q0+i)*SC_STRIDE + kt*64 + k0];
            float4 v = *dst;
            v.x += acc[i][0]*s; v.y += acc[i][1]*s; v.z += acc[i][2]*s; v.w += acc[i][3]*s;
            *dst = v;
        }
    }
    __syncthreads();

    // softmax: 8 lanes per row, strided access (conflict-free with stride 520)
    {
        const int row = t >> 3, l = t & 7;
        float* r = sc + row*SC_STRIDE;
        float m = -1e30f;
        #pragma unroll 8
        for (int j = 0; j < 64; j++) m = fmaxf(m, r[j*8 + l]);
        m = fmaxf(m, __shfl_xor_sync(0xffffffffu, m, 1));
        m = fmaxf(m, __shfl_xor_sync(0xffffffffu, m, 2));
        m = fmaxf(m, __shfl_xor_sync(0xffffffffu, m, 4));
        float ssum = 0.f;
        #pragma unroll 8
        for (int j = 0; j < 64; j++) {
            float e = __expf(r[j*8 + l] - m);
            r[j*8 + l] = e;
            ssum += e;
        }
        ssum += __shfl_xor_sync(0xffffffffu, ssum, 1);
        ssum += __shfl_xor_sync(0xffffffffu, ssum, 2);
        ssum += __shfl_xor_sync(0xffffffffu, ssum, 4);
        float inv = 1.f / ssum;
        #pragma unroll 8
        for (int j = 0; j < 64; j++) r[j*8 + l] *= inv;
    }

    // O = P V
    float o[2][4] = {};
    const int d0 = tx * 4;
    for (int kt = 0; kt < 8; kt++) {
        __syncthreads();
        for (int i = t; i < 64*64; i += 256) {          // V tile, natural: Vs[k][d]
            int k = i >> 6, d = i & 63;
            KV[k*68 + d] = qkv[(size_t)(tokbase + kt*64 + k)*1536 + 1024 + h*64 + d];
        }
        __syncthreads();
        #pragma unroll 8
        for (int kk = 0; kk < 64; kk++) {
            float p0 = sc[q0*SC_STRIDE + kt*64 + kk];
            float p1 = sc[(q0+1)*SC_STRIDE + kt*64 + kk];
            float4 v = *(const float4*)&KV[kk*68 + d0];
            o[0][0] += p0*v.x; o[0][1] += p0*v.y; o[0][2] += p0*v.z; o[0][3] += p0*v.w;
            o[1][0] += p1*v.x; o[1][1] += p1*v.y; o[1][2] += p1*v.z; o[1][3] += p1*v.w;
        }
    }
    #pragma unroll
    for (int i = 0; i < 2; i++) {
        float4 v = make_float4(o[i][0], o[i][1], o[i][2], o[i][3]);
        *(float4*)&upd[(size_t)(tokbase + q0g + q0 + i)*HDIM + h*64 + d0] = v;
    }
}

// ---------------- launch -----------------------------------------------
extern "C" void kernel_launch(void* const* d_in, const int* in_sizes, int n_in,
                              void* d_out, int out_size) {
    const float* pos  = (const float*)d_in[0];
    const float* feat = (const float*)d_in[1];
    const float* Wk   = (const float*)d_in[2];
    const float* Wq   = (const float*)d_in[3];
    const float* Wv   = (const float*)d_in[4];
    const float* W1   = (const float*)d_in[5];
    const float* b1   = (const float*)d_in[6];
    const float* W2   = (const float*)d_in[7];
    const float* b2   = (const float*)d_in[8];
    const float* W3   = (const float*)d_in[9];
    const float* b3   = (const float*)d_in[10];
    float* out = (float*)d_out;

    void* p;
    cudaGetSymbolAddress(&p, g_qkv); float* qkv = (float*)p;
    cudaGetSymbolAddress(&p, g_upd); float* upd = (float*)p;
    cudaGetSymbolAddress(&p, g_h1);  float* h1  = (float*)p;
    cudaGetSymbolAddress(&p, g_h2);  float* h2  = (float*)p;

    dim3 blk(256);

    // QKV projections into fused [tok][Q|K|V] scratch (Q cols 0-511, K 512-1023, V 1024-1535)
    gemm64<false,false><<<dim3(8, MTOK/64), blk>>>(feat, Wq, nullptr, qkv + 0,    INDIM, INDIM, HDIM, 3*HDIM);
    gemm64<false,false><<<dim3(8, MTOK/64), blk>>>(feat, Wk, nullptr, qkv + 512,  INDIM, INDIM, HDIM, 3*HDIM);
    gemm64<false,false><<<dim3(8, MTOK/64), blk>>>(feat, Wv, nullptr, qkv + 1024, INDIM, INDIM, HDIM, 3*HDIM);

    // fused attention
    size_t shmem = (size_t)ATT_SMEM_FLOATS * sizeof(float);
    cudaFuncSetAttribute(attn_kernel, cudaFuncAttributeMaxDynamicSharedMemorySize, (int)shmem);
    attn_kernel<<<dim3(SEQ/32, NHEADS, BATCH), blk, shmem>>>(pos, qkv, upd);

    // out MLP with fused bias + SiLU
    gemm64<true,true><<<dim3(2, MTOK/64), blk>>>(upd, W1, b1, h1,  HDIM, HDIM, 128, 128);
    gemm64<true,true><<<dim3(1, MTOK/64), blk>>>(h1,  W2, b2, h2,  128,  128,  64,  64);
    gemm64<true,true><<<dim3(4, MTOK/64), blk>>>(h2,  W3, b3, out, 64,   64,   INDIM, INDIM);
}

// round 2
// speedup vs baseline: 1.0356x; 1.0356x over previous
#include <cuda_runtime.h>
#include <math.h>

#define BATCH   32
#define SEQ     512
#define NHEADS  8
#define HID     64
#define INDIM   256
#define HDIM    512               // NHEADS*HID
#define MTOK    (BATCH*SEQ)       // 16384

// ---------------- scratch (device globals; no allocation allowed) ----------
__device__ float g_qkv [(size_t)MTOK * 3 * HDIM];   // [tok][1536] = Q|K|V, col = h*64+d
__device__ float g_upd [(size_t)MTOK * HDIM];       // [tok][512]  head-major
__device__ float g_dist[(size_t)BATCH * SEQ * SEQ]; // dist(b,q,k) * sqrt(2)
__device__ float g_h1  [(size_t)MTOK * 128];
__device__ float g_h2  [(size_t)MTOK * 64];

// ---------------- generic 64x64 tiled fp32 GEMM, optional bias+SiLU --------
template<bool BIAS, bool SILU>
__global__ __launch_bounds__(256)
void gemm64(const float* __restrict__ A, const float* __restrict__ Bm,
            const float* __restrict__ bias, float* __restrict__ C,
            int K, int lda, int ldb, int ldc) {
    __shared__ float As[16][64];   // [k][row]
    __shared__ float Bs[16][64];   // [k][col]
    const int t  = threadIdx.x;
    const int bm = blockIdx.y * 64, bn = blockIdx.x * 64;
    const int ty = t >> 4, tx = t & 15;
    const int arow = t >> 2,  akq = (t & 3) * 4;
    const int brow = t >> 4,  bcq = (t & 15) * 4;
    const float* Ap = A  + (size_t)(bm + arow) * lda + akq;
    const float* Bp = Bm + (size_t)brow * ldb + bn + bcq;

    float acc[4][4] = {};
    for (int kt = 0; kt < K; kt += 16) {
        float4 a4 = *(const float4*)(Ap + kt);
        float4 b4 = *(const float4*)(Bp + (size_t)kt * ldb);
        As[akq+0][arow] = a4.x;
        As[akq+1][arow] = a4.y;
        As[akq+2][arow] = a4.z;
        As[akq+3][arow] = a4.w;
        *(float4*)&Bs[brow][bcq] = b4;
        __syncthreads();
        #pragma unroll
        for (int kk = 0; kk < 16; kk++) {
            float4 av = *(const float4*)&As[kk][ty*4];
            float4 bv = *(const float4*)&Bs[kk][tx*4];
            acc[0][0] += av.x*bv.x; acc[0][1] += av.x*bv.y; acc[0][2] += av.x*bv.z; acc[0][3] += av.x*bv.w;
            acc[1][0] += av.y*bv.x; acc[1][1] += av.y*bv.y; acc[1][2] += av.y*bv.z; acc[1][3] += av.y*bv.w;
            acc[2][0] += av.z*bv.x; acc[2][1] += av.z*bv.y; acc[2][2] += av.z*bv.z; acc[2][3] += av.z*bv.w;
            acc[3][0] += av.w*bv.x; acc[3][1] += av.w*bv.y; acc[3][2] += av.w*bv.z; acc[3][3] += av.w*bv.w;
        }
        __syncthreads();
    }

    float4 bb = make_float4(0.f, 0.f, 0.f, 0.f);
    if (BIAS) bb = *(const float4*)&bias[bn + tx*4];
    #pragma unroll
    for (int i = 0; i < 4; i++) {
        float4 v = make_float4(acc[i][0], acc[i][1], acc[i][2], acc[i][3]);
        if (BIAS) { v.x += bb.x; v.y += bb.y; v.z += bb.z; v.w += bb.w; }
        if (SILU) {
            v.x = v.x / (1.f + __expf(-v.x));
            v.y = v.y / (1.f + __expf(-v.y));
            v.z = v.z / (1.f + __expf(-v.z));
            v.w = v.w / (1.f + __expf(-v.w));
        }
        *(float4*)&C[(size_t)(bm + ty*4 + i) * ldc + bn + tx*4] = v;
    }
}

// ---------------- distance precompute (shared across all 8 heads) ----------
// dist(b,q,k) = sqrt(|p_q - p_k|^2) * sqrt(2)     [folds /0.5 and /sqrt(2)]
__global__ __launch_bounds__(256)
void dist_kernel(const float* __restrict__ pos, float* __restrict__ dist) {
    __shared__ float pk[SEQ * 3];
    const int t = threadIdx.x;
    const int b = blockIdx.y, q0g = blockIdx.x * 32;
    for (int i = t; i < SEQ * 3; i += 256) pk[i] = pos[(size_t)b * SEQ * 3 + i];
    __syncthreads();
    float* drow = dist + ((size_t)b * SEQ + q0g) * SEQ;
    for (int i = t; i < 32 * SEQ; i += 256) {
        int q = i >> 9, k = i & 511;
        float dx = pk[(q0g+q)*3+0] - pk[k*3+0];
        float dy = pk[(q0g+q)*3+1] - pk[k*3+1];
        float dz = pk[(q0g+q)*3+2] - pk[k*3+2];
        float d2 = dx*dx + dy*dy + dz*dz;
        drow[(size_t)q * SEQ + k] = (d2 > 0.f) ? sqrtf(d2) * 1.4142135623730951f : 0.f;
    }
}

// ---------------- fused attention --------------------------------------
// grid: (qtile=16, h=8, b=32), 256 threads. 32 queries x 512 keys per block.
#define SC_STRIDE 520
#define QS_STRIDE 68
#define KT_STRIDE 132            // KsT row (k fast), 128 k + pad
#define VS_STRIDE 68             // Vs row (d fast), 64 d + pad
#define KV_FLOATS (128 * VS_STRIDE)   // 8704 >= 64*KT_STRIDE (8448)
#define ATT_SMEM_FLOATS (32*SC_STRIDE + 32*QS_STRIDE + KV_FLOATS)

__global__ __launch_bounds__(256, 2)
void attn_kernel(const float* __restrict__ dist, const float* __restrict__ qkv,
                 float* __restrict__ upd) {
    extern __shared__ float sm[];
    float* sc = sm;                         // [32][520]
    float* Qs = sm + 32*SC_STRIDE;          // [32][68]
    float* KV = Qs + 32*QS_STRIDE;          // KsT [64][132] / Vs [128][68]

    const int t  = threadIdx.x;
    const int qt = blockIdx.x, h = blockIdx.y, b = blockIdx.z;
    const int q0g = qt * 32;
    const int tokbase = b * SEQ;
    const int ty = t >> 4, tx = t & 15;
    const int q0 = ty * 2;

    // stage Q (vectorized)
    for (int i = t; i < 32 * 16; i += 256) {
        int q = i >> 4, d4 = (i & 15) * 4;
        *(float4*)&Qs[q*QS_STRIDE + d4] =
            *(const float4*)&qkv[(size_t)(tokbase + q0g + q)*1536 + h*64 + d4];
    }
    // init scores with precomputed distance term
    const float* dbase = dist + ((size_t)b * SEQ + q0g) * SEQ;
    for (int i = t; i < 32 * 128; i += 256) {
        int q = i >> 7, k4 = (i & 127) * 4;
        *(float4*)&sc[q*SC_STRIDE + k4] = *(const float4*)&dbase[(size_t)q * SEQ + k4];
    }

    // ---- S += Q K^T / (8*sqrt2), k-tiles of 128, 2x8 micro-tile ----
    const int kd  = t & 63;           // d for K-transpose staging
    const int kgb = (t >> 6) * 4;     // k group base
    const int k0  = tx * 8;
    for (int kt = 0; kt < 4; kt++) {
        __syncthreads();
        // stage K transposed: KsT[d][k]
        for (int kk0 = kgb; kk0 < 128; kk0 += 16) {
            const float* gp = &qkv[(size_t)(tokbase + kt*128 + kk0)*1536 + 512 + h*64 + kd];
            float v0 = gp[0*1536], v1 = gp[1*1536], v2 = gp[2*1536], v3 = gp[3*1536];
            *(float4*)&KV[kd*KT_STRIDE + kk0] = make_float4(v0, v1, v2, v3);
        }
        __syncthreads();
        float s[2][8] = {};
        #pragma unroll 8
        for (int d = 0; d < 64; d++) {
            float a0 = Qs[q0*QS_STRIDE + d];
            float a1 = Qs[(q0+1)*QS_STRIDE + d];
            float4 kA = *(const float4*)&KV[d*KT_STRIDE + k0];
            float4 kB = *(const float4*)&KV[d*KT_STRIDE + k0 + 4];
            s[0][0] += a0*kA.x; s[0][1] += a0*kA.y; s[0][2] += a0*kA.z; s[0][3] += a0*kA.w;
            s[0][4] += a0*kB.x; s[0][5] += a0*kB.y; s[0][6] += a0*kB.z; s[0][7] += a0*kB.w;
            s[1][0] += a1*kA.x; s[1][1] += a1*kA.y; s[1][2] += a1*kA.z; s[1][3] += a1*kA.w;
            s[1][4] += a1*kB.x; s[1][5] += a1*kB.y; s[1][6] += a1*kB.z; s[1][7] += a1*kB.w;
        }
        const float scl = 0.08838834764831845f;   // 1/(8*sqrt2)
        #pragma unroll
        for (int r = 0; r < 2; r++) {
            float4* dst = (float4*)&sc[(q0+r)*SC_STRIDE + kt*128 + k0];
            float4 v = dst[0];
            v.x += s[r][0]*scl; v.y += s[r][1]*scl; v.z += s[r][2]*scl; v.w += s[r][3]*scl;
            dst[0] = v;
            float4 w = dst[1];
            w.x += s[r][4]*scl; w.y += s[r][5]*scl; w.z += s[r][6]*scl; w.w += s[r][7]*scl;
            dst[1] = w;
        }
    }
    __syncthreads();

    // ---- softmax: 8 lanes per row ----
    {
        const int row = t >> 3, l = t & 7;
        float* r = sc + row*SC_STRIDE;
        float m = -1e30f;
        #pragma unroll 8
        for (int j = 0; j < 64; j++) m = fmaxf(m, r[j*8 + l]);
        m = fmaxf(m, __shfl_xor_sync(0xffffffffu, m, 1));
        m = fmaxf(m, __shfl_xor_sync(0xffffffffu, m, 2));
        m = fmaxf(m, __shfl_xor_sync(0xffffffffu, m, 4));
        float ssum = 0.f;
        #pragma unroll 8
        for (int j = 0; j < 64; j++) {
            float e = __expf(r[j*8 + l] - m);
            r[j*8 + l] = e;
            ssum += e;
        }
        ssum += __shfl_xor_sync(0xffffffffu, ssum, 1);
        ssum += __shfl_xor_sync(0xffffffffu, ssum, 2);
        ssum += __shfl_xor_sync(0xffffffffu, ssum, 4);
        float inv = 1.f / ssum;
        #pragma unroll 8
        for (int j = 0; j < 64; j++) r[j*8 + l] *= inv;
    }

    // ---- O = P V, k-tiles of 128, 4-wide k chunks ----
    float o[2][4] = {};
    const int d0 = tx * 4;
    for (int kt = 0; kt < 4; kt++) {
        __syncthreads();
        for (int i = t; i < 128 * 16; i += 256) {      // Vs[k][d], vectorized
            int k = i >> 4, d4 = (i & 15) * 4;
            *(float4*)&KV[k*VS_STRIDE + d4] =
                *(const float4*)&qkv[(size_t)(tokbase + kt*128 + k)*1536 + 1024 + h*64 + d4];
        }
        __syncthreads();
        const float* p0r = &sc[q0*SC_STRIDE + kt*128];
        const float* p1r = &sc[(q0+1)*SC_STRIDE + kt*128];
        #pragma unroll 4
        for (int kk = 0; kk < 128; kk += 4) {
            float4 p0 = *(const float4*)&p0r[kk];
            float4 p1 = *(const float4*)&p1r[kk];
            float4 v0 = *(const float4*)&KV[(kk+0)*VS_STRIDE + d0];
            float4 v1 = *(const float4*)&KV[(kk+1)*VS_STRIDE + d0];
            float4 v2 = *(const float4*)&KV[(kk+2)*VS_STRIDE + d0];
            float4 v3 = *(const float4*)&KV[(kk+3)*VS_STRIDE + d0];
            o[0][0] += p0.x*v0.x + p0.y*v1.x + p0.z*v2.x + p0.w*v3.x;
            o[0][1] += p0.x*v0.y + p0.y*v1.y + p0.z*v2.y + p0.w*v3.y;
            o[0][2] += p0.x*v0.z + p0.y*v1.z + p0.z*v2.z + p0.w*v3.z;
            o[0][3] += p0.x*v0.w + p0.y*v1.w + p0.z*v2.w + p0.w*v3.w;
            o[1][0] += p1.x*v0.x + p1.y*v1.x + p1.z*v2.x + p1.w*v3.x;
            o[1][1] += p1.x*v0.y + p1.y*v1.y + p1.z*v2.y + p1.w*v3.y;
            o[1][2] += p1.x*v0.z + p1.y*v1.z + p1.z*v2.z + p1.w*v3.z;
            o[1][3] += p1.x*v0.w + p1.y*v1.w + p1.z*v2.w + p1.w*v3.w;
        }
    }
    #pragma unroll
    for (int i = 0; i < 2; i++) {
        *(float4*)&upd[(size_t)(tokbase + q0g + q0 + i)*HDIM + h*64 + d0] =
            make_float4(o[i][0], o[i][1], o[i][2], o[i][3]);
    }
}

// ---------------- launch -----------------------------------------------
extern "C" void kernel_launch(void* const* d_in, const int* in_sizes, int n_in,
                              void* d_out, int out_size) {
    const float* pos  = (const float*)d_in[0];
    const float* feat = (const float*)d_in[1];
    const float* Wk   = (const float*)d_in[2];
    const float* Wq   = (const float*)d_in[3];
    const float* Wv   = (const float*)d_in[4];
    const float* W1   = (const float*)d_in[5];
    const float* b1   = (const float*)d_in[6];
    const float* W2   = (const float*)d_in[7];
    const float* b2   = (const float*)d_in[8];
    const float* W3   = (const float*)d_in[9];
    const float* b3   = (const float*)d_in[10];
    float* out = (float*)d_out;

    void* p;
    cudaGetSymbolAddress(&p, g_qkv);  float* qkv  = (float*)p;
    cudaGetSymbolAddress(&p, g_upd);  float* upd  = (float*)p;
    cudaGetSymbolAddress(&p, g_dist); float* dist = (float*)p;
    cudaGetSymbolAddress(&p, g_h1);   float* h1   = (float*)p;
    cudaGetSymbolAddress(&p, g_h2);   float* h2   = (float*)p;

    dim3 blk(256);

    // distance precompute (shared across heads)
    dist_kernel<<<dim3(SEQ/32, BATCH), blk>>>(pos, dist);

    // QKV projections into fused [tok][Q|K|V] scratch
    gemm64<false,false><<<dim3(8, MTOK/64), blk>>>(feat, Wq, nullptr, qkv + 0,    INDIM, INDIM, HDIM, 3*HDIM);
    gemm64<false,false><<<dim3(8, MTOK/64), blk>>>(feat, Wk, nullptr, qkv + 512,  INDIM, INDIM, HDIM, 3*HDIM);
    gemm64<false,false><<<dim3(8, MTOK/64), blk>>>(feat, Wv, nullptr, qkv + 1024, INDIM, INDIM, HDIM, 3*HDIM);

    // fused attention
    size_t shmem = (size_t)ATT_SMEM_FLOATS * sizeof(float);
    cudaFuncSetAttribute(attn_kernel, cudaFuncAttributeMaxDynamicSharedMemorySize, (int)shmem);
    attn_kernel<<<dim3(SEQ/32, NHEADS, BATCH), blk, shmem>>>(dist, qkv, upd);

    // out MLP with fused bias + SiLU
    gemm64<true,true><<<dim3(2, MTOK/64), blk>>>(upd, W1, b1, h1,  HDIM, HDIM, 128, 128);
    gemm64<true,true><<<dim3(1, MTOK/64), blk>>>(h1,  W2, b2, h2,  128,  128,  64,  64);
    gemm64<true,true><<<dim3(4, MTOK/64), blk>>>(h2,  W3, b3, out, 64,   64,   INDIM, INDIM);
}

// round 3
// speedup vs baseline: 2.3313x; 2.2513x over previous
#include <cuda_runtime.h>
#include <math.h>
#include <stdint.h>

#define BATCH   32
#define SEQ     512
#define NHEADS  8
#define HID     64
#define INDIM   256
#define HDIM    512
#define MTOK    (BATCH*SEQ)       // 16384

// ---------------- scratch ----------------
__device__ float g_qkv [(size_t)MTOK * 3 * HDIM];
__device__ float g_upd [(size_t)MTOK * HDIM];
__device__ float g_dist[(size_t)BATCH * SEQ * SEQ];
__device__ float g_h1  [(size_t)MTOK * 128];
__device__ float g_h2  [(size_t)MTOK * 64];

// ---------------- tf32 helpers ----------------
__device__ __forceinline__ float totf32(float x) {
    uint32_t u;
    asm("cvt.rna.tf32.f32 %0, %1;" : "=r"(u) : "f"(x));
    return __uint_as_float(u);
}
__device__ __forceinline__ float4 cvt4(float4 v) {
    return make_float4(totf32(v.x), totf32(v.y), totf32(v.z), totf32(v.w));
}
// D = A(16x8,row) * B(8x8,col) + D, tf32 inputs (fp32 regs), fp32 accum
__device__ __forceinline__ void mma8(float c[4], const float a[4], const float b[2]) {
    asm volatile(
        "mma.sync.aligned.m16n8k8.row.col.f32.tf32.tf32.f32 "
        "{%0,%1,%2,%3}, {%4,%5,%6,%7}, {%8,%9}, {%0,%1,%2,%3};\n"
        : "+f"(c[0]), "+f"(c[1]), "+f"(c[2]), "+f"(c[3])
        : "r"(__float_as_uint(a[0])), "r"(__float_as_uint(a[1])),
          "r"(__float_as_uint(a[2])), "r"(__float_as_uint(a[3])),
          "r"(__float_as_uint(b[0])), "r"(__float_as_uint(b[1])));
}

// ---------------- tf32 dense GEMM: C = act(A@B + bias) ------------------
// BM=128 BN=64 BK=32, 256 threads (8 warps: 4 in M x 2 in N), warp tile 32x32
#define AS_S 36
#define BS_S 72
template<bool BIAS, bool SILU>
__global__ __launch_bounds__(256)
void gemm_tf32(const float* __restrict__ A, const float* __restrict__ Bm,
               const float* __restrict__ bias, float* __restrict__ C,
               int K, int lda, int ldb, int ldc) {
    __shared__ float As[128 * AS_S];   // [m][k], k-pad
    __shared__ float Bs[32 * BS_S];    // [k][n], n-pad
    const int t = threadIdx.x;
    const int w = t >> 5, l = t & 31, g = l >> 2, ti = l & 3;
    const int bm = blockIdx.y * 128, bn = blockIdx.x * 64;
    const int rmb = (w >> 1) * 32, cnb = (w & 1) * 32;

    float c[2][4][4] = {};
    for (int kt = 0; kt < K; kt += 32) {
        // stage A [128][32] -> As[m][k]  (coalesced, tf32-rounded)
        #pragma unroll
        for (int i = t; i < 128 * 8; i += 256) {
            int m = i >> 3, q4 = (i & 7) * 4;
            float4 v = *(const float4*)&A[(size_t)(bm + m) * lda + kt + q4];
            *(float4*)&As[m * AS_S + q4] = cvt4(v);
        }
        // stage B [32][64] -> Bs[k][n]
        #pragma unroll
        for (int i = t; i < 32 * 16; i += 256) {
            int kr = i >> 4, n4 = (i & 15) * 4;
            float4 v = *(const float4*)&Bm[(size_t)(kt + kr) * ldb + bn + n4];
            *(float4*)&Bs[kr * BS_S + n4] = cvt4(v);
        }
        __syncthreads();
        #pragma unroll
        for (int ks = 0; ks < 4; ks++) {
            float a[2][4], b[4][2];
            #pragma unroll
            for (int mt = 0; mt < 2; mt++) {
                int r = rmb + mt * 16;
                a[mt][0] = As[(r + g)     * AS_S + ks*8 + ti];
                a[mt][1] = As[(r + g + 8) * AS_S + ks*8 + ti];
                a[mt][2] = As[(r + g)     * AS_S + ks*8 + ti + 4];
                a[mt][3] = As[(r + g + 8) * AS_S + ks*8 + ti + 4];
            }
            #pragma unroll
            for (int nt = 0; nt < 4; nt++) {
                int cc = cnb + nt * 8 + g;
                b[nt][0] = Bs[(ks*8 + ti)     * BS_S + cc];
                b[nt][1] = Bs[(ks*8 + ti + 4) * BS_S + cc];
            }
            #pragma unroll
            for (int mt = 0; mt < 2; mt++)
                #pragma unroll
                for (int nt = 0; nt < 4; nt++)
                    mma8(c[mt][nt], a[mt], b[nt]);
        }
        __syncthreads();
    }
    // epilogue
    #pragma unroll
    for (int mt = 0; mt < 2; mt++) {
        #pragma unroll
        for (int nt = 0; nt < 4; nt++) {
            int row = bm + rmb + mt * 16 + g;
            int col = bn + cnb + nt * 8 + 2 * ti;
            float b0 = 0.f, b1 = 0.f;
            if (BIAS) { b0 = bias[col]; b1 = bias[col + 1]; }
            float v0 = c[mt][nt][0] + b0, v1 = c[mt][nt][1] + b1;
            float v2 = c[mt][nt][2] + b0, v3 = c[mt][nt][3] + b1;
            if (SILU) {
                v0 = v0 / (1.f + __expf(-v0)); v1 = v1 / (1.f + __expf(-v1));
                v2 = v2 / (1.f + __expf(-v2)); v3 = v3 / (1.f + __expf(-v3));
            }
            *(float2*)&C[(size_t)row * ldc + col]       = make_float2(v0, v1);
            *(float2*)&C[(size_t)(row + 8) * ldc + col] = make_float2(v2, v3);
        }
    }
}

// ---------------- distance precompute ----------------
__global__ __launch_bounds__(256)
void dist_kernel(const float* __restrict__ pos, float* __restrict__ dist) {
    __shared__ float pk[SEQ * 3];
    const int t = threadIdx.x;
    const int b = blockIdx.y, q0g = blockIdx.x * 32;
    for (int i = t; i < SEQ * 3; i += 256) pk[i] = pos[(size_t)b * SEQ * 3 + i];
    __syncthreads();
    float* drow = dist + ((size_t)b * SEQ + q0g) * SEQ;
    for (int i = t; i < 32 * SEQ; i += 256) {
        int q = i >> 9, k = i & 511;
        float dx = pk[(q0g+q)*3+0] - pk[k*3+0];
        float dy = pk[(q0g+q)*3+1] - pk[k*3+1];
        float dz = pk[(q0g+q)*3+2] - pk[k*3+2];
        float d2 = dx*dx + dy*dy + dz*dz;
        drow[(size_t)q * SEQ + k] = (d2 > 0.f) ? sqrtf(d2) * 1.4142135623730951f : 0.f;
    }
}

// ---------------- fused attention, tf32 MMA ------------------------------
// grid (16,8,32), 256 thr (8 warps). 32 q x 512 k per block.
#define SCS 520
#define QSS 68
#define KTS 136
#define VSS 72
#define ATT_FLOATS (32*SCS + 32*QSS + 128*VSS)   // 16640+2176+9216 = 28032

__global__ __launch_bounds__(256, 2)
void attn_kernel(const float* __restrict__ dist, const float* __restrict__ qkv,
                 float* __restrict__ upd) {
    extern __shared__ float sm[];
    float* sc = sm;                 // [32][520] fp32 scores/probs
    float* Qs = sm + 32*SCS;        // [32][68]  tf32
    float* KV = Qs + 32*QSS;        // KsT [64][136] / Vs [128][72], tf32

    const int t = threadIdx.x;
    const int w = t >> 5, l = t & 31, g = l >> 2, ti = l & 3;
    const int qt = blockIdx.x, h = blockIdx.y, b = blockIdx.z;
    const int q0g = qt * 32, tokbase = b * SEQ;

    // stage Q (tf32)
    for (int i = t; i < 32 * 16; i += 256) {
        int q = i >> 4, d4 = (i & 15) * 4;
        float4 v = *(const float4*)&qkv[(size_t)(tokbase + q0g + q)*1536 + h*64 + d4];
        *(float4*)&Qs[q*QSS + d4] = cvt4(v);
    }
    // init scores with distance term
    const float* dbase = dist + ((size_t)b * SEQ + q0g) * SEQ;
    for (int i = t; i < 32 * 128; i += 256) {
        int q = i >> 7, k4 = (i & 127) * 4;
        *(float4*)&sc[q*SCS + k4] = *(const float4*)&dbase[(size_t)q * SEQ + k4];
    }

    // ---- S += QK^T * scl : 4 k-tiles of 128; warp w owns 16 k-cols ----
    const float scl = 0.08838834764831845f;   // 1/(8*sqrt2)
    const int kd = t & 63, kgb = (t >> 6) * 4;
    for (int kt = 0; kt < 4; kt++) {
        __syncthreads();
        #pragma unroll
        for (int kk0 = kgb; kk0 < 128; kk0 += 16) {   // KsT[d][k], tf32
            const float* gp = &qkv[(size_t)(tokbase + kt*128 + kk0)*1536 + 512 + h*64 + kd];
            float4 v = make_float4(totf32(gp[0]), totf32(gp[1536]),
                                   totf32(gp[3072]), totf32(gp[4608]));
            *(float4*)&KV[kd*KTS + kk0] = v;
        }
        __syncthreads();
        float cS[2][2][4] = {};
        #pragma unroll
        for (int ks = 0; ks < 8; ks++) {
            float a[2][4], bf[2][2];
            #pragma unroll
            for (int mt = 0; mt < 2; mt++) {
                int r = mt * 16;
                a[mt][0] = Qs[(r + g)     * QSS + ks*8 + ti];
                a[mt][1] = Qs[(r + g + 8) * QSS + ks*8 + ti];
                a[mt][2] = Qs[(r + g)     * QSS + ks*8 + ti + 4];
                a[mt][3] = Qs[(r + g + 8) * QSS + ks*8 + ti + 4];
            }
            int cb = w * 16 + g;
            bf[0][0] = KV[(ks*8 + ti)     * KTS + cb];
            bf[0][1] = KV[(ks*8 + ti + 4) * KTS + cb];
            bf[1][0] = KV[(ks*8 + ti)     * KTS + cb + 8];
            bf[1][1] = KV[(ks*8 + ti + 4) * KTS + cb + 8];
            #pragma unroll
            for (int mt = 0; mt < 2; mt++) {
                mma8(cS[mt][0], a[mt], bf[0]);
                mma8(cS[mt][1], a[mt], bf[1]);
            }
        }
        #pragma unroll
        for (int mt = 0; mt < 2; mt++)
            #pragma unroll
            for (int nt = 0; nt < 2; nt++) {
                int r0 = mt*16 + g;
                int c0 = kt*128 + w*16 + nt*8 + 2*ti;
                float2* p0 = (float2*)&sc[r0*SCS + c0];
                float2 u0 = *p0;
                u0.x += cS[mt][nt][0]*scl; u0.y += cS[mt][nt][1]*scl;
                *p0 = u0;
                float2* p1 = (float2*)&sc[(r0+8)*SCS + c0];
                float2 u1 = *p1;
                u1.x += cS[mt][nt][2]*scl; u1.y += cS[mt][nt][3]*scl;
                *p1 = u1;
            }
    }
    __syncthreads();

    // ---- softmax (fp32), final probs tf32-rounded ----
    {
        const int row = t >> 3, ll = t & 7;
        float* r = sc + row*SCS;
        float m = -1e30f;
        #pragma unroll 8
        for (int j = 0; j < 64; j++) m = fmaxf(m, r[j*8 + ll]);
        m = fmaxf(m, __shfl_xor_sync(0xffffffffu, m, 1));
        m = fmaxf(m, __shfl_xor_sync(0xffffffffu, m, 2));
        m = fmaxf(m, __shfl_xor_sync(0xffffffffu, m, 4));
        float ssum = 0.f;
        #pragma unroll 8
        for (int j = 0; j < 64; j++) {
            float e = __expf(r[j*8 + ll] - m);
            r[j*8 + ll] = e;
            ssum += e;
        }
        ssum += __shfl_xor_sync(0xffffffffu, ssum, 1);
        ssum += __shfl_xor_sync(0xffffffffu, ssum, 2);
        ssum += __shfl_xor_sync(0xffffffffu, ssum, 4);
        float inv = 1.f / ssum;
        #pragma unroll 8
        for (int j = 0; j < 64; j++) r[j*8 + ll] = totf32(r[j*8 + ll] * inv);
    }

    // ---- O = P V : warp w owns d-strip of 8 ----
    float cO[2][4] = {};
    const int dn = w * 8;
    for (int kt = 0; kt < 4; kt++) {
        __syncthreads();
        for (int i = t; i < 128 * 16; i += 256) {     // Vs[k][d], tf32
            int k = i >> 4, d4 = (i & 15) * 4;
            float4 v = *(const float4*)&qkv[(size_t)(tokbase + kt*128 + k)*1536 + 1024 + h*64 + d4];
            *(float4*)&KV[k*VSS + d4] = cvt4(v);
        }
        __syncthreads();
        #pragma unroll
        for (int ks = 0; ks < 16; ks++) {
            int kk = kt*128 + ks*8;
            float a[2][4], bf[2];
            #pragma unroll
            for (int mt = 0; mt < 2; mt++) {
                int r = mt * 16;
                a[mt][0] = sc[(r + g)     * SCS + kk + ti];
                a[mt][1] = sc[(r + g + 8) * SCS + kk + ti];
                a[mt][2] = sc[(r + g)     * SCS + kk + ti + 4];
                a[mt][3] = sc[(r + g + 8) * SCS + kk + ti + 4];
            }
            bf[0] = KV[(ks*8 + ti)     * VSS + dn + g];
            bf[1] = KV[(ks*8 + ti + 4) * VSS + dn + g];
            mma8(cO[0], a[0], bf);
            mma8(cO[1], a[1], bf);
        }
    }
    #pragma unroll
    for (int mt = 0; mt < 2; mt++) {
        int r = q0g + mt*16 + g;
        int col = h*64 + dn + 2*ti;
        *(float2*)&upd[(size_t)(tokbase + r) * HDIM + col]     = make_float2(cO[mt][0], cO[mt][1]);
        *(float2*)&upd[(size_t)(tokbase + r + 8) * HDIM + col] = make_float2(cO[mt][2], cO[mt][3]);
    }
}

// ---------------- launch ----------------
extern "C" void kernel_launch(void* const* d_in, const int* in_sizes, int n_in,
                              void* d_out, int out_size) {
    const float* pos  = (const float*)d_in[0];
    const float* feat = (const float*)d_in[1];
    const float* Wk   = (const float*)d_in[2];
    const float* Wq   = (const float*)d_in[3];
    const float* Wv   = (const float*)d_in[4];
    const float* W1   = (const float*)d_in[5];
    const float* b1   = (const float*)d_in[6];
    const float* W2   = (const float*)d_in[7];
    const float* b2   = (const float*)d_in[8];
    const float* W3   = (const float*)d_in[9];
    const float* b3   = (const float*)d_in[10];
    float* out = (float*)d_out;

    void* p;
    cudaGetSymbolAddress(&p, g_qkv);  float* qkv  = (float*)p;
    cudaGetSymbolAddress(&p, g_upd);  float* upd  = (float*)p;
    cudaGetSymbolAddress(&p, g_dist); float* dist = (float*)p;
    cudaGetSymbolAddress(&p, g_h1);   float* h1   = (float*)p;
    cudaGetSymbolAddress(&p, g_h2);   float* h2   = (float*)p;

    dim3 blk(256);

    dist_kernel<<<dim3(SEQ/32, BATCH), blk>>>(pos, dist);

    // QKV projections (tf32 MMA) into fused [tok][Q|K|V] scratch
    gemm_tf32<false,false><<<dim3(8, MTOK/128), blk>>>(feat, Wq, nullptr, qkv + 0,    INDIM, INDIM, HDIM, 3*HDIM);
    gemm_tf32<false,false><<<dim3(8, MTOK/128), blk>>>(feat, Wk, nullptr, qkv + 512,  INDIM, INDIM, HDIM, 3*HDIM);
    gemm_tf32<false,false><<<dim3(8, MTOK/128), blk>>>(feat, Wv, nullptr, qkv + 1024, INDIM, INDIM, HDIM, 3*HDIM);

    // fused attention (tf32 MMA)
    size_t shmem = (size_t)ATT_FLOATS * sizeof(float);
    cudaFuncSetAttribute(attn_kernel, cudaFuncAttributeMaxDynamicSharedMemorySize, (int)shmem);
    attn_kernel<<<dim3(SEQ/32, NHEADS, BATCH), blk, shmem>>>(dist, qkv, upd);

    // out MLP (tf32 MMA, fused bias + SiLU)
    gemm_tf32<true,true><<<dim3(2, MTOK/128), blk>>>(upd, W1, b1, h1,  HDIM, HDIM, 128, 128);
    gemm_tf32<true,true><<<dim3(1, MTOK/128), blk>>>(h1,  W2, b2, h2,  128,  128,  64,  64);
    gemm_tf32<true,true><<<dim3(4, MTOK/128), blk>>>(h2,  W3, b3, out, 64,   64,   INDIM, INDIM);
}

// round 4
// speedup vs baseline: 2.7416x; 1.1760x over previous
#include <cuda_runtime.h>
#include <math.h>
#include <stdint.h>

#define BATCH   32
#define SEQ     512
#define NHEADS  8
#define HID     64
#define INDIM   256
#define HDIM    512
#define MTOK    (BATCH*SEQ)       // 16384

// ---------------- scratch ----------------
__device__ float g_qkv [(size_t)MTOK * 3 * HDIM];
__device__ float g_upd [(size_t)MTOK * HDIM];
__device__ float g_dist[(size_t)BATCH * SEQ * SEQ];
__device__ float g_h1  [(size_t)MTOK * 128];
__device__ float g_h2  [(size_t)MTOK * 64];

// ---------------- helpers ----------------
__device__ __forceinline__ float totf32(float x) {
    uint32_t u;
    asm("cvt.rna.tf32.f32 %0, %1;" : "=r"(u) : "f"(x));
    return __uint_as_float(u);
}
__device__ __forceinline__ float4 cvt4(float4 v) {
    return make_float4(totf32(v.x), totf32(v.y), totf32(v.z), totf32(v.w));
}
__device__ __forceinline__ float fsqrt_fast(float x) {
    float y;
    asm("sqrt.approx.f32 %0, %1;" : "=f"(y) : "f"(x));
    return y;
}
__device__ __forceinline__ void mma8(float c[4], const float a[4], const float b[2]) {
    asm volatile(
        "mma.sync.aligned.m16n8k8.row.col.f32.tf32.tf32.f32 "
        "{%0,%1,%2,%3}, {%4,%5,%6,%7}, {%8,%9}, {%0,%1,%2,%3};\n"
        : "+f"(c[0]), "+f"(c[1]), "+f"(c[2]), "+f"(c[3])
        : "r"(__float_as_uint(a[0])), "r"(__float_as_uint(a[1])),
          "r"(__float_as_uint(a[2])), "r"(__float_as_uint(a[3])),
          "r"(__float_as_uint(b[0])), "r"(__float_as_uint(b[1])));
}

// ---------------- shared tf32 GEMM body (BM=128 BN=64 BK=32, 256 thr) ------
#define AS_S 36
#define BS_S 72
template<bool BIAS, bool SILU>
__device__ __forceinline__
void gemm_body(const float* __restrict__ A, const float* __restrict__ Bm,
               const float* __restrict__ bias, float* __restrict__ C,
               int K, int lda, int ldb, int ldc,
               int bm, int bn_src, int bn_dst) {
    __shared__ float As[128 * AS_S];
    __shared__ float Bs[32 * BS_S];
    const int t = threadIdx.x;
    const int w = t >> 5, l = t & 31, g = l >> 2, ti = l & 3;
    const int rmb = (w >> 1) * 32, cnb = (w & 1) * 32;

    float c[2][4][4] = {};
    for (int kt = 0; kt < K; kt += 32) {
        #pragma unroll
        for (int i = t; i < 128 * 8; i += 256) {
            int m = i >> 3, q4 = (i & 7) * 4;
            float4 v = *(const float4*)&A[(size_t)(bm + m) * lda + kt + q4];
            *(float4*)&As[m * AS_S + q4] = cvt4(v);
        }
        #pragma unroll
        for (int i = t; i < 32 * 16; i += 256) {
            int kr = i >> 4, n4 = (i & 15) * 4;
            float4 v = *(const float4*)&Bm[(size_t)(kt + kr) * ldb + bn_src + n4];
            *(float4*)&Bs[kr * BS_S + n4] = cvt4(v);
        }
        __syncthreads();
        #pragma unroll
        for (int ks = 0; ks < 4; ks++) {
            float a[2][4], b[4][2];
            #pragma unroll
            for (int mt = 0; mt < 2; mt++) {
                int r = rmb + mt * 16;
                a[mt][0] = As[(r + g)     * AS_S + ks*8 + ti];
                a[mt][1] = As[(r + g + 8) * AS_S + ks*8 + ti];
                a[mt][2] = As[(r + g)     * AS_S + ks*8 + ti + 4];
                a[mt][3] = As[(r + g + 8) * AS_S + ks*8 + ti + 4];
            }
            #pragma unroll
            for (int nt = 0; nt < 4; nt++) {
                int cc = cnb + nt * 8 + g;
                b[nt][0] = Bs[(ks*8 + ti)     * BS_S + cc];
                b[nt][1] = Bs[(ks*8 + ti + 4) * BS_S + cc];
            }
            #pragma unroll
            for (int mt = 0; mt < 2; mt++)
                #pragma unroll
                for (int nt = 0; nt < 4; nt++)
                    mma8(c[mt][nt], a[mt], b[nt]);
        }
        __syncthreads();
    }
    #pragma unroll
    for (int mt = 0; mt < 2; mt++) {
        #pragma unroll
        for (int nt = 0; nt < 4; nt++) {
            int row = bm + rmb + mt * 16 + g;
            int col = bn_dst + cnb + nt * 8 + 2 * ti;
            float b0 = 0.f, b1 = 0.f;
            if (BIAS) { b0 = bias[col - bn_dst + bn_src]; b1 = bias[col - bn_dst + bn_src + 1]; }
            float v0 = c[mt][nt][0] + b0, v1 = c[mt][nt][1] + b1;
            float v2 = c[mt][nt][2] + b0, v3 = c[mt][nt][3] + b1;
            if (SILU) {
                v0 = v0 / (1.f + __expf(-v0)); v1 = v1 / (1.f + __expf(-v1));
                v2 = v2 / (1.f + __expf(-v2)); v3 = v3 / (1.f + __expf(-v3));
            }
            *(float2*)&C[(size_t)row * ldc + col]       = make_float2(v0, v1);
            *(float2*)&C[(size_t)(row + 8) * ldc + col] = make_float2(v2, v3);
        }
    }
}

template<bool BIAS, bool SILU>
__global__ __launch_bounds__(256)
void gemm_tf32(const float* __restrict__ A, const float* __restrict__ Bm,
               const float* __restrict__ bias, float* __restrict__ C,
               int K, int lda, int ldb, int ldc) {
    gemm_body<BIAS, SILU>(A, Bm, bias, C, K, lda, ldb, ldc,
                          blockIdx.y * 128, blockIdx.x * 64, blockIdx.x * 64);
}

// fused QKV: grid (24, 128); block x selects Wq/Wk/Wv
__global__ __launch_bounds__(256)
void qkv_gemm(const float* __restrict__ feat,
              const float* __restrict__ Wq, const float* __restrict__ Wk,
              const float* __restrict__ Wv, float* __restrict__ qkv) {
    const int nb = blockIdx.x;
    const int which = nb >> 3;
    const int bn = (nb & 7) * 64;
    const float* W = (which == 0) ? Wq : (which == 1) ? Wk : Wv;
    gemm_body<false, false>(feat, W, nullptr, qkv, INDIM, INDIM, HDIM, 3*HDIM,
                            blockIdx.y * 128, bn, which * 512 + bn);
}

// ---------------- distance precompute: symmetric halves ----------------
// grid (16,16,32), active when bx>=by; 32x32 tile, writes both mirrors
__global__ __launch_bounds__(256)
void dist_kernel(const float* __restrict__ pos, float* __restrict__ dist) {
    const int bx = blockIdx.x, by = blockIdx.y, b = blockIdx.z;
    if (bx < by) return;
    __shared__ float pq[32*3], pk[32*3];
    const int t = threadIdx.x;
    const int q0 = by * 32, k0 = bx * 32;
    if (t < 96) pq[t] = pos[(size_t)(b * SEQ + q0) * 3 + t];
    else if (t < 192) pk[t-96] = pos[(size_t)(b * SEQ + k0) * 3 + (t-96)];
    __syncthreads();
    float* D = dist + (size_t)b * SEQ * SEQ;
    #pragma unroll
    for (int i = t; i < 1024; i += 256) {
        int q = i >> 5, k = i & 31;
        float dx = pq[q*3+0] - pk[k*3+0];
        float dy = pq[q*3+1] - pk[k*3+1];
        float dz = pq[q*3+2] - pk[k*3+2];
        float d2 = dx*dx + dy*dy + dz*dz;
        float d = (d2 > 0.f) ? fsqrt_fast(d2) * 1.4142135623730951f : 0.f;
        D[(size_t)(q0 + q) * SEQ + (k0 + k)] = d;
        if (bx != by) D[(size_t)(k0 + k) * SEQ + (q0 + q)] = d;
    }
}

// ---------------- fused attention, tf32 MMA, 64q x 512k -------------------
// grid (8,8,32), 512 thr (16 warps). K and V staged in NATURAL [k][d] layout.
#define SCS 520
#define QSS 68
#define KSS 68
#define VSS 72
#define ATT_FLOATS (64*SCS + 64*QSS + 128*VSS)   // 33280+4352+9216 = 46848

__global__ __launch_bounds__(512, 1)
void attn_kernel(const float* __restrict__ dist, const float* __restrict__ qkv,
                 float* __restrict__ upd) {
    extern __shared__ float sm[];
    float* sc = sm;                 // [64][520] fp32 scores/probs
    float* Qs = sm + 64*SCS;        // [64][68]  tf32
    float* KV = Qs + 64*QSS;        // Ks [128][68] / Vs [128][72]

    const int t = threadIdx.x;
    const int w = t >> 5, l = t & 31, g = l >> 2, ti = l & 3;
    const int wm = w >> 2;          // m-tile (16 rows each, 4 tiles)
    const int wn = w & 3;           // key strip (QK) / d strip (PV)
    const int qt = blockIdx.x, h = blockIdx.y, b = blockIdx.z;
    const int q0g = qt * 64, tokbase = b * SEQ;

    // stage Q (tf32)
    #pragma unroll
    for (int i = t; i < 64 * 16; i += 512) {
        int q = i >> 4, d4 = (i & 15) * 4;
        float4 v = *(const float4*)&qkv[(size_t)(tokbase + q0g + q)*1536 + h*64 + d4];
        *(float4*)&Qs[q*QSS + d4] = cvt4(v);
    }
    // init scores with distance term
    const float* dbase = dist + ((size_t)b * SEQ + q0g) * SEQ;
    #pragma unroll
    for (int i = t; i < 64 * 128; i += 512) {
        int q = i >> 7, k4 = (i & 127) * 4;
        *(float4*)&sc[q*SCS + k4] = *(const float4*)&dbase[(size_t)q * SEQ + k4];
    }

    // ---- S += QK^T * scl : 4 k-tiles of 128; warp: m-tile wm, 32 keys wn ----
    const float scl = 0.08838834764831845f;   // 1/(8*sqrt2)
    for (int kt = 0; kt < 4; kt++) {
        __syncthreads();
        #pragma unroll
        for (int i = t; i < 128 * 16; i += 512) {   // Ks[k][d] natural, tf32
            int k = i >> 4, d4 = (i & 15) * 4;
            float4 v = *(const float4*)&qkv[(size_t)(tokbase + kt*128 + k)*1536 + 512 + h*64 + d4];
            *(float4*)&KV[k*KSS + d4] = cvt4(v);
        }
        __syncthreads();
        float cS[4][4] = {};
        #pragma unroll
        for (int ks = 0; ks < 8; ks++) {
            float a[4], bf[4][2];
            a[0] = Qs[(wm*16 + g)     * QSS + ks*8 + ti];
            a[1] = Qs[(wm*16 + g + 8) * QSS + ks*8 + ti];
            a[2] = Qs[(wm*16 + g)     * QSS + ks*8 + ti + 4];
            a[3] = Qs[(wm*16 + g + 8) * QSS + ks*8 + ti + 4];
            #pragma unroll
            for (int nt = 0; nt < 4; nt++) {
                int key = wn*32 + nt*8 + g;
                bf[nt][0] = KV[key*KSS + ks*8 + ti];
                bf[nt][1] = KV[key*KSS + ks*8 + ti + 4];
            }
            #pragma unroll
            for (int nt = 0; nt < 4; nt++) mma8(cS[nt], a, bf[nt]);
        }
        #pragma unroll
        for (int nt = 0; nt < 4; nt++) {
            int r0 = wm*16 + g;
            int c0 = kt*128 + wn*32 + nt*8 + 2*ti;
            float2* p0 = (float2*)&sc[r0*SCS + c0];
            float2 u0 = *p0;
            u0.x += cS[nt][0]*scl; u0.y += cS[nt][1]*scl;
            *p0 = u0;
            float2* p1 = (float2*)&sc[(r0+8)*SCS + c0];
            float2 u1 = *p1;
            u1.x += cS[nt][2]*scl; u1.y += cS[nt][3]*scl;
            *p1 = u1;
        }
    }
    __syncthreads();

    // ---- softmax (fp32), probs tf32-rounded: 8 lanes per row, 64 rows ----
    {
        const int row = t >> 3, ll = t & 7;
        float* r = sc + row*SCS;
        float m = -1e30f;
        #pragma unroll 8
        for (int j = 0; j < 64; j++) m = fmaxf(m, r[j*8 + ll]);
        m = fmaxf(m, __shfl_xor_sync(0xffffffffu, m, 1));
        m = fmaxf(m, __shfl_xor_sync(0xffffffffu, m, 2));
        m = fmaxf(m, __shfl_xor_sync(0xffffffffu, m, 4));
        float ssum = 0.f;
        #pragma unroll 8
        for (int j = 0; j < 64; j++) {
            float e = __expf(r[j*8 + ll] - m);
            r[j*8 + ll] = e;
            ssum += e;
        }
        ssum += __shfl_xor_sync(0xffffffffu, ssum, 1);
        ssum += __shfl_xor_sync(0xffffffffu, ssum, 2);
        ssum += __shfl_xor_sync(0xffffffffu, ssum, 4);
        float inv = 1.f / ssum;
        #pragma unroll 8
        for (int j = 0; j < 64; j++) r[j*8 + ll] = totf32(r[j*8 + ll] * inv);
    }

    // ---- O = P V : warp: m-tile wm, 16 d-cols (2 n-tiles) via wn ----
    float cO[2][4] = {};
    const int dn = wn * 16;
    for (int kt = 0; kt < 4; kt++) {
        __syncthreads();
        #pragma unroll
        for (int i = t; i < 128 * 16; i += 512) {   // Vs[k][d] natural, tf32
            int k = i >> 4, d4 = (i & 15) * 4;
            float4 v = *(const float4*)&qkv[(size_t)(tokbase + kt*128 + k)*1536 + 1024 + h*64 + d4];
            *(float4*)&KV[k*VSS + d4] = cvt4(v);
        }
        __syncthreads();
        #pragma unroll
        for (int ks = 0; ks < 16; ks++) {
            int kk = kt*128 + ks*8;
            float a[4], bf[2][2];
            a[0] = sc[(wm*16 + g)     * SCS + kk + ti];
            a[1] = sc[(wm*16 + g + 8) * SCS + kk + ti];
            a[2] = sc[(wm*16 + g)     * SCS + kk + ti + 4];
            a[3] = sc[(wm*16 + g + 8) * SCS + kk + ti + 4];
            #pragma unroll
            for (int nt = 0; nt < 2; nt++) {
                bf[nt][0] = KV[(ks*8 + ti)     * VSS + dn + nt*8 + g];
                bf[nt][1] = KV[(ks*8 + ti + 4) * VSS + dn + nt*8 + g];
            }
            mma8(cO[0], a, bf[0]);
            mma8(cO[1], a, bf[1]);
        }
    }
    #pragma unroll
    for (int nt = 0; nt < 2; nt++) {
        int r = tokbase + q0g + wm*16 + g;
        int col = h*64 + dn + nt*8 + 2*ti;
        *(float2*)&upd[(size_t)r * HDIM + col]       = make_float2(cO[nt][0], cO[nt][1]);
        *(float2*)&upd[(size_t)(r + 8) * HDIM + col] = make_float2(cO[nt][2], cO[nt][3]);
    }
}

// ---------------- launch ----------------
extern "C" void kernel_launch(void* const* d_in, const int* in_sizes, int n_in,
                              void* d_out, int out_size) {
    const float* pos  = (const float*)d_in[0];
    const float* feat = (const float*)d_in[1];
    const float* Wk   = (const float*)d_in[2];
    const float* Wq   = (const float*)d_in[3];
    const float* Wv   = (const float*)d_in[4];
    const float* W1   = (const float*)d_in[5];
    const float* b1   = (const float*)d_in[6];
    const float* W2   = (const float*)d_in[7];
    const float* b2   = (const float*)d_in[8];
    const float* W3   = (const float*)d_in[9];
    const float* b3   = (const float*)d_in[10];
    float* out = (float*)d_out;

    void* p;
    cudaGetSymbolAddress(&p, g_qkv);  float* qkv  = (float*)p;
    cudaGetSymbolAddress(&p, g_upd);  float* upd  = (float*)p;
    cudaGetSymbolAddress(&p, g_dist); float* dist = (float*)p;
    cudaGetSymbolAddress(&p, g_h1);   float* h1   = (float*)p;
    cudaGetSymbolAddress(&p, g_h2);   float* h2   = (float*)p;

    dist_kernel<<<dim3(16, 16, BATCH), 256>>>(pos, dist);

    // fused QKV projections (single launch)
    qkv_gemm<<<dim3(24, MTOK/128), 256>>>(feat, Wq, Wk, Wv, qkv);

    // fused attention
    size_t shmem = (size_t)ATT_FLOATS * sizeof(float);
    cudaFuncSetAttribute(attn_kernel, cudaFuncAttributeMaxDynamicSharedMemorySize, (int)shmem);
    attn_kernel<<<dim3(SEQ/64, NHEADS, BATCH), 512, shmem>>>(dist, qkv, upd);

    // out MLP (tf32 MMA, fused bias + SiLU)
    gemm_tf32<true,true><<<dim3(2, MTOK/128), 256>>>(upd, W1, b1, h1,  HDIM, HDIM, 128, 128);
    gemm_tf32<true,true><<<dim3(1, MTOK/128), 256>>>(h1,  W2, b2, h2,  128,  128,  64,  64);
    gemm_tf32<true,true><<<dim3(4, MTOK/128), 256>>>(h2,  W3, b3, out, 64,   64,   INDIM, INDIM);
}

// round 6
// speedup vs baseline: 3.2646x; 1.1907x over previous
#include <cuda_runtime.h>
#include <math.h>
#include <stdint.h>

#define BATCH   32
#define SEQ     512
#define NHEADS  8
#define HID     64
#define INDIM   256
#define HDIM    512
#define MTOK    (BATCH*SEQ)       // 16384

// ---------------- scratch ----------------
__device__ float g_qkv [(size_t)MTOK * 3 * HDIM];
__device__ float g_upd [(size_t)MTOK * HDIM];
__device__ float g_dist[(size_t)BATCH * SEQ * SEQ];
__device__ float g_h1  [(size_t)MTOK * 128];
__device__ float g_h2  [(size_t)MTOK * 64];

// ---------------- helpers ----------------
__device__ __forceinline__ float totf32(float x) {
    uint32_t u;
    asm("cvt.rna.tf32.f32 %0, %1;" : "=r"(u) : "f"(x));
    return __uint_as_float(u);
}
__device__ __forceinline__ float4 cvt4(float4 v) {
    return make_float4(totf32(v.x), totf32(v.y), totf32(v.z), totf32(v.w));
}
__device__ __forceinline__ float fsqrt_fast(float x) {
    float y;
    asm("sqrt.approx.f32 %0, %1;" : "=f"(y) : "f"(x));
    return y;
}
__device__ __forceinline__ void mma8(float c[4], const float a[4], const float b[2]) {
    asm volatile(
        "mma.sync.aligned.m16n8k8.row.col.f32.tf32.tf32.f32 "
        "{%0,%1,%2,%3}, {%4,%5,%6,%7}, {%8,%9}, {%0,%1,%2,%3};\n"
        : "+f"(c[0]), "+f"(c[1]), "+f"(c[2]), "+f"(c[3])
        : "r"(__float_as_uint(a[0])), "r"(__float_as_uint(a[1])),
          "r"(__float_as_uint(a[2])), "r"(__float_as_uint(a[3])),
          "r"(__float_as_uint(b[0])), "r"(__float_as_uint(b[1])));
}
__device__ __forceinline__ void cp16(float* dst_smem, const float* src) {
    uint32_t d = (uint32_t)__cvta_generic_to_shared(dst_smem);
    asm volatile("cp.async.cg.shared.global [%0], [%1], 16;" :: "r"(d), "l"(src));
}
#define CP_COMMIT()  asm volatile("cp.async.commit_group;")
#define CP_WAIT0()   asm volatile("cp.async.wait_group 0;")
#define CP_WAIT1()   asm volatile("cp.async.wait_group 1;")

// ---------------- pipelined tf32 GEMM body (BM=128 BN=64 BK=32, 256 thr) ----
template<bool BIAS, bool SILU, bool ROUND>
__device__ __forceinline__
void gemm_body(const float* __restrict__ A, const float* __restrict__ Bm,
               const float* __restrict__ bias, float* __restrict__ C,
               int K, int lda, int ldb, int ldc,
               int bm, int bn_src, int bn_dst) {
    __shared__ float As[128 * 36];
    __shared__ float Bs[32 * 72];
    const int t = threadIdx.x;
    const int w = t >> 5, l = t & 31, g = l >> 2, ti = l & 3;
    const int rmb = (w >> 1) * 32, cnb = (w & 1) * 32;

    float4 ra[4], rb[2];
    #pragma unroll
    for (int j = 0; j < 4; j++) { int i = t + 256*j;
        ra[j] = *(const float4*)&A[(size_t)(bm + (i>>3)) * lda + (i&7)*4]; }
    #pragma unroll
    for (int j = 0; j < 2; j++) { int i = t + 256*j;
        rb[j] = *(const float4*)&Bm[(size_t)(i>>4) * ldb + bn_src + (i&15)*4]; }

    float c[2][4][4] = {};
    for (int kt = 0; kt < K; kt += 32) {
        #pragma unroll
        for (int j = 0; j < 4; j++) { int i = t + 256*j;
            *(float4*)&As[(i>>3)*36 + (i&7)*4] = cvt4(ra[j]); }
        #pragma unroll
        for (int j = 0; j < 2; j++) { int i = t + 256*j;
            *(float4*)&Bs[(i>>4)*72 + (i&15)*4] = cvt4(rb[j]); }
        __syncthreads();
        if (kt + 32 < K) {
            #pragma unroll
            for (int j = 0; j < 4; j++) { int i = t + 256*j;
                ra[j] = *(const float4*)&A[(size_t)(bm + (i>>3)) * lda + kt + 32 + (i&7)*4]; }
            #pragma unroll
            for (int j = 0; j < 2; j++) { int i = t + 256*j;
                rb[j] = *(const float4*)&Bm[(size_t)(kt + 32 + (i>>4)) * ldb + bn_src + (i&15)*4]; }
        }
        #pragma unroll
        for (int ks = 0; ks < 4; ks++) {
            float a[2][4], b[4][2];
            #pragma unroll
            for (int mt = 0; mt < 2; mt++) {
                int r = rmb + mt * 16;
                a[mt][0] = As[(r + g)     * 36 + ks*8 + ti];
                a[mt][1] = As[(r + g + 8) * 36 + ks*8 + ti];
                a[mt][2] = As[(r + g)     * 36 + ks*8 + ti + 4];
                a[mt][3] = As[(r + g + 8) * 36 + ks*8 + ti + 4];
            }
            #pragma unroll
            for (int nt = 0; nt < 4; nt++) {
                int cc = cnb + nt * 8 + g;
                b[nt][0] = Bs[(ks*8 + ti)     * 72 + cc];
                b[nt][1] = Bs[(ks*8 + ti + 4) * 72 + cc];
            }
            #pragma unroll
            for (int mt = 0; mt < 2; mt++)
                #pragma unroll
                for (int nt = 0; nt < 4; nt++)
                    mma8(c[mt][nt], a[mt], b[nt]);
        }
        __syncthreads();
    }
    #pragma unroll
    for (int mt = 0; mt < 2; mt++) {
        #pragma unroll
        for (int nt = 0; nt < 4; nt++) {
            int row = bm + rmb + mt * 16 + g;
            int col = bn_dst + cnb + nt * 8 + 2 * ti;
            float b0 = 0.f, b1 = 0.f;
            if (BIAS) { b0 = bias[col - bn_dst + bn_src]; b1 = bias[col - bn_dst + bn_src + 1]; }
            float v0 = c[mt][nt][0] + b0, v1 = c[mt][nt][1] + b1;
            float v2 = c[mt][nt][2] + b0, v3 = c[mt][nt][3] + b1;
            if (SILU) {
                v0 = v0 / (1.f + __expf(-v0)); v1 = v1 / (1.f + __expf(-v1));
                v2 = v2 / (1.f + __expf(-v2)); v3 = v3 / (1.f + __expf(-v3));
            }
            if (ROUND) { v0 = totf32(v0); v1 = totf32(v1); v2 = totf32(v2); v3 = totf32(v3); }
            *(float2*)&C[(size_t)row * ldc + col]       = make_float2(v0, v1);
            *(float2*)&C[(size_t)(row + 8) * ldc + col] = make_float2(v2, v3);
        }
    }
}

template<bool BIAS, bool SILU, bool ROUND>
__global__ __launch_bounds__(256)
void gemm_tf32(const float* __restrict__ A, const float* __restrict__ Bm,
               const float* __restrict__ bias, float* __restrict__ C,
               int K, int lda, int ldb, int ldc) {
    gemm_body<BIAS, SILU, ROUND>(A, Bm, bias, C, K, lda, ldb, ldc,
                                 blockIdx.y * 128, blockIdx.x * 64, blockIdx.x * 64);
}

// fused QKV: grid (24, 128); output pre-rounded to tf32 for cp.async consumers
__global__ __launch_bounds__(256)
void qkv_gemm(const float* __restrict__ feat,
              const float* __restrict__ Wq, const float* __restrict__ Wk,
              const float* __restrict__ Wv, float* __restrict__ qkv) {
    const int nb = blockIdx.x;
    const int which = nb >> 3;
    const int bn = (nb & 7) * 64;
    const float* W = (which == 0) ? Wq : (which == 1) ? Wk : Wv;
    gemm_body<false, false, true>(feat, W, nullptr, qkv, INDIM, INDIM, HDIM, 3*HDIM,
                                  blockIdx.y * 128, bn, which * 512 + bn);
}

// ---------------- distance precompute ----------------
__global__ __launch_bounds__(256)
void dist_kernel(const float* __restrict__ pos, float* __restrict__ dist) {
    const int bx = blockIdx.x, by = blockIdx.y, b = blockIdx.z;
    if (bx < by) return;
    __shared__ float pq[32*3], pk[32*3];
    const int t = threadIdx.x;
    const int q0 = by * 32, k0 = bx * 32;
    if (t < 96) pq[t] = pos[(size_t)(b * SEQ + q0) * 3 + t];
    else if (t < 192) pk[t-96] = pos[(size_t)(b * SEQ + k0) * 3 + (t-96)];
    __syncthreads();
    float* D = dist + (size_t)b * SEQ * SEQ;
    #pragma unroll
    for (int i = t; i < 1024; i += 256) {
        int q = i >> 5, k = i & 31;
        float dx = pq[q*3+0] - pk[k*3+0];
        float dy = pq[q*3+1] - pk[k*3+1];
        float dz = pq[q*3+2] - pk[k*3+2];
        float d2 = dx*dx + dy*dy + dz*dz;
        float d = (d2 > 0.f) ? fsqrt_fast(d2) * 1.4142135623730951f : 0.f;
        D[(size_t)(q0 + q) * SEQ + (k0 + k)] = d;
        if (bx != by) D[(size_t)(k0 + k) * SEQ + (q0 + q)] = d;
    }
}

// ---------------- fused attention, tf32 MMA, 64q x 512k, cp.async ----------
#define SCS 516
#define QSS 68
#define KSS 68
#define VSS 72
#define OFS_Q  (64*SCS)                  // 33024
#define OFS_KV (OFS_Q + 64*QSS)          // 37376
#define VBUF   (128*VSS)                 // 9216 floats per V buffer
#define ATT_FLOATS (OFS_KV + 2*VBUF)     // 55808 floats = 223232 B

__global__ __launch_bounds__(512, 1)
void attn_kernel(const float* __restrict__ dist, const float* __restrict__ qkv,
                 float* __restrict__ upd) {
    extern __shared__ float sm[];
    float* sc = sm;                 // [64][516] scores/probs
    float* Qs = sm + OFS_Q;         // [64][68]
    float* KV = sm + OFS_KV;        // K tile [256][68]  /  V dbl-buf 2x[128][72]

    const int t = threadIdx.x;
    const int w = t >> 5, l = t & 31, g = l >> 2, ti = l & 3;
    const int qt = blockIdx.x, h = blockIdx.y, b = blockIdx.z;
    const int q0g = qt * 64, tokbase = b * SEQ;

    // async stage: dist -> sc, Q -> Qs, K keys 0..255 -> KV   (qkv pre-rounded tf32)
    const float* dbase = dist + ((size_t)b * SEQ + q0g) * SEQ;
    #pragma unroll
    for (int i = t; i < 64 * 128; i += 512) {
        int q = i >> 7, k4 = (i & 127) * 4;
        cp16(&sc[q*SCS + k4], &dbase[(size_t)q * SEQ + k4]);
    }
    #pragma unroll
    for (int i = t; i < 64 * 16; i += 512) {
        int q = i >> 4, d4 = (i & 15) * 4;
        cp16(&Qs[q*QSS + d4], &qkv[(size_t)(tokbase + q0g + q)*1536 + h*64 + d4]);
    }
    #pragma unroll
    for (int i = t; i < 256 * 16; i += 512) {
        int k = i >> 4, d4 = (i & 15) * 4;
        cp16(&KV[k*KSS + d4], &qkv[(size_t)(tokbase + k)*1536 + 512 + h*64 + d4]);
    }
    CP_COMMIT();

    // ---- S += QK^T * scl : 2 k-tiles of 256; warps 2m x 8n, mt=2 nt=4 ----
    const float scl = 0.08838834764831845f;   // 1/(8*sqrt2)
    const int wm2 = w >> 3, wn8 = w & 7;
    for (int kt = 0; kt < 2; kt++) {
        CP_WAIT0();
        __syncthreads();
        float cS[2][4][4] = {};
        #pragma unroll
        for (int ks = 0; ks < 8; ks++) {
            float a[2][4], bf[4][2];
            #pragma unroll
            for (int mt = 0; mt < 2; mt++) {
                int r = wm2*32 + mt*16;
                a[mt][0] = Qs[(r + g)     * QSS + ks*8 + ti];
                a[mt][1] = Qs[(r + g + 8) * QSS + ks*8 + ti];
                a[mt][2] = Qs[(r + g)     * QSS + ks*8 + ti + 4];
                a[mt][3] = Qs[(r + g + 8) * QSS + ks*8 + ti + 4];
            }
            #pragma unroll
            for (int nt = 0; nt < 4; nt++) {
                int key = wn8*32 + nt*8 + g;
                bf[nt][0] = KV[key*KSS + ks*8 + ti];
                bf[nt][1] = KV[key*KSS + ks*8 + ti + 4];
            }
            #pragma unroll
            for (int mt = 0; mt < 2; mt++)
                #pragma unroll
                for (int nt = 0; nt < 4; nt++)
                    mma8(cS[mt][nt], a[mt], bf[nt]);
        }
        __syncthreads();            // all warps done reading K tile
        if (kt == 0) {              // stage K keys 256..511 (overlaps writeback)
            #pragma unroll
            for (int i = t; i < 256 * 16; i += 512) {
                int k = i >> 4, d4 = (i & 15) * 4;
                cp16(&KV[k*KSS + d4], &qkv[(size_t)(tokbase + 256 + k)*1536 + 512 + h*64 + d4]);
            }
            CP_COMMIT();
        }
        #pragma unroll
        for (int mt = 0; mt < 2; mt++)
            #pragma unroll
            for (int nt = 0; nt < 4; nt++) {
                int r0 = wm2*32 + mt*16 + g;
                int c0 = kt*256 + wn8*32 + nt*8 + 2*ti;
                float2* p0 = (float2*)&sc[r0*SCS + c0];
                float2 u0 = *p0;
                u0.x += cS[mt][nt][0]*scl; u0.y += cS[mt][nt][1]*scl;
                *p0 = u0;
                float2* p1 = (float2*)&sc[(r0+8)*SCS + c0];
                float2 u1 = *p1;
                u1.x += cS[mt][nt][2]*scl; u1.y += cS[mt][nt][3]*scl;
                *p1 = u1;
            }
    }
    __syncthreads();

    // prefetch V chunks 0,1 (overlaps softmax)
    #pragma unroll
    for (int i = t; i < 128 * 16; i += 512) {
        int k = i >> 4, d4 = (i & 15) * 4;
        cp16(&KV[k*VSS + d4], &qkv[(size_t)(tokbase + k)*1536 + 1024 + h*64 + d4]);
    }
    CP_COMMIT();
    #pragma unroll
    for (int i = t; i < 128 * 16; i += 512) {
        int k = i >> 4, d4 = (i & 15) * 4;
        cp16(&KV[VBUF + k*VSS + d4], &qkv[(size_t)(tokbase + 128 + k)*1536 + 1024 + h*64 + d4]);
    }
    CP_COMMIT();

    // ---- softmax: one warp per row (conflict-free), 4 rows/warp ----
    for (int r = w; r < 64; r += 16) {
        float* row = sc + r*SCS;
        float m = -1e30f;
        #pragma unroll
        for (int j = 0; j < 16; j++) m = fmaxf(m, row[j*32 + l]);
        #pragma unroll
        for (int o = 16; o > 0; o >>= 1) m = fmaxf(m, __shfl_xor_sync(0xffffffffu, m, o));
        float s = 0.f;
        #pragma unroll
        for (int j = 0; j < 16; j++) {
            float e = __expf(row[j*32 + l] - m);
            row[j*32 + l] = e;
            s += e;
        }
        #pragma unroll
        for (int o = 16; o > 0; o >>= 1) s += __shfl_xor_sync(0xffffffffu, s, o);
        float inv = 1.f / s;
        #pragma unroll
        for (int j = 0; j < 16; j++) row[j*32 + l] = totf32(row[j*32 + l] * inv);
    }
    __syncthreads();

    // ---- O = P V : 4 chunks of 128 keys, double-buffered ----
    float cO[2][4] = {};
    const int wm = w >> 2, wn = w & 3, dn = wn * 16;
    for (int c = 0; c < 4; c++) {
        if (c < 3) { CP_WAIT1(); } else { CP_WAIT0(); }
        __syncthreads();
        const float* Vb = KV + (c & 1) * VBUF;
        #pragma unroll
        for (int ks = 0; ks < 16; ks++) {
            int kk = c*128 + ks*8;
            float a[4], bf[2][2];
            a[0] = sc[(wm*16 + g)     * SCS + kk + ti];
            a[1] = sc[(wm*16 + g + 8) * SCS + kk + ti];
            a[2] = sc[(wm*16 + g)     * SCS + kk + ti + 4];
            a[3] = sc[(wm*16 + g + 8) * SCS + kk + ti + 4];
            #pragma unroll
            for (int nt = 0; nt < 2; nt++) {
                bf[nt][0] = Vb[(ks*8 + ti)     * VSS + dn + nt*8 + g];
                bf[nt][1] = Vb[(ks*8 + ti + 4) * VSS + dn + nt*8 + g];
            }
            mma8(cO[0], a, bf[0]);
            mma8(cO[1], a, bf[1]);
        }
        __syncthreads();            // buffer (c&1) free
        if (c + 2 < 4) {
            #pragma unroll
            for (int i = t; i < 128 * 16; i += 512) {
                int k = i >> 4, d4 = (i & 15) * 4;
                cp16(&KV[(c & 1)*VBUF + k*VSS + d4],
                     &qkv[(size_t)(tokbase + (c+2)*128 + k)*1536 + 1024 + h*64 + d4]);
            }
            CP_COMMIT();
        }
    }
    // write O (pre-rounded tf32 for the MLP)
    #pragma unroll
    for (int nt = 0; nt < 2; nt++) {
        int r = tokbase + q0g + wm*16 + g;
        int col = h*64 + dn + nt*8 + 2*ti;
        *(float2*)&upd[(size_t)r * HDIM + col] =
            make_float2(totf32(cO[nt][0]), totf32(cO[nt][1]));
        *(float2*)&upd[(size_t)(r + 8) * HDIM + col] =
            make_float2(totf32(cO[nt][2]), totf32(cO[nt][3]));
    }
}

// ---------------- launch ----------------
extern "C" void kernel_launch(void* const* d_in, const int* in_sizes, int n_in,
                              void* d_out, int out_size) {
    const float* pos  = (const float*)d_in[0];
    const float* feat = (const float*)d_in[1];
    const float* Wk   = (const float*)d_in[2];
    const float* Wq   = (const float*)d_in[3];
    const float* Wv   = (const float*)d_in[4];
    const float* W1   = (const float*)d_in[5];
    const float* b1   = (const float*)d_in[6];
    const float* W2   = (const float*)d_in[7];
    const float* b2   = (const float*)d_in[8];
    const float* W3   = (const float*)d_in[9];
    const float* b3   = (const float*)d_in[10];
    float* out = (float*)d_out;

    void* p;
    cudaGetSymbolAddress(&p, g_qkv);  float* qkv  = (float*)p;
    cudaGetSymbolAddress(&p, g_upd);  float* upd  = (float*)p;
    cudaGetSymbolAddress(&p, g_dist); float* dist = (float*)p;
    cudaGetSymbolAddress(&p, g_h1);   float* h1   = (float*)p;
    cudaGetSymbolAddress(&p, g_h2);   float* h2   = (float*)p;

    dist_kernel<<<dim3(16, 16, BATCH), 256>>>(pos, dist);

    qkv_gemm<<<dim3(24, MTOK/128), 256>>>(feat, Wq, Wk, Wv, qkv);

    size_t shmem = (size_t)ATT_FLOATS * sizeof(float);
    cudaFuncSetAttribute(attn_kernel, cudaFuncAttributeMaxDynamicSharedMemorySize, (int)shmem);
    attn_kernel<<<dim3(SEQ/64, NHEADS, BATCH), 512, shmem>>>(dist, qkv, upd);

    gemm_tf32<true,true,true ><<<dim3(2, MTOK/128), 256>>>(upd, W1, b1, h1,  HDIM, HDIM, 128, 128);
    gemm_tf32<true,true,true ><<<dim3(1, MTOK/128), 256>>>(h1,  W2, b2, h2,  128,  128,  64,  64);
    gemm_tf32<true,true,false><<<dim3(4, MTOK/128), 256>>>(h2,  W3, b3, out, 64,   64,   INDIM, INDIM);
}

// round 7
// speedup vs baseline: 3.3940x; 1.0396x over previous
#include <cuda_runtime.h>
#include <math.h>
#include <stdint.h>

#define BATCH   32
#define SEQ     512
#define NHEADS  8
#define HID     64
#define INDIM   256
#define HDIM    512
#define MTOK    (BATCH*SEQ)       // 16384

// ---------------- scratch ----------------
__device__ float g_qkv [(size_t)MTOK * 3 * HDIM];
__device__ float g_upd [(size_t)MTOK * HDIM];
__device__ float g_dist[(size_t)BATCH * SEQ * SEQ];   // dist * sqrt2 * log2(e)
__device__ float g_h1  [(size_t)MTOK * 128];
__device__ float g_h2  [(size_t)MTOK * 64];

// ---------------- helpers ----------------
__device__ __forceinline__ float totf32(float x) {
    uint32_t u;
    asm("cvt.rna.tf32.f32 %0, %1;" : "=r"(u) : "f"(x));
    return __uint_as_float(u);
}
__device__ __forceinline__ float4 cvt4(float4 v) {
    return make_float4(totf32(v.x), totf32(v.y), totf32(v.z), totf32(v.w));
}
__device__ __forceinline__ float fsqrt_fast(float x) {
    float y;
    asm("sqrt.approx.f32 %0, %1;" : "=f"(y) : "f"(x));
    return y;
}
// 2^x via FMA pipe (no MUFU). |rel err| ~2e-6, then tf32-rounded anyway.
__device__ __forceinline__ float exp2_fast(float x) {
    x = fminf(fmaxf(x, -120.f), 120.f);
    float z = x + 12582912.0f;                 // 1.5*2^23: round-to-nearest-int
    float n = z - 12582912.0f;
    float r = x - n;                           // r in [-0.5, 0.5]
    int   ni = __float_as_int(z) - 0x4B400000;
    float s = __int_as_float((ni + 127) << 23);
    float p = 1.3333558e-3f;
    p = fmaf(p, r, 9.6181291e-3f);
    p = fmaf(p, r, 5.5504110e-2f);
    p = fmaf(p, r, 2.4022651e-1f);
    p = fmaf(p, r, 6.9314718e-1f);
    p = fmaf(p, r, 1.0f);
    return p * s;
}
__device__ __forceinline__ void mma8(float c[4], const float a[4], const float b[2]) {
    asm volatile(
        "mma.sync.aligned.m16n8k8.row.col.f32.tf32.tf32.f32 "
        "{%0,%1,%2,%3}, {%4,%5,%6,%7}, {%8,%9}, {%0,%1,%2,%3};\n"
        : "+f"(c[0]), "+f"(c[1]), "+f"(c[2]), "+f"(c[3])
        : "r"(__float_as_uint(a[0])), "r"(__float_as_uint(a[1])),
          "r"(__float_as_uint(a[2])), "r"(__float_as_uint(a[3])),
          "r"(__float_as_uint(b[0])), "r"(__float_as_uint(b[1])));
}
__device__ __forceinline__ void cp16(float* dst_smem, const float* src) {
    uint32_t d = (uint32_t)__cvta_generic_to_shared(dst_smem);
    asm volatile("cp.async.cg.shared.global [%0], [%1], 16;" :: "r"(d), "l"(src));
}
#define CP_COMMIT()  asm volatile("cp.async.commit_group;")
#define CP_WAIT0()   asm volatile("cp.async.wait_group 0;")
#define CP_WAIT1()   asm volatile("cp.async.wait_group 1;")

// ---------------- pipelined tf32 GEMM body (BM=128 BN=64 BK=32, 256 thr) ----
template<bool BIAS, bool SILU, bool ROUND>
__device__ __forceinline__
void gemm_body(const float* __restrict__ A, const float* __restrict__ Bm,
               const float* __restrict__ bias, float* __restrict__ C,
               int K, int lda, int ldb, int ldc,
               int bm, int bn_src, int bn_dst) {
    __shared__ float As[128 * 36];
    __shared__ float Bs[32 * 72];
    const int t = threadIdx.x;
    const int w = t >> 5, l = t & 31, g = l >> 2, ti = l & 3;
    const int rmb = (w >> 1) * 32, cnb = (w & 1) * 32;

    float4 ra[4], rb[2];
    #pragma unroll
    for (int j = 0; j < 4; j++) { int i = t + 256*j;
        ra[j] = *(const float4*)&A[(size_t)(bm + (i>>3)) * lda + (i&7)*4]; }
    #pragma unroll
    for (int j = 0; j < 2; j++) { int i = t + 256*j;
        rb[j] = *(const float4*)&Bm[(size_t)(i>>4) * ldb + bn_src + (i&15)*4]; }

    float c[2][4][4] = {};
    for (int kt = 0; kt < K; kt += 32) {
        #pragma unroll
        for (int j = 0; j < 4; j++) { int i = t + 256*j;
            *(float4*)&As[(i>>3)*36 + (i&7)*4] = cvt4(ra[j]); }
        #pragma unroll
        for (int j = 0; j < 2; j++) { int i = t + 256*j;
            *(float4*)&Bs[(i>>4)*72 + (i&15)*4] = cvt4(rb[j]); }
        __syncthreads();
        if (kt + 32 < K) {
            #pragma unroll
            for (int j = 0; j < 4; j++) { int i = t + 256*j;
                ra[j] = *(const float4*)&A[(size_t)(bm + (i>>3)) * lda + kt + 32 + (i&7)*4]; }
            #pragma unroll
            for (int j = 0; j < 2; j++) { int i = t + 256*j;
                rb[j] = *(const float4*)&Bm[(size_t)(kt + 32 + (i>>4)) * ldb + bn_src + (i&15)*4]; }
        }
        #pragma unroll
        for (int ks = 0; ks < 4; ks++) {
            float a[2][4], b[4][2];
            #pragma unroll
            for (int mt = 0; mt < 2; mt++) {
                int r = rmb + mt * 16;
                a[mt][0] = As[(r + g)     * 36 + ks*8 + ti];
                a[mt][1] = As[(r + g + 8) * 36 + ks*8 + ti];
                a[mt][2] = As[(r + g)     * 36 + ks*8 + ti + 4];
                a[mt][3] = As[(r + g + 8) * 36 + ks*8 + ti + 4];
            }
            #pragma unroll
            for (int nt = 0; nt < 4; nt++) {
                int cc = cnb + nt * 8 + g;
                b[nt][0] = Bs[(ks*8 + ti)     * 72 + cc];
                b[nt][1] = Bs[(ks*8 + ti + 4) * 72 + cc];
            }
            #pragma unroll
            for (int mt = 0; mt < 2; mt++)
                #pragma unroll
                for (int nt = 0; nt < 4; nt++)
                    mma8(c[mt][nt], a[mt], b[nt]);
        }
        __syncthreads();
    }
    #pragma unroll
    for (int mt = 0; mt < 2; mt++) {
        #pragma unroll
        for (int nt = 0; nt < 4; nt++) {
            int row = bm + rmb + mt * 16 + g;
            int col = bn_dst + cnb + nt * 8 + 2 * ti;
            float b0 = 0.f, b1 = 0.f;
            if (BIAS) { b0 = bias[col - bn_dst + bn_src]; b1 = bias[col - bn_dst + bn_src + 1]; }
            float v0 = c[mt][nt][0] + b0, v1 = c[mt][nt][1] + b1;
            float v2 = c[mt][nt][2] + b0, v3 = c[mt][nt][3] + b1;
            if (SILU) {
                v0 = v0 / (1.f + __expf(-v0)); v1 = v1 / (1.f + __expf(-v1));
                v2 = v2 / (1.f + __expf(-v2)); v3 = v3 / (1.f + __expf(-v3));
            }
            if (ROUND) { v0 = totf32(v0); v1 = totf32(v1); v2 = totf32(v2); v3 = totf32(v3); }
            *(float2*)&C[(size_t)row * ldc + col]       = make_float2(v0, v1);
            *(float2*)&C[(size_t)(row + 8) * ldc + col] = make_float2(v2, v3);
        }
    }
}

template<bool BIAS, bool SILU, bool ROUND>
__global__ __launch_bounds__(256)
void gemm_tf32(const float* __restrict__ A, const float* __restrict__ Bm,
               const float* __restrict__ bias, float* __restrict__ C,
               int K, int lda, int ldb, int ldc) {
    gemm_body<BIAS, SILU, ROUND>(A, Bm, bias, C, K, lda, ldb, ldc,
                                 blockIdx.y * 128, blockIdx.x * 64, blockIdx.x * 64);
}

// fused QKV: grid (24, 128); output pre-rounded to tf32 for cp.async consumers
__global__ __launch_bounds__(256)
void qkv_gemm(const float* __restrict__ feat,
              const float* __restrict__ Wq, const float* __restrict__ Wk,
              const float* __restrict__ Wv, float* __restrict__ qkv) {
    const int nb = blockIdx.x;
    const int which = nb >> 3;
    const int bn = (nb & 7) * 64;
    const float* W = (which == 0) ? Wq : (which == 1) ? Wk : Wv;
    gemm_body<false, false, true>(feat, W, nullptr, qkv, INDIM, INDIM, HDIM, 3*HDIM,
                                  blockIdx.y * 128, bn, which * 512 + bn);
}

// ---------------- distance precompute: log2-domain -------------------------
// stores dist(b,q,k) * sqrt(2) * log2(e)  (ready to feed exp2)
__global__ __launch_bounds__(256)
void dist_kernel(const float* __restrict__ pos, float* __restrict__ dist) {
    const int bx = blockIdx.x, by = blockIdx.y, b = blockIdx.z;
    if (bx < by) return;
    __shared__ float pq[32*3], pk[32*3];
    const int t = threadIdx.x;
    const int q0 = by * 32, k0 = bx * 32;
    if (t < 96) pq[t] = pos[(size_t)(b * SEQ + q0) * 3 + t];
    else if (t < 192) pk[t-96] = pos[(size_t)(b * SEQ + k0) * 3 + (t-96)];
    __syncthreads();
    const float C2 = (float)(1.4142135623730951 * 1.4426950408889634);
    float* D = dist + (size_t)b * SEQ * SEQ;
    #pragma unroll
    for (int i = t; i < 1024; i += 256) {
        int q = i >> 5, k = i & 31;
        float dx = pq[q*3+0] - pk[k*3+0];
        float dy = pq[q*3+1] - pk[k*3+1];
        float dz = pq[q*3+2] - pk[k*3+2];
        float d2 = dx*dx + dy*dy + dz*dz;
        float d = (d2 > 0.f) ? fsqrt_fast(d2) * C2 : 0.f;
        D[(size_t)(q0 + q) * SEQ + (k0 + k)] = d;
        if (bx != by) D[(size_t)(k0 + k) * SEQ + (q0 + q)] = d;
    }
}

// ---------------- fused attention, tf32 MMA, 64q x 512k, cp.async ----------
// exp fused into QK epilogue (no max pass: scores provably bounded),
// normalization deferred to PV epilogue.
#define SCS 516
#define QSS 68
#define KSS 68
#define VSS 72
#define OFS_Q  (64*SCS)                  // 33024
#define OFS_KV (OFS_Q + 64*QSS)          // 37376
#define VBUF   (128*VSS)                 // 9216 floats per V buffer
#define ATT_FLOATS (OFS_KV + 2*VBUF)     // 55808 floats = 223232 B

__global__ __launch_bounds__(512, 1)
void attn_kernel(const float* __restrict__ dist, const float* __restrict__ qkv,
                 float* __restrict__ upd) {
    extern __shared__ float sm[];
    float* sc = sm;                 // [64][516] dist -> exp(scores)
    float* Qs = sm + OFS_Q;         // [64][68]; first 64 floats reused as 1/rowsum
    float* KV = sm + OFS_KV;        // K tile [256][68]  /  V dbl-buf 2x[128][72]
    float* rsum = Qs;

    const int t = threadIdx.x;
    const int w = t >> 5, l = t & 31, g = l >> 2, ti = l & 3;
    const int qt = blockIdx.x, h = blockIdx.y, b = blockIdx.z;
    const int q0g = qt * 64, tokbase = b * SEQ;

    // async stage: dist -> sc, Q -> Qs, K keys 0..255 -> KV   (qkv pre-rounded tf32)
    const float* dbase = dist + ((size_t)b * SEQ + q0g) * SEQ;
    #pragma unroll
    for (int i = t; i < 64 * 128; i += 512) {
        int q = i >> 7, k4 = (i & 127) * 4;
        cp16(&sc[q*SCS + k4], &dbase[(size_t)q * SEQ + k4]);
    }
    #pragma unroll
    for (int i = t; i < 64 * 16; i += 512) {
        int q = i >> 4, d4 = (i & 15) * 4;
        cp16(&Qs[q*QSS + d4], &qkv[(size_t)(tokbase + q0g + q)*1536 + h*64 + d4]);
    }
    #pragma unroll
    for (int i = t; i < 256 * 16; i += 512) {
        int k = i >> 4, d4 = (i & 15) * 4;
        cp16(&KV[k*KSS + d4], &qkv[(size_t)(tokbase + k)*1536 + 512 + h*64 + d4]);
    }
    CP_COMMIT();

    // ---- P = exp(S) fused: 2 k-tiles of 256; warps 2m x 8n, mt=2 nt=4 ----
    // K1 = log2(e) / (8*sqrt(2));  dist already in log2 domain
    const float K1 = (float)(1.4426950408889634 * 0.08838834764831845);
    const int wm2 = w >> 3, wn8 = w & 7;
    for (int kt = 0; kt < 2; kt++) {
        CP_WAIT0();
        __syncthreads();
        float cS[2][4][4] = {};
        #pragma unroll
        for (int ks = 0; ks < 8; ks++) {
            float a[2][4], bf[4][2];
            #pragma unroll
            for (int mt = 0; mt < 2; mt++) {
                int r = wm2*32 + mt*16;
                a[mt][0] = Qs[(r + g)     * QSS + ks*8 + ti];
                a[mt][1] = Qs[(r + g + 8) * QSS + ks*8 + ti];
                a[mt][2] = Qs[(r + g)     * QSS + ks*8 + ti + 4];
                a[mt][3] = Qs[(r + g + 8) * QSS + ks*8 + ti + 4];
            }
            #pragma unroll
            for (int nt = 0; nt < 4; nt++) {
                int key = wn8*32 + nt*8 + g;
                bf[nt][0] = KV[key*KSS + ks*8 + ti];
                bf[nt][1] = KV[key*KSS + ks*8 + ti + 4];
            }
            #pragma unroll
            for (int mt = 0; mt < 2; mt++)
                #pragma unroll
                for (int nt = 0; nt < 4; nt++)
                    mma8(cS[mt][nt], a[mt], bf[nt]);
        }
        __syncthreads();            // all warps done reading K tile
        if (kt == 0) {              // stage K keys 256..511 (overlaps epilogue)
            #pragma unroll
            for (int i = t; i < 256 * 16; i += 512) {
                int k = i >> 4, d4 = (i & 15) * 4;
                cp16(&KV[k*KSS + d4], &qkv[(size_t)(tokbase + 256 + k)*1536 + 512 + h*64 + d4]);
            }
            CP_COMMIT();
        }
        #pragma unroll
        for (int mt = 0; mt < 2; mt++)
            #pragma unroll
            for (int nt = 0; nt < 4; nt++) {
                int r0 = wm2*32 + mt*16 + g;
                int c0 = kt*256 + wn8*32 + nt*8 + 2*ti;
                float2* p0 = (float2*)&sc[r0*SCS + c0];
                float2 u0 = *p0;
                u0.x = totf32(exp2_fast(fmaf(cS[mt][nt][0], K1, u0.x)));
                u0.y = totf32(exp2_fast(fmaf(cS[mt][nt][1], K1, u0.y)));
                *p0 = u0;
                float2* p1 = (float2*)&sc[(r0+8)*SCS + c0];
                float2 u1 = *p1;
                u1.x = totf32(exp2_fast(fmaf(cS[mt][nt][2], K1, u1.x)));
                u1.y = totf32(exp2_fast(fmaf(cS[mt][nt][3], K1, u1.y)));
                *p1 = u1;
            }
    }
    __syncthreads();

    // prefetch V chunks 0,1 (overlaps row-sum)
    #pragma unroll
    for (int i = t; i < 128 * 16; i += 512) {
        int k = i >> 4, d4 = (i & 15) * 4;
        cp16(&KV[k*VSS + d4], &qkv[(size_t)(tokbase + k)*1536 + 1024 + h*64 + d4]);
    }
    CP_COMMIT();
    #pragma unroll
    for (int i = t; i < 128 * 16; i += 512) {
        int k = i >> 4, d4 = (i & 15) * 4;
        cp16(&KV[VBUF + k*VSS + d4], &qkv[(size_t)(tokbase + 128 + k)*1536 + 1024 + h*64 + d4]);
    }
    CP_COMMIT();

    // ---- row-sum only (one warp per row); norm deferred to PV epilogue ----
    for (int r = w; r < 64; r += 16) {
        const float* row = sc + r*SCS;
        float s = 0.f;
        #pragma unroll
        for (int j = 0; j < 16; j++) s += row[j*32 + l];
        #pragma unroll
        for (int o = 16; o > 0; o >>= 1) s += __shfl_xor_sync(0xffffffffu, s, o);
        if (l == 0) rsum[r] = 1.f / s;
    }
    __syncthreads();

    // ---- O = P V : 4 chunks of 128 keys, double-buffered ----
    float cO[2][4] = {};
    const int wm = w >> 2, wn = w & 3, dn = wn * 16;
    for (int c = 0; c < 4; c++) {
        if (c < 3) { CP_WAIT1(); } else { CP_WAIT0(); }
        __syncthreads();
        const float* Vb = KV + (c & 1) * VBUF;
        #pragma unroll
        for (int ks = 0; ks < 16; ks++) {
            int kk = c*128 + ks*8;
            float a[4], bf[2][2];
            a[0] = sc[(wm*16 + g)     * SCS + kk + ti];
            a[1] = sc[(wm*16 + g + 8) * SCS + kk + ti];
            a[2] = sc[(wm*16 + g)     * SCS + kk + ti + 4];
            a[3] = sc[(wm*16 + g + 8) * SCS + kk + ti + 4];
            #pragma unroll
            for (int nt = 0; nt < 2; nt++) {
                bf[nt][0] = Vb[(ks*8 + ti)     * VSS + dn + nt*8 + g];
                bf[nt][1] = Vb[(ks*8 + ti + 4) * VSS + dn + nt*8 + g];
            }
            mma8(cO[0], a, bf[0]);
            mma8(cO[1], a, bf[1]);
        }
        __syncthreads();            // buffer (c&1) free
        if (c + 2 < 4) {
            #pragma unroll
            for (int i = t; i < 128 * 16; i += 512) {
                int k = i >> 4, d4 = (i & 15) * 4;
                cp16(&KV[(c & 1)*VBUF + k*VSS + d4],
                     &qkv[(size_t)(tokbase + (c+2)*128 + k)*1536 + 1024 + h*64 + d4]);
            }
            CP_COMMIT();
        }
    }
    // write O, normalized + pre-rounded tf32 for the MLP
    {
        float inv0 = rsum[wm*16 + g];
        float inv1 = rsum[wm*16 + g + 8];
        #pragma unroll
        for (int nt = 0; nt < 2; nt++) {
            int r = tokbase + q0g + wm*16 + g;
            int col = h*64 + dn + nt*8 + 2*ti;
            *(float2*)&upd[(size_t)r * HDIM + col] =
                make_float2(totf32(cO[nt][0]*inv0), totf32(cO[nt][1]*inv0));
            *(float2*)&upd[(size_t)(r + 8) * HDIM + col] =
                make_float2(totf32(cO[nt][2]*inv1), totf32(cO[nt][3]*inv1));
        }
    }
}

// ---------------- launch ----------------
extern "C" void kernel_launch(void* const* d_in, const int* in_sizes, int n_in,
                              void* d_out, int out_size) {
    const float* pos  = (const float*)d_in[0];
    const float* feat = (const float*)d_in[1];
    const float* Wk   = (const float*)d_in[2];
    const float* Wq   = (const float*)d_in[3];
    const float* Wv   = (const float*)d_in[4];
    const float* W1   = (const float*)d_in[5];
    const float* b1   = (const float*)d_in[6];
    const float* W2   = (const float*)d_in[7];
    const float* b2   = (const float*)d_in[8];
    const float* W3   = (const float*)d_in[9];
    const float* b3   = (const float*)d_in[10];
    float* out = (float*)d_out;

    void* p;
    cudaGetSymbolAddress(&p, g_qkv);  float* qkv  = (float*)p;
    cudaGetSymbolAddress(&p, g_upd);  float* upd  = (float*)p;
    cudaGetSymbolAddress(&p, g_dist); float* dist = (float*)p;
    cudaGetSymbolAddress(&p, g_h1);   float* h1   = (float*)p;
    cudaGetSymbolAddress(&p, g_h2);   float* h2   = (float*)p;

    dist_kernel<<<dim3(16, 16, BATCH), 256>>>(pos, dist);

    qkv_gemm<<<dim3(24, MTOK/128), 256>>>(feat, Wq, Wk, Wv, qkv);

    size_t shmem = (size_t)ATT_FLOATS * sizeof(float);
    cudaFuncSetAttribute(attn_kernel, cudaFuncAttributeMaxDynamicSharedMemorySize, (int)shmem);
    attn_kernel<<<dim3(SEQ/64, NHEADS, BATCH), 512, shmem>>>(dist, qkv, upd);

    gemm_tf32<true,true,true ><<<dim3(2, MTOK/128), 256>>>(upd, W1, b1, h1,  HDIM, HDIM, 128, 128);
    gemm_tf32<true,true,true ><<<dim3(1, MTOK/128), 256>>>(h1,  W2, b2, h2,  128,  128,  64,  64);
    gemm_tf32<true,true,false><<<dim3(4, MTOK/128), 256>>>(h2,  W3, b3, out, 64,   64,   INDIM, INDIM);
}

// round 8
// speedup vs baseline: 3.6516x; 1.0759x over previous
#include <cuda_runtime.h>
#include <math.h>
#include <stdint.h>

#define BATCH   32
#define SEQ     512
#define NHEADS  8
#define HID     64
#define INDIM   256
#define HDIM    512
#define MTOK    (BATCH*SEQ)       // 16384

// ---------------- scratch ----------------
__device__ float g_qkv [(size_t)MTOK * 3 * HDIM];
__device__ float g_upd [(size_t)MTOK * HDIM];
__device__ float g_dist[(size_t)BATCH * SEQ * SEQ];   // dist * sqrt2 * log2(e)
__device__ float g_h1  [(size_t)MTOK * 128];
__device__ float g_h2  [(size_t)MTOK * 64];

// ---------------- helpers ----------------
__device__ __forceinline__ float totf32(float x) {
    uint32_t u;
    asm("cvt.rna.tf32.f32 %0, %1;" : "=r"(u) : "f"(x));
    return __uint_as_float(u);
}
__device__ __forceinline__ float4 cvt4(float4 v) {
    return make_float4(totf32(v.x), totf32(v.y), totf32(v.z), totf32(v.w));
}
__device__ __forceinline__ float fsqrt_fast(float x) {
    float y;
    asm("sqrt.approx.f32 %0, %1;" : "=f"(y) : "f"(x));
    return y;
}
// 2^x via FMA pipe (no MUFU). |rel err| ~2e-6, then tf32-rounded anyway.
__device__ __forceinline__ float exp2_fast(float x) {
    x = fminf(fmaxf(x, -120.f), 120.f);
    float z = x + 12582912.0f;                 // 1.5*2^23: round-to-nearest-int
    float n = z - 12582912.0f;
    float r = x - n;                           // r in [-0.5, 0.5]
    int   ni = __float_as_int(z) - 0x4B400000;
    float s = __int_as_float((ni + 127) << 23);
    float p = 1.3333558e-3f;
    p = fmaf(p, r, 9.6181291e-3f);
    p = fmaf(p, r, 5.5504110e-2f);
    p = fmaf(p, r, 2.4022651e-1f);
    p = fmaf(p, r, 6.9314718e-1f);
    p = fmaf(p, r, 1.0f);
    return p * s;
}
__device__ __forceinline__ void mma8(float c[4], const float a[4], const float b[2]) {
    asm volatile(
        "mma.sync.aligned.m16n8k8.row.col.f32.tf32.tf32.f32 "
        "{%0,%1,%2,%3}, {%4,%5,%6,%7}, {%8,%9}, {%0,%1,%2,%3};\n"
        : "+f"(c[0]), "+f"(c[1]), "+f"(c[2]), "+f"(c[3])
        : "r"(__float_as_uint(a[0])), "r"(__float_as_uint(a[1])),
          "r"(__float_as_uint(a[2])), "r"(__float_as_uint(a[3])),
          "r"(__float_as_uint(b[0])), "r"(__float_as_uint(b[1])));
}
__device__ __forceinline__ void cp16(float* dst_smem, const float* src) {
    uint32_t d = (uint32_t)__cvta_generic_to_shared(dst_smem);
    asm volatile("cp.async.cg.shared.global [%0], [%1], 16;" :: "r"(d), "l"(src));
}
#define CP_COMMIT()  asm volatile("cp.async.commit_group;")
#define CP_WAIT0()   asm volatile("cp.async.wait_group 0;")
#define CP_WAIT1()   asm volatile("cp.async.wait_group 1;")

// ---------------- pipelined tf32 GEMM body (BM=128 BN=64 BK=32, 256 thr) ----
template<bool BIAS, bool SILU, bool ROUND>
__device__ __forceinline__
void gemm_body(const float* __restrict__ A, const float* __restrict__ Bm,
               const float* __restrict__ bias, float* __restrict__ C,
               int K, int lda, int ldb, int ldc,
               int bm, int bn_src, int bn_dst) {
    __shared__ float As[128 * 36];
    __shared__ float Bs[32 * 72];
    const int t = threadIdx.x;
    const int w = t >> 5, l = t & 31, g = l >> 2, ti = l & 3;
    const int rmb = (w >> 1) * 32, cnb = (w & 1) * 32;

    float4 ra[4], rb[2];
    #pragma unroll
    for (int j = 0; j < 4; j++) { int i = t + 256*j;
        ra[j] = *(const float4*)&A[(size_t)(bm + (i>>3)) * lda + (i&7)*4]; }
    #pragma unroll
    for (int j = 0; j < 2; j++) { int i = t + 256*j;
        rb[j] = *(const float4*)&Bm[(size_t)(i>>4) * ldb + bn_src + (i&15)*4]; }

    float c[2][4][4] = {};
    for (int kt = 0; kt < K; kt += 32) {
        #pragma unroll
        for (int j = 0; j < 4; j++) { int i = t + 256*j;
            *(float4*)&As[(i>>3)*36 + (i&7)*4] = cvt4(ra[j]); }
        #pragma unroll
        for (int j = 0; j < 2; j++) { int i = t + 256*j;
            *(float4*)&Bs[(i>>4)*72 + (i&15)*4] = cvt4(rb[j]); }
        __syncthreads();
        if (kt + 32 < K) {
            #pragma unroll
            for (int j = 0; j < 4; j++) { int i = t + 256*j;
                ra[j] = *(const float4*)&A[(size_t)(bm + (i>>3)) * lda + kt + 32 + (i&7)*4]; }
            #pragma unroll
            for (int j = 0; j < 2; j++) { int i = t + 256*j;
                rb[j] = *(const float4*)&Bm[(size_t)(kt + 32 + (i>>4)) * ldb + bn_src + (i&15)*4]; }
        }
        #pragma unroll
        for (int ks = 0; ks < 4; ks++) {
            float a[2][4], b[4][2];
            #pragma unroll
            for (int mt = 0; mt < 2; mt++) {
                int r = rmb + mt * 16;
                a[mt][0] = As[(r + g)     * 36 + ks*8 + ti];
                a[mt][1] = As[(r + g + 8) * 36 + ks*8 + ti];
                a[mt][2] = As[(r + g)     * 36 + ks*8 + ti + 4];
                a[mt][3] = As[(r + g + 8) * 36 + ks*8 + ti + 4];
            }
            #pragma unroll
            for (int nt = 0; nt < 4; nt++) {
                int cc = cnb + nt * 8 + g;
                b[nt][0] = Bs[(ks*8 + ti)     * 72 + cc];
                b[nt][1] = Bs[(ks*8 + ti + 4) * 72 + cc];
            }
            #pragma unroll
            for (int mt = 0; mt < 2; mt++)
                #pragma unroll
                for (int nt = 0; nt < 4; nt++)
                    mma8(c[mt][nt], a[mt], b[nt]);
        }
        __syncthreads();
    }
    #pragma unroll
    for (int mt = 0; mt < 2; mt++) {
        #pragma unroll
        for (int nt = 0; nt < 4; nt++) {
            int row = bm + rmb + mt * 16 + g;
            int col = bn_dst + cnb + nt * 8 + 2 * ti;
            float b0 = 0.f, b1 = 0.f;
            if (BIAS) { b0 = bias[col - bn_dst + bn_src]; b1 = bias[col - bn_dst + bn_src + 1]; }
            float v0 = c[mt][nt][0] + b0, v1 = c[mt][nt][1] + b1;
            float v2 = c[mt][nt][2] + b0, v3 = c[mt][nt][3] + b1;
            if (SILU) {
                v0 = v0 / (1.f + __expf(-v0)); v1 = v1 / (1.f + __expf(-v1));
                v2 = v2 / (1.f + __expf(-v2)); v3 = v3 / (1.f + __expf(-v3));
            }
            if (ROUND) { v0 = totf32(v0); v1 = totf32(v1); v2 = totf32(v2); v3 = totf32(v3); }
            *(float2*)&C[(size_t)row * ldc + col]       = make_float2(v0, v1);
            *(float2*)&C[(size_t)(row + 8) * ldc + col] = make_float2(v2, v3);
        }
    }
}

template<bool BIAS, bool SILU, bool ROUND>
__global__ __launch_bounds__(256)
void gemm_tf32(const float* __restrict__ A, const float* __restrict__ Bm,
               const float* __restrict__ bias, float* __restrict__ C,
               int K, int lda, int ldb, int ldc) {
    gemm_body<BIAS, SILU, ROUND>(A, Bm, bias, C, K, lda, ldb, ldc,
                                 blockIdx.y * 128, blockIdx.x * 64, blockIdx.x * 64);
}

// fused QKV: grid (24, 128); output pre-rounded to tf32 for cp.async consumers
__global__ __launch_bounds__(256)
void qkv_gemm(const float* __restrict__ feat,
              const float* __restrict__ Wq, const float* __restrict__ Wk,
              const float* __restrict__ Wv, float* __restrict__ qkv) {
    const int nb = blockIdx.x;
    const int which = nb >> 3;
    const int bn = (nb & 7) * 64;
    const float* W = (which == 0) ? Wq : (which == 1) ? Wk : Wv;
    gemm_body<false, false, true>(feat, W, nullptr, qkv, INDIM, INDIM, HDIM, 3*HDIM,
                                  blockIdx.y * 128, bn, which * 512 + bn);
}

// ---------------- distance precompute: log2-domain -------------------------
__global__ __launch_bounds__(256)
void dist_kernel(const float* __restrict__ pos, float* __restrict__ dist) {
    const int bx = blockIdx.x, by = blockIdx.y, b = blockIdx.z;
    if (bx < by) return;
    __shared__ float pq[32*3], pk[32*3];
    const int t = threadIdx.x;
    const int q0 = by * 32, k0 = bx * 32;
    if (t < 96) pq[t] = pos[(size_t)(b * SEQ + q0) * 3 + t];
    else if (t < 192) pk[t-96] = pos[(size_t)(b * SEQ + k0) * 3 + (t-96)];
    __syncthreads();
    const float C2 = (float)(1.4142135623730951 * 1.4426950408889634);
    float* D = dist + (size_t)b * SEQ * SEQ;
    #pragma unroll
    for (int i = t; i < 1024; i += 256) {
        int q = i >> 5, k = i & 31;
        float dx = pq[q*3+0] - pk[k*3+0];
        float dy = pq[q*3+1] - pk[k*3+1];
        float dz = pq[q*3+2] - pk[k*3+2];
        float d2 = dx*dx + dy*dy + dz*dz;
        float d = (d2 > 0.f) ? fsqrt_fast(d2) * C2 : 0.f;
        D[(size_t)(q0 + q) * SEQ + (k0 + k)] = d;
        if (bx != by) D[(size_t)(k0 + k) * SEQ + (q0 + q)] = d;
    }
}

// ---------------- flash-style attention: 64q, key chunks of 64 -------------
// smem ~105 KB -> 2 CTAs/SM. dist chunk buffer overwritten in place by P.
#define QSS 68
#define PSS 68
#define KSS 68
#define VSS 72
#define OFS_P   (64*QSS)                 // 4352
#define OFS_K   (OFS_P + 64*PSS)         // 8704
#define OFS_V   (OFS_K + 2*64*KSS)       // 17408
#define OFS_RS  (OFS_V + 2*64*VSS)       // 26624
#define OFS_RT  (OFS_RS + 4*64)          // 26880
#define ATT_FLOATS (OFS_RT + 64)         // 26944 floats = 107776 B

__global__ __launch_bounds__(512, 2)
void attn_kernel(const float* __restrict__ dist, const float* __restrict__ qkv,
                 float* __restrict__ upd) {
    extern __shared__ float sm[];
    float* Qs  = sm;                 // [64][68]
    float* P   = sm + OFS_P;         // [64][68]  dist chunk -> exp(S) in place
    float* Kb  = sm + OFS_K;         // 2 x [64][68]
    float* Vb  = sm + OFS_V;         // 2 x [64][72]
    float* rsP = sm + OFS_RS;        // [4][64] per-warp-col partial row sums
    float* rsum= sm + OFS_RT;        // [64] 1/rowsum

    const int t = threadIdx.x;
    const int w = t >> 5, l = t & 31, g = l >> 2, ti = l & 3;
    const int wm = w >> 2, wn = w & 3;
    const int qt = blockIdx.x, h = blockIdx.y, b = blockIdx.z;
    const int q0g = qt * 64, tokbase = b * SEQ;
    const float* dbase = dist + ((size_t)b * SEQ + q0g) * SEQ;

    // prologue: Q + dist chunk 0 + K chunk 0 (group A), V chunk 0 (group B)
    #pragma unroll
    for (int i = t; i < 64 * 16; i += 512) {
        int q = i >> 4, d4 = (i & 15) * 4;
        cp16(&Qs[q*QSS + d4], &qkv[(size_t)(tokbase + q0g + q)*1536 + h*64 + d4]);
    }
    #pragma unroll
    for (int i = t; i < 64 * 16; i += 512) {
        int q = i >> 4, k4 = (i & 15) * 4;
        cp16(&P[q*PSS + k4], &dbase[(size_t)q * SEQ + k4]);
    }
    #pragma unroll
    for (int i = t; i < 64 * 16; i += 512) {
        int k = i >> 4, d4 = (i & 15) * 4;
        cp16(&Kb[k*KSS + d4], &qkv[(size_t)(tokbase + k)*1536 + 512 + h*64 + d4]);
    }
    CP_COMMIT();
    #pragma unroll
    for (int i = t; i < 64 * 16; i += 512) {
        int k = i >> 4, d4 = (i & 15) * 4;
        cp16(&Vb[k*VSS + d4], &qkv[(size_t)(tokbase + k)*1536 + 1024 + h*64 + d4]);
    }
    CP_COMMIT();

    const float K1 = (float)(1.4426950408889634 * 0.08838834764831845);
    float cO[2][4] = {};
    float rs0 = 0.f, rs1 = 0.f;

    for (int c = 0; c < 8; c++) {
        CP_WAIT1();                  // K_c + dist_c done (V_c may pend)
        __syncthreads();
        const float* Kc = Kb + (c & 1) * 64 * KSS;

        // S_c = Q K_c^T : warp (wm 16q) x (wn 16k), nt=2
        float cS[2][4] = {};
        #pragma unroll
        for (int ks = 0; ks < 8; ks++) {
            float a[4], bf[2][2];
            a[0] = Qs[(wm*16 + g)     * QSS + ks*8 + ti];
            a[1] = Qs[(wm*16 + g + 8) * QSS + ks*8 + ti];
            a[2] = Qs[(wm*16 + g)     * QSS + ks*8 + ti + 4];
            a[3] = Qs[(wm*16 + g + 8) * QSS + ks*8 + ti + 4];
            #pragma unroll
            for (int nt = 0; nt < 2; nt++) {
                int key = wn*16 + nt*8 + g;
                bf[nt][0] = Kc[key*KSS + ks*8 + ti];
                bf[nt][1] = Kc[key*KSS + ks*8 + ti + 4];
            }
            mma8(cS[0], a, bf[0]);
            mma8(cS[1], a, bf[1]);
        }
        // prefetch K_{c+1} (other K buffer: last read two barriers ago)
        if (c < 7) {
            #pragma unroll
            for (int i = t; i < 64 * 16; i += 512) {
                int k = i >> 4, d4 = (i & 15) * 4;
                cp16(&Kb[((c+1)&1)*64*KSS + k*KSS + d4],
                     &qkv[(size_t)(tokbase + (c+1)*64 + k)*1536 + 512 + h*64 + d4]);
            }
            CP_COMMIT();
        }
        // epilogue: P = tf32(exp2(S*K1 + dist)) in place; accumulate row sums
        #pragma unroll
        for (int nt = 0; nt < 2; nt++) {
            int r0 = wm*16 + g;
            int c0 = wn*16 + nt*8 + 2*ti;
            float2* p0 = (float2*)&P[r0*PSS + c0];
            float2 u0 = *p0;
            u0.x = totf32(exp2_fast(fmaf(cS[nt][0], K1, u0.x)));
            u0.y = totf32(exp2_fast(fmaf(cS[nt][1], K1, u0.y)));
            *p0 = u0;
            rs0 += u0.x + u0.y;
            float2* p1 = (float2*)&P[(r0+8)*PSS + c0];
            float2 u1 = *p1;
            u1.x = totf32(exp2_fast(fmaf(cS[nt][2], K1, u1.x)));
            u1.y = totf32(exp2_fast(fmaf(cS[nt][3], K1, u1.y)));
            *p1 = u1;
            rs1 += u1.x + u1.y;
        }
        if (c < 7) { CP_WAIT1(); } else { CP_WAIT0(); }   // V_c done
        __syncthreads();                                   // P + V_c visible
        const float* Vc = Vb + (c & 1) * 64 * VSS;

        // O += P_c V_c : warp (wm 16q) x (wn 16d), nt=2
        #pragma unroll
        for (int ks = 0; ks < 8; ks++) {
            float a[4], bf[2][2];
            a[0] = P[(wm*16 + g)     * PSS + ks*8 + ti];
            a[1] = P[(wm*16 + g + 8) * PSS + ks*8 + ti];
            a[2] = P[(wm*16 + g)     * PSS + ks*8 + ti + 4];
            a[3] = P[(wm*16 + g + 8) * PSS + ks*8 + ti + 4];
            #pragma unroll
            for (int nt = 0; nt < 2; nt++) {
                int dc = wn*16 + nt*8 + g;
                bf[nt][0] = Vc[(ks*8 + ti)     * VSS + dc];
                bf[nt][1] = Vc[(ks*8 + ti + 4) * VSS + dc];
            }
            mma8(cO[0], a, bf[0]);
            mma8(cO[1], a, bf[1]);
        }
        __syncthreads();             // P free (dist c+1) and V buffer cycling
        if (c < 7) {
            #pragma unroll
            for (int i = t; i < 64 * 16; i += 512) {
                int q = i >> 4, k4 = (i & 15) * 4;
                cp16(&P[q*PSS + k4], &dbase[(size_t)q * SEQ + (c+1)*64 + k4]);
            }
            CP_COMMIT();
            #pragma unroll
            for (int i = t; i < 64 * 16; i += 512) {
                int k = i >> 4, d4 = (i & 15) * 4;
                cp16(&Vb[((c+1)&1)*64*VSS + k*VSS + d4],
                     &qkv[(size_t)(tokbase + (c+1)*64 + k)*1536 + 1024 + h*64 + d4]);
            }
            CP_COMMIT();
        }
    }

    // deterministic rowsum reduce: shfl over ti, stage per wn, fixed-order sum
    rs0 += __shfl_xor_sync(0xffffffffu, rs0, 1);
    rs0 += __shfl_xor_sync(0xffffffffu, rs0, 2);
    rs1 += __shfl_xor_sync(0xffffffffu, rs1, 1);
    rs1 += __shfl_xor_sync(0xffffffffu, rs1, 2);
    if (ti == 0) {
        rsP[wn*64 + wm*16 + g]     = rs0;
        rsP[wn*64 + wm*16 + g + 8] = rs1;
    }
    __syncthreads();
    if (t < 64) rsum[t] = 1.f / (rsP[t] + rsP[64 + t] + rsP[128 + t] + rsP[192 + t]);
    __syncthreads();

    // write O, normalized + tf32-rounded for the MLP
    {
        float inv0 = rsum[wm*16 + g];
        float inv1 = rsum[wm*16 + g + 8];
        #pragma unroll
        for (int nt = 0; nt < 2; nt++) {
            int r = tokbase + q0g + wm*16 + g;
            int col = h*64 + wn*16 + nt*8 + 2*ti;
            *(float2*)&upd[(size_t)r * HDIM + col] =
                make_float2(totf32(cO[nt][0]*inv0), totf32(cO[nt][1]*inv0));
            *(float2*)&upd[(size_t)(r + 8) * HDIM + col] =
                make_float2(totf32(cO[nt][2]*inv1), totf32(cO[nt][3]*inv1));
        }
    }
}

// ---------------- launch ----------------
extern "C" void kernel_launch(void* const* d_in, const int* in_sizes, int n_in,
                              void* d_out, int out_size) {
    const float* pos  = (const float*)d_in[0];
    const float* feat = (const float*)d_in[1];
    const float* Wk   = (const float*)d_in[2];
    const float* Wq   = (const float*)d_in[3];
    const float* Wv   = (const float*)d_in[4];
    const float* W1   = (const float*)d_in[5];
    const float* b1   = (const float*)d_in[6];
    const float* W2   = (const float*)d_in[7];
    const float* b2   = (const float*)d_in[8];
    const float* W3   = (const float*)d_in[9];
    const float* b3   = (const float*)d_in[10];
    float* out = (float*)d_out;

    void* p;
    cudaGetSymbolAddress(&p, g_qkv);  float* qkv  = (float*)p;
    cudaGetSymbolAddress(&p, g_upd);  float* upd  = (float*)p;
    cudaGetSymbolAddress(&p, g_dist); float* dist = (float*)p;
    cudaGetSymbolAddress(&p, g_h1);   float* h1   = (float*)p;
    cudaGetSymbolAddress(&p, g_h2);   float* h2   = (float*)p;

    dist_kernel<<<dim3(16, 16, BATCH), 256>>>(pos, dist);

    qkv_gemm<<<dim3(24, MTOK/128), 256>>>(feat, Wq, Wk, Wv, qkv);

    size_t shmem = (size_t)ATT_FLOATS * sizeof(float);
    cudaFuncSetAttribute(attn_kernel, cudaFuncAttributeMaxDynamicSharedMemorySize, (int)shmem);
    attn_kernel<<<dim3(SEQ/64, NHEADS, BATCH), 512, shmem>>>(dist, qkv, upd);

    gemm_tf32<true,true,true ><<<dim3(2, MTOK/128), 256>>>(upd, W1, b1, h1,  HDIM, HDIM, 128, 128);
    gemm_tf32<true,true,true ><<<dim3(1, MTOK/128), 256>>>(h1,  W2, b2, h2,  128,  128,  64,  64);
    gemm_tf32<true,true,false><<<dim3(4, MTOK/128), 256>>>(h2,  W3, b3, out, 64,   64,   INDIM, INDIM);
}

// round 9
// speedup vs baseline: 3.9164x; 1.0725x over previous
#include <cuda_runtime.h>
#include <math.h>
#include <stdint.h>

#define BATCH   32
#define SEQ     512
#define NHEADS  8
#define HID     64
#define INDIM   256
#define HDIM    512
#define MTOK    (BATCH*SEQ)       // 16384

// ---------------- scratch ----------------
__device__ float g_qkv [(size_t)MTOK * 3 * HDIM];
__device__ float g_upd [(size_t)MTOK * HDIM];

// ---------------- helpers ----------------
__device__ __forceinline__ float totf32(float x) {
    uint32_t u;
    asm("cvt.rna.tf32.f32 %0, %1;" : "=r"(u) : "f"(x));
    return __uint_as_float(u);
}
__device__ __forceinline__ float4 cvt4(float4 v) {
    return make_float4(totf32(v.x), totf32(v.y), totf32(v.z), totf32(v.w));
}
__device__ __forceinline__ float fsqrt_fast(float x) {
    float y;
    asm("sqrt.approx.f32 %0, %1;" : "=f"(y) : "f"(x));
    return y;
}
// 2^x via FMA pipe (no MUFU). |rel err| ~2e-6, then tf32-rounded anyway.
__device__ __forceinline__ float exp2_fast(float x) {
    x = fminf(fmaxf(x, -120.f), 120.f);
    float z = x + 12582912.0f;                 // 1.5*2^23: round-to-nearest-int
    float n = z - 12582912.0f;
    float r = x - n;                           // r in [-0.5, 0.5]
    int   ni = __float_as_int(z) - 0x4B400000;
    float s = __int_as_float((ni + 127) << 23);
    float p = 1.3333558e-3f;
    p = fmaf(p, r, 9.6181291e-3f);
    p = fmaf(p, r, 5.5504110e-2f);
    p = fmaf(p, r, 2.4022651e-1f);
    p = fmaf(p, r, 6.9314718e-1f);
    p = fmaf(p, r, 1.0f);
    return p * s;
}
__device__ __forceinline__ void mma8(float c[4], const float a[4], const float b[2]) {
    asm volatile(
        "mma.sync.aligned.m16n8k8.row.col.f32.tf32.tf32.f32 "
        "{%0,%1,%2,%3}, {%4,%5,%6,%7}, {%8,%9}, {%0,%1,%2,%3};\n"
        : "+f"(c[0]), "+f"(c[1]), "+f"(c[2]), "+f"(c[3])
        : "r"(__float_as_uint(a[0])), "r"(__float_as_uint(a[1])),
          "r"(__float_as_uint(a[2])), "r"(__float_as_uint(a[3])),
          "r"(__float_as_uint(b[0])), "r"(__float_as_uint(b[1])));
}
__device__ __forceinline__ void cp16(float* dst_smem, const float* src) {
    uint32_t d = (uint32_t)__cvta_generic_to_shared(dst_smem);
    asm volatile("cp.async.cg.shared.global [%0], [%1], 16;" :: "r"(d), "l"(src));
}
__device__ __forceinline__ void cp4(float* dst_smem, const float* src) {
    uint32_t d = (uint32_t)__cvta_generic_to_shared(dst_smem);
    asm volatile("cp.async.ca.shared.global [%0], [%1], 4;" :: "r"(d), "l"(src));
}
#define CP_COMMIT()  asm volatile("cp.async.commit_group;")
#define CP_WAIT0()   asm volatile("cp.async.wait_group 0;")
#define CP_WAIT1()   asm volatile("cp.async.wait_group 1;")

// ---------------- pipelined tf32 GEMM body (BM=128 BN=64 BK=32, 256 thr) ----
template<bool ROUND>
__device__ __forceinline__
void gemm_body(const float* __restrict__ A, const float* __restrict__ Bm,
               float* __restrict__ C, int K, int lda, int ldb, int ldc,
               int bm, int bn_src, int bn_dst) {
    __shared__ float As[128 * 36];
    __shared__ float Bs[32 * 72];
    const int t = threadIdx.x;
    const int w = t >> 5, l = t & 31, g = l >> 2, ti = l & 3;
    const int rmb = (w >> 1) * 32, cnb = (w & 1) * 32;

    float4 ra[4], rb[2];
    #pragma unroll
    for (int j = 0; j < 4; j++) { int i = t + 256*j;
        ra[j] = *(const float4*)&A[(size_t)(bm + (i>>3)) * lda + (i&7)*4]; }
    #pragma unroll
    for (int j = 0; j < 2; j++) { int i = t + 256*j;
        rb[j] = *(const float4*)&Bm[(size_t)(i>>4) * ldb + bn_src + (i&15)*4]; }

    float c[2][4][4] = {};
    for (int kt = 0; kt < K; kt += 32) {
        #pragma unroll
        for (int j = 0; j < 4; j++) { int i = t + 256*j;
            *(float4*)&As[(i>>3)*36 + (i&7)*4] = cvt4(ra[j]); }
        #pragma unroll
        for (int j = 0; j < 2; j++) { int i = t + 256*j;
            *(float4*)&Bs[(i>>4)*72 + (i&15)*4] = cvt4(rb[j]); }
        __syncthreads();
        if (kt + 32 < K) {
            #pragma unroll
            for (int j = 0; j < 4; j++) { int i = t + 256*j;
                ra[j] = *(const float4*)&A[(size_t)(bm + (i>>3)) * lda + kt + 32 + (i&7)*4]; }
            #pragma unroll
            for (int j = 0; j < 2; j++) { int i = t + 256*j;
                rb[j] = *(const float4*)&Bm[(size_t)(kt + 32 + (i>>4)) * ldb + bn_src + (i&15)*4]; }
        }
        #pragma unroll
        for (int ks = 0; ks < 4; ks++) {
            float a[2][4], b[4][2];
            #pragma unroll
            for (int mt = 0; mt < 2; mt++) {
                int r = rmb + mt * 16;
                a[mt][0] = As[(r + g)     * 36 + ks*8 + ti];
                a[mt][1] = As[(r + g + 8) * 36 + ks*8 + ti];
                a[mt][2] = As[(r + g)     * 36 + ks*8 + ti + 4];
                a[mt][3] = As[(r + g + 8) * 36 + ks*8 + ti + 4];
            }
            #pragma unroll
            for (int nt = 0; nt < 4; nt++) {
                int cc = cnb + nt * 8 + g;
                b[nt][0] = Bs[(ks*8 + ti)     * 72 + cc];
                b[nt][1] = Bs[(ks*8 + ti + 4) * 72 + cc];
            }
            #pragma unroll
            for (int mt = 0; mt < 2; mt++)
                #pragma unroll
                for (int nt = 0; nt < 4; nt++)
                    mma8(c[mt][nt], a[mt], b[nt]);
        }
        __syncthreads();
    }
    #pragma unroll
    for (int mt = 0; mt < 2; mt++) {
        #pragma unroll
        for (int nt = 0; nt < 4; nt++) {
            int row = bm + rmb + mt * 16 + g;
            int col = bn_dst + cnb + nt * 8 + 2 * ti;
            float v0 = c[mt][nt][0], v1 = c[mt][nt][1];
            float v2 = c[mt][nt][2], v3 = c[mt][nt][3];
            if (ROUND) { v0 = totf32(v0); v1 = totf32(v1); v2 = totf32(v2); v3 = totf32(v3); }
            *(float2*)&C[(size_t)row * ldc + col]       = make_float2(v0, v1);
            *(float2*)&C[(size_t)(row + 8) * ldc + col] = make_float2(v2, v3);
        }
    }
}

// fused QKV: grid (24, 128); output pre-rounded to tf32 for cp.async consumers
__global__ __launch_bounds__(256)
void qkv_gemm(const float* __restrict__ feat,
              const float* __restrict__ Wq, const float* __restrict__ Wk,
              const float* __restrict__ Wv, float* __restrict__ qkv) {
    const int nb = blockIdx.x;
    const int which = nb >> 3;
    const int bn = (nb & 7) * 64;
    const float* W = (which == 0) ? Wq : (which == 1) ? Wk : Wv;
    gemm_body<true>(feat, W, qkv, INDIM, INDIM, HDIM, 3*HDIM,
                    blockIdx.y * 128, bn, which * 512 + bn);
}

// ---------------- flash attention: dist computed in-register ---------------
#define QSS 68
#define PSS 68
#define KSS 68
#define VSS 72
#define AOFS_P  (64*QSS)             // 4352
#define AOFS_K  (AOFS_P + 64*PSS)    // 8704
#define AOFS_V  (AOFS_K + 2*64*KSS)  // 17408
#define AOFS_PQ (AOFS_V + 2*64*VSS)  // 26624
#define AOFS_PK (AOFS_PQ + 192)      // 26816
#define AOFS_RS (AOFS_PK + 384)      // 27200
#define AOFS_RT (AOFS_RS + 256)      // 27456
#define ATT_FLOATS (AOFS_RT + 64)    // 27520 floats = 110080 B

__global__ __launch_bounds__(512, 2)
void attn_kernel(const float* __restrict__ pos, const float* __restrict__ qkv,
                 float* __restrict__ upd) {
    extern __shared__ float sm[];
    float* Qs  = sm;                 // [64][68]
    float* P   = sm + AOFS_P;        // [64][68]  exp(S) (write-only epilogue)
    float* Kb  = sm + AOFS_K;        // 2 x [64][68]
    float* Vb  = sm + AOFS_V;        // 2 x [64][72]
    float* pq  = sm + AOFS_PQ;       // [64][3] query positions
    float* pk  = sm + AOFS_PK;       // 2 x [64][3] key positions
    float* rsP = sm + AOFS_RS;       // [4][64]
    float* rsum= sm + AOFS_RT;       // [64]

    const int t = threadIdx.x;
    const int w = t >> 5, l = t & 31, g = l >> 2, ti = l & 3;
    const int wm = w >> 2, wn = w & 3;
    const int qt = blockIdx.x, h = blockIdx.y, b = blockIdx.z;
    const int q0g = qt * 64, tokbase = b * SEQ;

    // prologue: Q, K0, V0, pos_q, pos_k0 — one commit group
    #pragma unroll
    for (int i = t; i < 64 * 16; i += 512) {
        int q = i >> 4, d4 = (i & 15) * 4;
        cp16(&Qs[q*QSS + d4], &qkv[(size_t)(tokbase + q0g + q)*1536 + h*64 + d4]);
    }
    #pragma unroll
    for (int i = t; i < 64 * 16; i += 512) {
        int k = i >> 4, d4 = (i & 15) * 4;
        cp16(&Kb[k*KSS + d4], &qkv[(size_t)(tokbase + k)*1536 + 512 + h*64 + d4]);
    }
    #pragma unroll
    for (int i = t; i < 64 * 16; i += 512) {
        int k = i >> 4, d4 = (i & 15) * 4;
        cp16(&Vb[k*VSS + d4], &qkv[(size_t)(tokbase + k)*1536 + 1024 + h*64 + d4]);
    }
    if (t < 192) cp4(&pq[t], &pos[(size_t)(tokbase + q0g)*3 + t]);
    else if (t < 384) cp4(&pk[t-192], &pos[(size_t)tokbase*3 + (t-192)]);
    CP_COMMIT();

    const float K1 = (float)(1.4426950408889634 * 0.08838834764831845); // log2e/(8*sqrt2)
    const float C2 = (float)(1.4142135623730951 * 1.4426950408889634);  // sqrt2*log2e
    float cO[2][4] = {};
    float rs0 = 0.f, rs1 = 0.f;

    for (int c = 0; c < 8; c++) {
        CP_WAIT0();                  // chunk-c group complete (K,V,pos)
        __syncthreads();             // visible; buffers (c+1)&1 free
        if (c < 7) {
            const int nx = (c + 1) & 1;
            #pragma unroll
            for (int i = t; i < 64 * 16; i += 512) {
                int k = i >> 4, d4 = (i & 15) * 4;
                cp16(&Kb[nx*64*KSS + k*KSS + d4],
                     &qkv[(size_t)(tokbase + (c+1)*64 + k)*1536 + 512 + h*64 + d4]);
            }
            #pragma unroll
            for (int i = t; i < 64 * 16; i += 512) {
                int k = i >> 4, d4 = (i & 15) * 4;
                cp16(&Vb[nx*64*VSS + k*VSS + d4],
                     &qkv[(size_t)(tokbase + (c+1)*64 + k)*1536 + 1024 + h*64 + d4]);
            }
            if (t < 192) cp4(&pk[nx*192 + t], &pos[(size_t)(tokbase + (c+1)*64)*3 + t]);
            CP_COMMIT();
        }
        const float* Kc = Kb + (c & 1) * 64 * KSS;

        // S_c = Q K_c^T
        float cS[2][4] = {};
        #pragma unroll
        for (int ks = 0; ks < 8; ks++) {
            float a[4], bf[2][2];
            a[0] = Qs[(wm*16 + g)     * QSS + ks*8 + ti];
            a[1] = Qs[(wm*16 + g + 8) * QSS + ks*8 + ti];
            a[2] = Qs[(wm*16 + g)     * QSS + ks*8 + ti + 4];
            a[3] = Qs[(wm*16 + g + 8) * QSS + ks*8 + ti + 4];
            #pragma unroll
            for (int nt = 0; nt < 2; nt++) {
                int key = wn*16 + nt*8 + g;
                bf[nt][0] = Kc[key*KSS + ks*8 + ti];
                bf[nt][1] = Kc[key*KSS + ks*8 + ti + 4];
            }
            mma8(cS[0], a, bf[0]);
            mma8(cS[1], a, bf[1]);
        }

        // epilogue: dist (regs) + exp -> P, rowsum accumulation
        {
            const int r0 = wm*16 + g;
            float qx0 = pq[r0*3],     qy0 = pq[r0*3+1],     qz0 = pq[r0*3+2];
            float qx1 = pq[(r0+8)*3], qy1 = pq[(r0+8)*3+1], qz1 = pq[(r0+8)*3+2];
            const float* pkc = pk + (c & 1) * 192;
            #pragma unroll
            for (int nt = 0; nt < 2; nt++) {
                int kl = wn*16 + nt*8 + 2*ti;
                float kx0 = pkc[kl*3],   ky0 = pkc[kl*3+1], kz0 = pkc[kl*3+2];
                float kx1 = pkc[kl*3+3], ky1 = pkc[kl*3+4], kz1 = pkc[kl*3+5];
                float dx, dy, dz;
                dx = qx0-kx0; dy = qy0-ky0; dz = qz0-kz0;
                float e00 = fsqrt_fast(fmaf(dx,dx,fmaf(dy,dy,dz*dz))) * C2;
                dx = qx0-kx1; dy = qy0-ky1; dz = qz0-kz1;
                float e01 = fsqrt_fast(fmaf(dx,dx,fmaf(dy,dy,dz*dz))) * C2;
                dx = qx1-kx0; dy = qy1-ky0; dz = qz1-kz0;
                float e10 = fsqrt_fast(fmaf(dx,dx,fmaf(dy,dy,dz*dz))) * C2;
                dx = qx1-kx1; dy = qy1-ky1; dz = qz1-kz1;
                float e11 = fsqrt_fast(fmaf(dx,dx,fmaf(dy,dy,dz*dz))) * C2;
                float2 u0, u1;
                u0.x = totf32(exp2_fast(fmaf(cS[nt][0], K1, e00)));
                u0.y = totf32(exp2_fast(fmaf(cS[nt][1], K1, e01)));
                u1.x = totf32(exp2_fast(fmaf(cS[nt][2], K1, e10)));
                u1.y = totf32(exp2_fast(fmaf(cS[nt][3], K1, e11)));
                *(float2*)&P[r0*PSS + kl]     = u0;
                *(float2*)&P[(r0+8)*PSS + kl] = u1;
                rs0 += u0.x + u0.y;
                rs1 += u1.x + u1.y;
            }
        }
        __syncthreads();             // P visible

        // O += P_c V_c
        const float* Vc = Vb + (c & 1) * 64 * VSS;
        #pragma unroll
        for (int ks = 0; ks < 8; ks++) {
            float a[4], bf[2][2];
            a[0] = P[(wm*16 + g)     * PSS + ks*8 + ti];
            a[1] = P[(wm*16 + g + 8) * PSS + ks*8 + ti];
            a[2] = P[(wm*16 + g)     * PSS + ks*8 + ti + 4];
            a[3] = P[(wm*16 + g + 8) * PSS + ks*8 + ti + 4];
            #pragma unroll
            for (int nt = 0; nt < 2; nt++) {
                int dc = wn*16 + nt*8 + g;
                bf[nt][0] = Vc[(ks*8 + ti)     * VSS + dc];
                bf[nt][1] = Vc[(ks*8 + ti + 4) * VSS + dc];
            }
            mma8(cO[0], a, bf[0]);
            mma8(cO[1], a, bf[1]);
        }
    }

    // deterministic rowsum reduce
    rs0 += __shfl_xor_sync(0xffffffffu, rs0, 1);
    rs0 += __shfl_xor_sync(0xffffffffu, rs0, 2);
    rs1 += __shfl_xor_sync(0xffffffffu, rs1, 1);
    rs1 += __shfl_xor_sync(0xffffffffu, rs1, 2);
    __syncthreads();                 // last PV done before rsP reuse
    if (ti == 0) {
        rsP[wn*64 + wm*16 + g]     = rs0;
        rsP[wn*64 + wm*16 + g + 8] = rs1;
    }
    __syncthreads();
    if (t < 64) rsum[t] = 1.f / (rsP[t] + rsP[64 + t] + rsP[128 + t] + rsP[192 + t]);
    __syncthreads();

    {
        float inv0 = rsum[wm*16 + g];
        float inv1 = rsum[wm*16 + g + 8];
        #pragma unroll
        for (int nt = 0; nt < 2; nt++) {
            int r = tokbase + q0g + wm*16 + g;
            int col = h*64 + wn*16 + nt*8 + 2*ti;
            *(float2*)&upd[(size_t)r * HDIM + col] =
                make_float2(totf32(cO[nt][0]*inv0), totf32(cO[nt][1]*inv0));
            *(float2*)&upd[(size_t)(r + 8) * HDIM + col] =
                make_float2(totf32(cO[nt][2]*inv1), totf32(cO[nt][3]*inv1));
        }
    }
}

// ---------------- fused 3-layer MLP: grid 128, 512 thr ---------------------
// 512 ->(W1,silu) 128 ->(W2,silu) 64 ->(W3,silu) 256 ; h1/h2 in smem
#define MH1S 132
#define MH2S 68
#define MAS  36
#define MBS  136
#define MW2S 72
#define MW3S 264
#define MOFS_H2 (128*MH1S)             // 16896
#define MOFS_ST (MOFS_H2 + 128*MH2S)   // 25600  (As+Bs in phase1, W3s in phase3)
#define MOFS_BS (MOFS_ST + 128*MAS)    // 30208
#define MOFS_W2 (MOFS_ST + 64*MW3S)    // 42496
#define MLP_FLOATS (MOFS_W2 + 128*MW2S) // 51712 floats = 206848 B

__global__ __launch_bounds__(512, 1)
void mlp_fused(const float* __restrict__ X,
               const float* __restrict__ W1, const float* __restrict__ b1,
               const float* __restrict__ W2, const float* __restrict__ b2,
               const float* __restrict__ W3, const float* __restrict__ b3,
               float* __restrict__ out) {
    extern __shared__ float sm[];
    float* H1  = sm;                 // [128][132]
    float* H2  = sm + MOFS_H2;       // [128][68]
    float* As  = sm + MOFS_ST;       // [128][36]   (phase1)
    float* Bs  = sm + MOFS_BS;       // [32][136]   (phase1)
    float* W3s = sm + MOFS_ST;       // [64][264]   (phase3, aliases As/Bs)
    float* W2s = sm + MOFS_W2;       // [128][72]

    const int t = threadIdx.x;
    const int w = t >> 5, l = t & 31, g = l >> 2, ti = l & 3;
    const int wm = w >> 2, wn = w & 3;
    const int bm = blockIdx.x * 128;

    // stage W2 async immediately (own region, used in phase2)
    #pragma unroll
    for (int j = 0; j < 4; j++) {
        int i = t + 512*j; int kr = i >> 4, n4 = (i & 15) * 4;
        cp16(&W2s[kr*MW2S + n4], &W2[kr*64 + n4]);
    }
    CP_COMMIT();

    // ---- phase 1: H1 = silu(X @ W1 + b1), K=512, reg-prefetch pipeline ----
    const float* A = X + (size_t)bm * HDIM;
    float4 ra[2], rb[2];
    #pragma unroll
    for (int j = 0; j < 2; j++) { int i = t + 512*j;
        ra[j] = *(const float4*)&A[(size_t)(i>>3) * HDIM + (i&7)*4]; }
    #pragma unroll
    for (int j = 0; j < 2; j++) { int i = t + 512*j;
        rb[j] = *(const float4*)&W1[(size_t)(i>>5) * 128 + (i&31)*4]; }

    float c1[2][4][4] = {};
    for (int kt = 0; kt < HDIM; kt += 32) {
        #pragma unroll
        for (int j = 0; j < 2; j++) { int i = t + 512*j;
            *(float4*)&As[(i>>3)*MAS + (i&7)*4] = ra[j]; }          // X already tf32
        #pragma unroll
        for (int j = 0; j < 2; j++) { int i = t + 512*j;
            *(float4*)&Bs[(i>>5)*MBS + (i&31)*4] = cvt4(rb[j]); }
        __syncthreads();
        if (kt + 32 < HDIM) {
            #pragma unroll
            for (int j = 0; j < 2; j++) { int i = t + 512*j;
                ra[j] = *(const float4*)&A[(size_t)(i>>3) * HDIM + kt + 32 + (i&7)*4]; }
            #pragma unroll
            for (int j = 0; j < 2; j++) { int i = t + 512*j;
                rb[j] = *(const float4*)&W1[(size_t)(kt + 32 + (i>>5)) * 128 + (i&31)*4]; }
        }
        #pragma unroll
        for (int ks = 0; ks < 4; ks++) {
            float a[2][4], bfr[4][2];
            #pragma unroll
            for (int mt = 0; mt < 2; mt++) {
                int r = wm*32 + mt*16;
                a[mt][0] = As[(r + g)     * MAS + ks*8 + ti];
                a[mt][1] = As[(r + g + 8) * MAS + ks*8 + ti];
                a[mt][2] = As[(r + g)     * MAS + ks*8 + ti + 4];
                a[mt][3] = As[(r + g + 8) * MAS + ks*8 + ti + 4];
            }
            #pragma unroll
            for (int nt = 0; nt < 4; nt++) {
                int cc = wn*32 + nt*8 + g;
                bfr[nt][0] = Bs[(ks*8 + ti)     * MBS + cc];
                bfr[nt][1] = Bs[(ks*8 + ti + 4) * MBS + cc];
            }
            #pragma unroll
            for (int mt = 0; mt < 2; mt++)
                #pragma unroll
                for (int nt = 0; nt < 4; nt++)
                    mma8(c1[mt][nt], a[mt], bfr[nt]);
        }
        __syncthreads();
    }
    #pragma unroll
    for (int mt = 0; mt < 2; mt++)
        #pragma unroll
        for (int nt = 0; nt < 4; nt++) {
            int row = wm*32 + mt*16 + g;
            int col = wn*32 + nt*8 + 2*ti;
            float bb0 = b1[col], bb1 = b1[col+1];
            float v0 = c1[mt][nt][0] + bb0, v1 = c1[mt][nt][1] + bb1;
            float v2 = c1[mt][nt][2] + bb0, v3 = c1[mt][nt][3] + bb1;
            v0 = totf32(v0 / (1.f + __expf(-v0))); v1 = totf32(v1 / (1.f + __expf(-v1)));
            v2 = totf32(v2 / (1.f + __expf(-v2))); v3 = totf32(v3 / (1.f + __expf(-v3)));
            *(float2*)&H1[row*MH1S + col]     = make_float2(v0, v1);
            *(float2*)&H1[(row+8)*MH1S + col] = make_float2(v2, v3);
        }
    __syncthreads();                 // H1 visible; As/Bs region free

    // stage W3 async into freed region (overlaps phase 2)
    #pragma unroll
    for (int j = 0; j < 8; j++) {
        int i = t + 512*j; int kr = i >> 6, n4 = (i & 63) * 4;
        cp16(&W3s[kr*MW3S + n4], &W3[kr*256 + n4]);
    }
    CP_COMMIT();
    CP_WAIT1();                      // W2 group complete (W3 still in flight)
    __syncthreads();

    // ---- phase 2: H2 = silu(H1 @ W2 + b2), K=128 ----
    float c2[2][2][4] = {};
    #pragma unroll
    for (int ks = 0; ks < 16; ks++) {
        float a[2][4], bfr[2][2];
        #pragma unroll
        for (int mt = 0; mt < 2; mt++) {
            int r = wm*32 + mt*16;
            a[mt][0] = H1[(r + g)     * MH1S + ks*8 + ti];
            a[mt][1] = H1[(r + g + 8) * MH1S + ks*8 + ti];
            a[mt][2] = H1[(r + g)     * MH1S + ks*8 + ti + 4];
            a[mt][3] = H1[(r + g + 8) * MH1S + ks*8 + ti + 4];
        }
        #pragma unroll
        for (int nt = 0; nt < 2; nt++) {
            int cc = wn*16 + nt*8 + g;
            bfr[nt][0] = totf32(W2s[(ks*8 + ti)     * MW2S + cc]);
            bfr[nt][1] = totf32(W2s[(ks*8 + ti + 4) * MW2S + cc]);
        }
        #pragma unroll
        for (int mt = 0; mt < 2; mt++)
            #pragma unroll
            for (int nt = 0; nt < 2; nt++)
                mma8(c2[mt][nt], a[mt], bfr[nt]);
    }
    #pragma unroll
    for (int mt = 0; mt < 2; mt++)
        #pragma unroll
        for (int nt = 0; nt < 2; nt++) {
            int row = wm*32 + mt*16 + g;
            int col = wn*16 + nt*8 + 2*ti;
            float bb0 = b2[col], bb1 = b2[col+1];
            float v0 = c2[mt][nt][0] + bb0, v1 = c2[mt][nt][1] + bb1;
            float v2 = c2[mt][nt][2] + bb0, v3 = c2[mt][nt][3] + bb1;
            v0 = totf32(v0 / (1.f + __expf(-v0))); v1 = totf32(v1 / (1.f + __expf(-v1)));
            v2 = totf32(v2 / (1.f + __expf(-v2))); v3 = totf32(v3 / (1.f + __expf(-v3)));
            *(float2*)&H2[row*MH2S + col]     = make_float2(v0, v1);
            *(float2*)&H2[(row+8)*MH2S + col] = make_float2(v2, v3);
        }
    CP_WAIT0();                      // W3 complete
    __syncthreads();                 // H2 + W3s visible

    // ---- phase 3: out = silu(H2 @ W3 + b3), K=64, N=256 ----
    float c3[2][8][4] = {};
    #pragma unroll
    for (int ks = 0; ks < 8; ks++) {
        float a[2][4];
        #pragma unroll
        for (int mt = 0; mt < 2; mt++) {
            int r = wm*32 + mt*16;
            a[mt][0] = H2[(r + g)     * MH2S + ks*8 + ti];
            a[mt][1] = H2[(r + g + 8) * MH2S + ks*8 + ti];
            a[mt][2] = H2[(r + g)     * MH2S + ks*8 + ti + 4];
            a[mt][3] = H2[(r + g + 8) * MH2S + ks*8 + ti + 4];
        }
        #pragma unroll
        for (int nt = 0; nt < 8; nt++) {
            float bfr[2];
            int cc = wn*64 + nt*8 + g;
            bfr[0] = totf32(W3s[(ks*8 + ti)     * MW3S + cc]);
            bfr[1] = totf32(W3s[(ks*8 + ti + 4) * MW3S + cc]);
            mma8(c3[0][nt], a[0], bfr);
            mma8(c3[1][nt], a[1], bfr);
        }
    }
    #pragma unroll
    for (int mt = 0; mt < 2; mt++)
        #pragma unroll
        for (int nt = 0; nt < 8; nt++) {
            int row = bm + wm*32 + mt*16 + g;
            int col = wn*64 + nt*8 + 2*ti;
            float bb0 = b3[col], bb1 = b3[col+1];
            float v0 = c3[mt][nt][0] + bb0, v1 = c3[mt][nt][1] + bb1;
            float v2 = c3[mt][nt][2] + bb0, v3 = c3[mt][nt][3] + bb1;
            v0 = v0 / (1.f + __expf(-v0)); v1 = v1 / (1.f + __expf(-v1));
            v2 = v2 / (1.f + __expf(-v2)); v3 = v3 / (1.f + __expf(-v3));
            *(float2*)&out[(size_t)row * INDIM + col]     = make_float2(v0, v1);
            *(float2*)&out[(size_t)(row+8) * INDIM + col] = make_float2(v2, v3);
        }
}

// ---------------- launch ----------------
extern "C" void kernel_launch(void* const* d_in, const int* in_sizes, int n_in,
                              void* d_out, int out_size) {
    const float* pos  = (const float*)d_in[0];
    const float* feat = (const float*)d_in[1];
    const float* Wk   = (const float*)d_in[2];
    const float* Wq   = (const float*)d_in[3];
    const float* Wv   = (const float*)d_in[4];
    const float* W1   = (const float*)d_in[5];
    const float* b1   = (const float*)d_in[6];
    const float* W2   = (const float*)d_in[7];
    const float* b2   = (const float*)d_in[8];
    const float* W3   = (const float*)d_in[9];
    const float* b3   = (const float*)d_in[10];
    float* out = (float*)d_out;

    void* p;
    cudaGetSymbolAddress(&p, g_qkv);  float* qkv  = (float*)p;
    cudaGetSymbolAddress(&p, g_upd);  float* upd  = (float*)p;

    qkv_gemm<<<dim3(24, MTOK/128), 256>>>(feat, Wq, Wk, Wv, qkv);

    size_t ash = (size_t)ATT_FLOATS * sizeof(float);
    cudaFuncSetAttribute(attn_kernel, cudaFuncAttributeMaxDynamicSharedMemorySize, (int)ash);
    attn_kernel<<<dim3(SEQ/64, NHEADS, BATCH), 512, ash>>>(pos, qkv, upd);

    size_t msh = (size_t)MLP_FLOATS * sizeof(float);
    cudaFuncSetAttribute(mlp_fused, cudaFuncAttributeMaxDynamicSharedMemorySize, (int)msh);
    mlp_fused<<<MTOK/128, 512, msh>>>(upd, W1, b1, W2, b2, W3, b3, out);
}

// round 10
// speedup vs baseline: 4.0337x; 1.0299x over previous
#include <cuda_runtime.h>
#include <math.h>
#include <stdint.h>

#define BATCH   32
#define SEQ     512
#define NHEADS  8
#define HID     64
#define INDIM   256
#define HDIM    512
#define MTOK    (BATCH*SEQ)       // 16384

// ---------------- scratch ----------------
__device__ float g_qkv  [(size_t)MTOK * 3 * HDIM];
__device__ float g_upd  [(size_t)MTOK * HDIM];
__device__ float g_featr[(size_t)MTOK * INDIM];
__device__ float g_wcat [(size_t)INDIM * 3 * HDIM];

// ---------------- helpers ----------------
__device__ __forceinline__ float totf32(float x) {
    uint32_t u;
    asm("cvt.rna.tf32.f32 %0, %1;" : "=r"(u) : "f"(x));
    return __uint_as_float(u);
}
__device__ __forceinline__ float4 cvt4(float4 v) {
    return make_float4(totf32(v.x), totf32(v.y), totf32(v.z), totf32(v.w));
}
__device__ __forceinline__ float fsqrt_fast(float x) {
    float y;
    asm("sqrt.approx.f32 %0, %1;" : "=f"(y) : "f"(x));
    return y;
}
// 2^x via FMA pipe (no MUFU). |rel err| ~2e-6, then tf32-rounded anyway.
__device__ __forceinline__ float exp2_fast(float x) {
    x = fminf(fmaxf(x, -120.f), 120.f);
    float z = x + 12582912.0f;                 // 1.5*2^23: round-to-nearest-int
    float n = z - 12582912.0f;
    float r = x - n;                           // r in [-0.5, 0.5]
    int   ni = __float_as_int(z) - 0x4B400000;
    float s = __int_as_float((ni + 127) << 23);
    float p = 1.3333558e-3f;
    p = fmaf(p, r, 9.6181291e-3f);
    p = fmaf(p, r, 5.5504110e-2f);
    p = fmaf(p, r, 2.4022651e-1f);
    p = fmaf(p, r, 6.9314718e-1f);
    p = fmaf(p, r, 1.0f);
    return p * s;
}
__device__ __forceinline__ void mma8(float c[4], const float a[4], const float b[2]) {
    asm volatile(
        "mma.sync.aligned.m16n8k8.row.col.f32.tf32.tf32.f32 "
        "{%0,%1,%2,%3}, {%4,%5,%6,%7}, {%8,%9}, {%0,%1,%2,%3};\n"
        : "+f"(c[0]), "+f"(c[1]), "+f"(c[2]), "+f"(c[3])
        : "r"(__float_as_uint(a[0])), "r"(__float_as_uint(a[1])),
          "r"(__float_as_uint(a[2])), "r"(__float_as_uint(a[3])),
          "r"(__float_as_uint(b[0])), "r"(__float_as_uint(b[1])));
}
__device__ __forceinline__ void cp16(float* dst_smem, const float* src) {
    uint32_t d = (uint32_t)__cvta_generic_to_shared(dst_smem);
    asm volatile("cp.async.cg.shared.global [%0], [%1], 16;" :: "r"(d), "l"(src));
}
__device__ __forceinline__ void cp4(float* dst_smem, const float* src) {
    uint32_t d = (uint32_t)__cvta_generic_to_shared(dst_smem);
    asm volatile("cp.async.ca.shared.global [%0], [%1], 4;" :: "r"(d), "l"(src));
}
#define CP_COMMIT()  asm volatile("cp.async.commit_group;")
#define CP_WAIT0()   asm volatile("cp.async.wait_group 0;")
#define CP_WAIT1()   asm volatile("cp.async.wait_group 1;")

// ---------------- prep: tf32-round feat, concat+round Wq|Wk|Wv -------------
__global__ __launch_bounds__(256)
void prep_round(const float* __restrict__ feat, const float* __restrict__ Wq,
                const float* __restrict__ Wk, const float* __restrict__ Wv,
                float* __restrict__ featr, float* __restrict__ wcat) {
    const int NF4 = MTOK * INDIM / 4;          // 1048576
    int i = blockIdx.x * 256 + threadIdx.x;
    if (i < NF4) {
        ((float4*)featr)[i] = cvt4(((const float4*)feat)[i]);
    } else {
        int j = i - NF4;                       // < 98304
        int k  = j / 384;                      // row (1536/4 = 384)
        int c4 = (j % 384) * 4;                // col
        const float* src = (c4 < 512)  ? &Wq[k*512 + c4] :
                           (c4 < 1024) ? &Wk[k*512 + c4 - 512] :
                                         &Wv[k*512 + c4 - 1024];
        ((float4*)wcat)[j] = cvt4(*(const float4*)src);
    }
}

// ---------------- QKV GEMM: BM=128 BN=256 BK=32, warp tile 64x64 -----------
#define GAS 36
#define GBS 264
#define GA_BUF (128*GAS)                   // 4608
#define GB_BUF (32*GBS)                    // 8448
#define GEMM_FLOATS (2*(GA_BUF+GB_BUF))    // 26112 floats = 104448 B

__global__ __launch_bounds__(256, 1)
void qkv_big(const float* __restrict__ A, const float* __restrict__ B,
             float* __restrict__ C) {
    extern __shared__ float smg[];
    float* As = smg;                 // 2 x [128][36]
    float* Bs = smg + 2*GA_BUF;      // 2 x [32][264]
    const int t = threadIdx.x;
    const int w = t >> 5, l = t & 31, g = l >> 2, ti = l & 3;
    const int wm = (w >> 2) * 64, wn = (w & 3) * 64;
    const int bm = blockIdx.y * 128, bn = blockIdx.x * 256;

    // prologue: chunk 0
    {
        #pragma unroll
        for (int j = 0; j < 4; j++) {
            int i = t + 256*j; int r = i >> 3, c4 = (i & 7) * 4;
            cp16(&As[r*GAS + c4], &A[(size_t)(bm + r)*INDIM + c4]);
        }
        #pragma unroll
        for (int j = 0; j < 8; j++) {
            int i = t + 256*j; int r = i >> 6, c4 = (i & 63) * 4;
            cp16(&Bs[r*GBS + c4], &B[(size_t)r*1536 + bn + c4]);
        }
        CP_COMMIT();
    }

    float c[4][8][4] = {};
    for (int kt = 0; kt < INDIM; kt += 32) {
        CP_WAIT0();
        __syncthreads();
        const int buf = (kt >> 5) & 1;
        if (kt + 32 < INDIM) {
            float* Ad = As + (buf ^ 1) * GA_BUF;
            float* Bd = Bs + (buf ^ 1) * GB_BUF;
            #pragma unroll
            for (int j = 0; j < 4; j++) {
                int i = t + 256*j; int r = i >> 3, c4 = (i & 7) * 4;
                cp16(&Ad[r*GAS + c4], &A[(size_t)(bm + r)*INDIM + kt + 32 + c4]);
            }
            #pragma unroll
            for (int j = 0; j < 8; j++) {
                int i = t + 256*j; int r = i >> 6, c4 = (i & 63) * 4;
                cp16(&Bd[r*GBS + c4], &B[(size_t)(kt + 32 + r)*1536 + bn + c4]);
            }
            CP_COMMIT();
        }
        const float* Af = As + buf * GA_BUF;
        const float* Bf = Bs + buf * GB_BUF;
        #pragma unroll
        for (int ks = 0; ks < 4; ks++) {
            float a[4][4], bfr[8][2];
            #pragma unroll
            for (int mt = 0; mt < 4; mt++) {
                int r = wm + mt*16;
                a[mt][0] = Af[(r + g)     * GAS + ks*8 + ti];
                a[mt][1] = Af[(r + g + 8) * GAS + ks*8 + ti];
                a[mt][2] = Af[(r + g)     * GAS + ks*8 + ti + 4];
                a[mt][3] = Af[(r + g + 8) * GAS + ks*8 + ti + 4];
            }
            #pragma unroll
            for (int nt = 0; nt < 8; nt++) {
                int cc = wn + nt*8 + g;
                bfr[nt][0] = Bf[(ks*8 + ti)     * GBS + cc];
                bfr[nt][1] = Bf[(ks*8 + ti + 4) * GBS + cc];
            }
            #pragma unroll
            for (int mt = 0; mt < 4; mt++)
                #pragma unroll
                for (int nt = 0; nt < 8; nt++)
                    mma8(c[mt][nt], a[mt], bfr[nt]);
        }
    }
    // epilogue: tf32-rounded (consumed by cp.async in attention)
    #pragma unroll
    for (int mt = 0; mt < 4; mt++)
        #pragma unroll
        for (int nt = 0; nt < 8; nt++) {
            int row = bm + wm + mt*16 + g;
            int col = bn + wn + nt*8 + 2*ti;
            *(float2*)&C[(size_t)row*1536 + col] =
                make_float2(totf32(c[mt][nt][0]), totf32(c[mt][nt][1]));
            *(float2*)&C[(size_t)(row+8)*1536 + col] =
                make_float2(totf32(c[mt][nt][2]), totf32(c[mt][nt][3]));
        }
}

// ---------------- flash attention: dist computed in-register ---------------
#define QSS 68
#define PSS 68
#define KSS 68
#define VSS 72
#define AOFS_P  (64*QSS)             // 4352
#define AOFS_K  (AOFS_P + 64*PSS)    // 8704
#define AOFS_V  (AOFS_K + 2*64*KSS)  // 17408
#define AOFS_PQ (AOFS_V + 2*64*VSS)  // 26624
#define AOFS_PK (AOFS_PQ + 192)      // 26816
#define AOFS_RS (AOFS_PK + 384)      // 27200
#define AOFS_RT (AOFS_RS + 256)      // 27456
#define ATT_FLOATS (AOFS_RT + 64)    // 27520 floats = 110080 B

__global__ __launch_bounds__(512, 2)
void attn_kernel(const float* __restrict__ pos, const float* __restrict__ qkv,
                 float* __restrict__ upd) {
    extern __shared__ float sm[];
    float* Qs  = sm;                 // [64][68]
    float* P   = sm + AOFS_P;        // [64][68]  exp(S) (write-only epilogue)
    float* Kb  = sm + AOFS_K;        // 2 x [64][68]
    float* Vb  = sm + AOFS_V;        // 2 x [64][72]
    float* pq  = sm + AOFS_PQ;       // [64][3] query positions
    float* pk  = sm + AOFS_PK;       // 2 x [64][3] key positions
    float* rsP = sm + AOFS_RS;       // [4][64]
    float* rsum= sm + AOFS_RT;       // [64]

    const int t = threadIdx.x;
    const int w = t >> 5, l = t & 31, g = l >> 2, ti = l & 3;
    const int wm = w >> 2, wn = w & 3;
    const int qt = blockIdx.x, h = blockIdx.y, b = blockIdx.z;
    const int q0g = qt * 64, tokbase = b * SEQ;

    // prologue: Q, K0, V0, pos_q, pos_k0 — one commit group
    #pragma unroll
    for (int i = t; i < 64 * 16; i += 512) {
        int q = i >> 4, d4 = (i & 15) * 4;
        cp16(&Qs[q*QSS + d4], &qkv[(size_t)(tokbase + q0g + q)*1536 + h*64 + d4]);
    }
    #pragma unroll
    for (int i = t; i < 64 * 16; i += 512) {
        int k = i >> 4, d4 = (i & 15) * 4;
        cp16(&Kb[k*KSS + d4], &qkv[(size_t)(tokbase + k)*1536 + 512 + h*64 + d4]);
    }
    #pragma unroll
    for (int i = t; i < 64 * 16; i += 512) {
        int k = i >> 4, d4 = (i & 15) * 4;
        cp16(&Vb[k*VSS + d4], &qkv[(size_t)(tokbase + k)*1536 + 1024 + h*64 + d4]);
    }
    if (t < 192) cp4(&pq[t], &pos[(size_t)(tokbase + q0g)*3 + t]);
    else if (t < 384) cp4(&pk[t-192], &pos[(size_t)tokbase*3 + (t-192)]);
    CP_COMMIT();

    const float K1 = (float)(1.4426950408889634 * 0.08838834764831845); // log2e/(8*sqrt2)
    const float C2 = (float)(1.4142135623730951 * 1.4426950408889634);  // sqrt2*log2e
    float cO[2][4] = {};
    float rs0 = 0.f, rs1 = 0.f;

    for (int c = 0; c < 8; c++) {
        CP_WAIT0();                  // chunk-c group complete (K,V,pos)
        __syncthreads();             // visible; buffers (c+1)&1 free
        if (c < 7) {
            const int nx = (c + 1) & 1;
            #pragma unroll
            for (int i = t; i < 64 * 16; i += 512) {
                int k = i >> 4, d4 = (i & 15) * 4;
                cp16(&Kb[nx*64*KSS + k*KSS + d4],
                     &qkv[(size_t)(tokbase + (c+1)*64 + k)*1536 + 512 + h*64 + d4]);
            }
            #pragma unroll
            for (int i = t; i < 64 * 16; i += 512) {
                int k = i >> 4, d4 = (i & 15) * 4;
                cp16(&Vb[nx*64*VSS + k*VSS + d4],
                     &qkv[(size_t)(tokbase + (c+1)*64 + k)*1536 + 1024 + h*64 + d4]);
            }
            if (t < 192) cp4(&pk[nx*192 + t], &pos[(size_t)(tokbase + (c+1)*64)*3 + t]);
            CP_COMMIT();
        }
        const float* Kc = Kb + (c & 1) * 64 * KSS;

        // S_c = Q K_c^T
        float cS[2][4] = {};
        #pragma unroll
        for (int ks = 0; ks < 8; ks++) {
            float a[4], bf[2][2];
            a[0] = Qs[(wm*16 + g)     * QSS + ks*8 + ti];
            a[1] = Qs[(wm*16 + g + 8) * QSS + ks*8 + ti];
            a[2] = Qs[(wm*16 + g)     * QSS + ks*8 + ti + 4];
            a[3] = Qs[(wm*16 + g + 8) * QSS + ks*8 + ti + 4];
            #pragma unroll
            for (int nt = 0; nt < 2; nt++) {
                int key = wn*16 + nt*8 + g;
                bf[nt][0] = Kc[key*KSS + ks*8 + ti];
                bf[nt][1] = Kc[key*KSS + ks*8 + ti + 4];
            }
            mma8(cS[0], a, bf[0]);
            mma8(cS[1], a, bf[1]);
        }

        // epilogue: dist (regs) + exp -> P, rowsum accumulation
        {
            const int r0 = wm*16 + g;
            float qx0 = pq[r0*3],     qy0 = pq[r0*3+1],     qz0 = pq[r0*3+2];
            float qx1 = pq[(r0+8)*3], qy1 = pq[(r0+8)*3+1], qz1 = pq[(r0+8)*3+2];
            const float* pkc = pk + (c & 1) * 192;
            #pragma unroll
            for (int nt = 0; nt < 2; nt++) {
                int kl = wn*16 + nt*8 + 2*ti;
                float kx0 = pkc[kl*3],   ky0 = pkc[kl*3+1], kz0 = pkc[kl*3+2];
                float kx1 = pkc[kl*3+3], ky1 = pkc[kl*3+4], kz1 = pkc[kl*3+5];
                float dx, dy, dz;
                dx = qx0-kx0; dy = qy0-ky0; dz = qz0-kz0;
                float e00 = fsqrt_fast(fmaf(dx,dx,fmaf(dy,dy,dz*dz))) * C2;
                dx = qx0-kx1; dy = qy0-ky1; dz = qz0-kz1;
                float e01 = fsqrt_fast(fmaf(dx,dx,fmaf(dy,dy,dz*dz))) * C2;
                dx = qx1-kx0; dy = qy1-ky0; dz = qz1-kz0;
                float e10 = fsqrt_fast(fmaf(dx,dx,fmaf(dy,dy,dz*dz))) * C2;
                dx = qx1-kx1; dy = qy1-ky1; dz = qz1-kz1;
                float e11 = fsqrt_fast(fmaf(dx,dx,fmaf(dy,dy,dz*dz))) * C2;
                float2 u0, u1;
                u0.x = totf32(exp2_fast(fmaf(cS[nt][0], K1, e00)));
                u0.y = totf32(exp2_fast(fmaf(cS[nt][1], K1, e01)));
                u1.x = totf32(exp2_fast(fmaf(cS[nt][2], K1, e10)));
                u1.y = totf32(exp2_fast(fmaf(cS[nt][3], K1, e11)));
                *(float2*)&P[r0*PSS + kl]     = u0;
                *(float2*)&P[(r0+8)*PSS + kl] = u1;
                rs0 += u0.x + u0.y;
                rs1 += u1.x + u1.y;
            }
        }
        __syncthreads();             // P visible

        // O += P_c V_c
        const float* Vc = Vb + (c & 1) * 64 * VSS;
        #pragma unroll
        for (int ks = 0; ks < 8; ks++) {
            float a[4], bf[2][2];
            a[0] = P[(wm*16 + g)     * PSS + ks*8 + ti];
            a[1] = P[(wm*16 + g + 8) * PSS + ks*8 + ti];
            a[2] = P[(wm*16 + g)     * PSS + ks*8 + ti + 4];
            a[3] = P[(wm*16 + g + 8) * PSS + ks*8 + ti + 4];
            #pragma unroll
            for (int nt = 0; nt < 2; nt++) {
                int dc = wn*16 + nt*8 + g;
                bf[nt][0] = Vc[(ks*8 + ti)     * VSS + dc];
                bf[nt][1] = Vc[(ks*8 + ti + 4) * VSS + dc];
            }
            mma8(cO[0], a, bf[0]);
            mma8(cO[1], a, bf[1]);
        }
    }

    // deterministic rowsum reduce
    rs0 += __shfl_xor_sync(0xffffffffu, rs0, 1);
    rs0 += __shfl_xor_sync(0xffffffffu, rs0, 2);
    rs1 += __shfl_xor_sync(0xffffffffu, rs1, 1);
    rs1 += __shfl_xor_sync(0xffffffffu, rs1, 2);
    __syncthreads();                 // last PV done before rsP reuse
    if (ti == 0) {
        rsP[wn*64 + wm*16 + g]     = rs0;
        rsP[wn*64 + wm*16 + g + 8] = rs1;
    }
    __syncthreads();
    if (t < 64) rsum[t] = 1.f / (rsP[t] + rsP[64 + t] + rsP[128 + t] + rsP[192 + t]);
    __syncthreads();

    {
        float inv0 = rsum[wm*16 + g];
        float inv1 = rsum[wm*16 + g + 8];
        #pragma unroll
        for (int nt = 0; nt < 2; nt++) {
            int r = tokbase + q0g + wm*16 + g;
            int col = h*64 + wn*16 + nt*8 + 2*ti;
            *(float2*)&upd[(size_t)r * HDIM + col] =
                make_float2(totf32(cO[nt][0]*inv0), totf32(cO[nt][1]*inv0));
            *(float2*)&upd[(size_t)(r + 8) * HDIM + col] =
                make_float2(totf32(cO[nt][2]*inv1), totf32(cO[nt][3]*inv1));
        }
    }
}

// ---------------- fused 3-layer MLP: grid 128, 512 thr ---------------------
#define MH1S 132
#define MH2S 68
#define MAS  36
#define MBS  136
#define MW2S 72
#define MW3S 264
#define MOFS_H2 (128*MH1S)             // 16896
#define MOFS_ST (MOFS_H2 + 128*MH2S)   // 25600
#define MOFS_BS (MOFS_ST + 128*MAS)    // 30208
#define MOFS_W2 (MOFS_ST + 64*MW3S)    // 42496
#define MLP_FLOATS (MOFS_W2 + 128*MW2S) // 51712 floats = 206848 B

__global__ __launch_bounds__(512, 1)
void mlp_fused(const float* __restrict__ X,
               const float* __restrict__ W1, const float* __restrict__ b1,
               const float* __restrict__ W2, const float* __restrict__ b2,
               const float* __restrict__ W3, const float* __restrict__ b3,
               float* __restrict__ out) {
    extern __shared__ float sm[];
    float* H1  = sm;                 // [128][132]
    float* H2  = sm + MOFS_H2;       // [128][68]
    float* As  = sm + MOFS_ST;       // [128][36]   (phase1)
    float* Bs  = sm + MOFS_BS;       // [32][136]   (phase1)
    float* W3s = sm + MOFS_ST;       // [64][264]   (phase3, aliases As/Bs)
    float* W2s = sm + MOFS_W2;       // [128][72]

    const int t = threadIdx.x;
    const int w = t >> 5, l = t & 31, g = l >> 2, ti = l & 3;
    const int wm = w >> 2, wn = w & 3;
    const int bm = blockIdx.x * 128;

    // stage W2 async immediately (own region, used in phase2)
    #pragma unroll
    for (int j = 0; j < 4; j++) {
        int i = t + 512*j; int kr = i >> 4, n4 = (i & 15) * 4;
        cp16(&W2s[kr*MW2S + n4], &W2[kr*64 + n4]);
    }
    CP_COMMIT();

    // ---- phase 1: H1 = silu(X @ W1 + b1), K=512, reg-prefetch pipeline ----
    const float* A = X + (size_t)bm * HDIM;
    float4 ra[2], rb[2];
    #pragma unroll
    for (int j = 0; j < 2; j++) { int i = t + 512*j;
        ra[j] = *(const float4*)&A[(size_t)(i>>3) * HDIM + (i&7)*4]; }
    #pragma unroll
    for (int j = 0; j < 2; j++) { int i = t + 512*j;
        rb[j] = *(const float4*)&W1[(size_t)(i>>5) * 128 + (i&31)*4]; }

    float c1[2][4][4] = {};
    for (int kt = 0; kt < HDIM; kt += 32) {
        #pragma unroll
        for (int j = 0; j < 2; j++) { int i = t + 512*j;
            *(float4*)&As[(i>>3)*MAS + (i&7)*4] = ra[j]; }          // X already tf32
        #pragma unroll
        for (int j = 0; j < 2; j++) { int i = t + 512*j;
            *(float4*)&Bs[(i>>5)*MBS + (i&31)*4] = cvt4(rb[j]); }
        __syncthreads();
        if (kt + 32 < HDIM) {
            #pragma unroll
            for (int j = 0; j < 2; j++) { int i = t + 512*j;
                ra[j] = *(const float4*)&A[(size_t)(i>>3) * HDIM + kt + 32 + (i&7)*4]; }
            #pragma unroll
            for (int j = 0; j < 2; j++) { int i = t + 512*j;
                rb[j] = *(const float4*)&W1[(size_t)(kt + 32 + (i>>5)) * 128 + (i&31)*4]; }
        }
        #pragma unroll
        for (int ks = 0; ks < 4; ks++) {
            float a[2][4], bfr[4][2];
            #pragma unroll
            for (int mt = 0; mt < 2; mt++) {
                int r = wm*32 + mt*16;
                a[mt][0] = As[(r + g)     * MAS + ks*8 + ti];
                a[mt][1] = As[(r + g + 8) * MAS + ks*8 + ti];
                a[mt][2] = As[(r + g)     * MAS + ks*8 + ti + 4];
                a[mt][3] = As[(r + g + 8) * MAS + ks*8 + ti + 4];
            }
            #pragma unroll
            for (int nt = 0; nt < 4; nt++) {
                int cc = wn*32 + nt*8 + g;
                bfr[nt][0] = Bs[(ks*8 + ti)     * MBS + cc];
                bfr[nt][1] = Bs[(ks*8 + ti + 4) * MBS + cc];
            }
            #pragma unroll
            for (int mt = 0; mt < 2; mt++)
                #pragma unroll
                for (int nt = 0; nt < 4; nt++)
                    mma8(c1[mt][nt], a[mt], bfr[nt]);
        }
        __syncthreads();
    }
    #pragma unroll
    for (int mt = 0; mt < 2; mt++)
        #pragma unroll
        for (int nt = 0; nt < 4; nt++) {
            int row = wm*32 + mt*16 + g;
            int col = wn*32 + nt*8 + 2*ti;
            float bb0 = b1[col], bb1 = b1[col+1];
            float v0 = c1[mt][nt][0] + bb0, v1 = c1[mt][nt][1] + bb1;
            float v2 = c1[mt][nt][2] + bb0, v3 = c1[mt][nt][3] + bb1;
            v0 = totf32(v0 / (1.f + __expf(-v0))); v1 = totf32(v1 / (1.f + __expf(-v1)));
            v2 = totf32(v2 / (1.f + __expf(-v2))); v3 = totf32(v3 / (1.f + __expf(-v3)));
            *(float2*)&H1[row*MH1S + col]     = make_float2(v0, v1);
            *(float2*)&H1[(row+8)*MH1S + col] = make_float2(v2, v3);
        }
    __syncthreads();                 // H1 visible; As/Bs region free

    // stage W3 async into freed region (overlaps phase 2)
    #pragma unroll
    for (int j = 0; j < 8; j++) {
        int i = t + 512*j; int kr = i >> 6, n4 = (i & 63) * 4;
        cp16(&W3s[kr*MW3S + n4], &W3[kr*256 + n4]);
    }
    CP_COMMIT();
    CP_WAIT1();                      // W2 group complete (W3 still in flight)
    __syncthreads();

    // ---- phase 2: H2 = silu(H1 @ W2 + b2), K=128 ----
    float c2[2][2][4] = {};
    #pragma unroll
    for (int ks = 0; ks < 16; ks++) {
        float a[2][4], bfr[2][2];
        #pragma unroll
        for (int mt = 0; mt < 2; mt++) {
            int r = wm*32 + mt*16;
            a[mt][0] = H1[(r + g)     * MH1S + ks*8 + ti];
            a[mt][1] = H1[(r + g + 8) * MH1S + ks*8 + ti];
            a[mt][2] = H1[(r + g)     * MH1S + ks*8 + ti + 4];
            a[mt][3] = H1[(r + g + 8) * MH1S + ks*8 + ti + 4];
        }
        #pragma unroll
        for (int nt = 0; nt < 2; nt++) {
            int cc = wn*16 + nt*8 + g;
            bfr[nt][0] = totf32(W2s[(ks*8 + ti)     * MW2S + cc]);
            bfr[nt][1] = totf32(W2s[(ks*8 + ti + 4) * MW2S + cc]);
        }
        #pragma unroll
        for (int mt = 0; mt < 2; mt++)
            #pragma unroll
            for (int nt = 0; nt < 2; nt++)
                mma8(c2[mt][nt], a[mt], bfr[nt]);
    }
    #pragma unroll
    for (int mt = 0; mt < 2; mt++)
        #pragma unroll
        for (int nt = 0; nt < 2; nt++) {
            int row = wm*32 + mt*16 + g;
            int col = wn*16 + nt*8 + 2*ti;
            float bb0 = b2[col], bb1 = b2[col+1];
            float v0 = c2[mt][nt][0] + bb0, v1 = c2[mt][nt][1] + bb1;
            float v2 = c2[mt][nt][2] + bb0, v3 = c2[mt][nt][3] + bb1;
            v0 = totf32(v0 / (1.f + __expf(-v0))); v1 = totf32(v1 / (1.f + __expf(-v1)));
            v2 = totf32(v2 / (1.f + __expf(-v2))); v3 = totf32(v3 / (1.f + __expf(-v3)));
            *(float2*)&H2[row*MH2S + col]     = make_float2(v0, v1);
            *(float2*)&H2[(row+8)*MH2S + col] = make_float2(v2, v3);
        }
    CP_WAIT0();                      // W3 complete
    __syncthreads();                 // H2 + W3s visible

    // ---- phase 3: out = silu(H2 @ W3 + b3), K=64, N=256 ----
    float c3[2][8][4] = {};
    #pragma unroll
    for (int ks = 0; ks < 8; ks++) {
        float a[2][4];
        #pragma unroll
        for (int mt = 0; mt < 2; mt++) {
            int r = wm*32 + mt*16;
            a[mt][0] = H2[(r + g)     * MH2S + ks*8 + ti];
            a[mt][1] = H2[(r + g + 8) * MH2S + ks*8 + ti];
            a[mt][2] = H2[(r + g)     * MH2S + ks*8 + ti + 4];
            a[mt][3] = H2[(r + g + 8) * MH2S + ks*8 + ti + 4];
        }
        #pragma unroll
        for (int nt = 0; nt < 8; nt++) {
            float bfr[2];
            int cc = wn*64 + nt*8 + g;
            bfr[0] = totf32(W3s[(ks*8 + ti)     * MW3S + cc]);
            bfr[1] = totf32(W3s[(ks*8 + ti + 4) * MW3S + cc]);
            mma8(c3[0][nt], a[0], bfr);
            mma8(c3[1][nt], a[1], bfr);
        }
    }
    #pragma unroll
    for (int mt = 0; mt < 2; mt++)
        #pragma unroll
        for (int nt = 0; nt < 8; nt++) {
            int row = bm + wm*32 + mt*16 + g;
            int col = wn*64 + nt*8 + 2*ti;
            float bb0 = b3[col], bb1 = b3[col+1];
            float v0 = c3[mt][nt][0] + bb0, v1 = c3[mt][nt][1] + bb1;
            float v2 = c3[mt][nt][2] + bb0, v3 = c3[mt][nt][3] + bb1;
            v0 = v0 / (1.f + __expf(-v0)); v1 = v1 / (1.f + __expf(-v1));
            v2 = v2 / (1.f + __expf(-v2)); v3 = v3 / (1.f + __expf(-v3));
            *(float2*)&out[(size_t)row * INDIM + col]     = make_float2(v0, v1);
            *(float2*)&out[(size_t)(row+8) * INDIM + col] = make_float2(v2, v3);
        }
}

// ---------------- launch ----------------
extern "C" void kernel_launch(void* const* d_in, const int* in_sizes, int n_in,
                              void* d_out, int out_size) {
    const float* pos  = (const float*)d_in[0];
    const float* feat = (const float*)d_in[1];
    const float* Wk   = (const float*)d_in[2];
    const float* Wq   = (const float*)d_in[3];
    const float* Wv   = (const float*)d_in[4];
    const float* W1   = (const float*)d_in[5];
    const float* b1   = (const float*)d_in[6];
    const float* W2   = (const float*)d_in[7];
    const float* b2   = (const float*)d_in[8];
    const float* W3   = (const float*)d_in[9];
    const float* b3   = (const float*)d_in[10];
    float* out = (float*)d_out;

    void* p;
    cudaGetSymbolAddress(&p, g_qkv);   float* qkv   = (float*)p;
    cudaGetSymbolAddress(&p, g_upd);   float* upd   = (float*)p;
    cudaGetSymbolAddress(&p, g_featr); float* featr = (float*)p;
    cudaGetSymbolAddress(&p, g_wcat);  float* wcat  = (float*)p;

    // pre-round inputs to tf32 (rna) for the cp.async GEMM path
    prep_round<<<(MTOK*INDIM/4 + INDIM*1536/4 + 255)/256, 256>>>(feat, Wq, Wk, Wv, featr, wcat);

    size_t gsh = (size_t)GEMM_FLOATS * sizeof(float);
    cudaFuncSetAttribute(qkv_big, cudaFuncAttributeMaxDynamicSharedMemorySize, (int)gsh);
    qkv_big<<<dim3(6, MTOK/128), 256, gsh>>>(featr, wcat, qkv);

    size_t ash = (size_t)ATT_FLOATS * sizeof(float);
    cudaFuncSetAttribute(attn_kernel, cudaFuncAttributeMaxDynamicSharedMemorySize, (int)ash);
    attn_kernel<<<dim3(SEQ/64, NHEADS, BATCH), 512, ash>>>(pos, qkv, upd);

    size_t msh = (size_t)MLP_FLOATS * sizeof(float);
    cudaFuncSetAttribute(mlp_fused, cudaFuncAttributeMaxDynamicSharedMemorySize, (int)msh);
    mlp_fused<<<MTOK/128, 512, msh>>>(upd, W1, b1, W2, b2, W3, b3, out);
}

// round 13
// speedup vs baseline: 4.1272x; 1.0232x over previous
#include <cuda_runtime.h>
#include <math.h>
#include <stdint.h>

#define BATCH   32
#define SEQ     512
#define NHEADS  8
#define HID     64
#define INDIM   256
#define HDIM    512
#define MTOK    (BATCH*SEQ)       /* 16384 tokens */

// ---------------- scratch buffers (device globals; no allocation) ----------
__device__ float g_qkv  [(size_t)MTOK * 3 * HDIM];
__device__ float g_upd  [(size_t)MTOK * HDIM];
__device__ float g_featr[(size_t)MTOK * INDIM];
__device__ float g_wcat [(size_t)INDIM * 3 * HDIM];

// ---------------- small helpers ----------------
__device__ __forceinline__ float totf32(float x) {
    uint32_t u;
    asm("cvt.rna.tf32.f32 %0, %1;" : "=r"(u) : "f"(x));
    return __uint_as_float(u);
}
__device__ __forceinline__ float4 cvt4(float4 v) {
    return make_float4(totf32(v.x), totf32(v.y), totf32(v.z), totf32(v.w));
}
__device__ __forceinline__ float fsqrt_fast(float x) {
    float y;
    asm("sqrt.approx.f32 %0, %1;" : "=f"(y) : "f"(x));
    return y;
}
// exp2 on the FMA pipe; |rel err| ~2e-6 (below subsequent tf32 rounding)
__device__ __forceinline__ float exp2_fast(float x) {
    x = fminf(fmaxf(x, -120.f), 120.f);
    float z = x + 12582912.0f;
    float n = z - 12582912.0f;
    float r = x - n;
    int   ni = __float_as_int(z) - 0x4B400000;
    float s = __int_as_float((ni + 127) << 23);
    float p = 1.3333558e-3f;
    p = fmaf(p, r, 9.6181291e-3f);
    p = fmaf(p, r, 5.5504110e-2f);
    p = fmaf(p, r, 2.4022651e-1f);
    p = fmaf(p, r, 6.9314718e-1f);
    p = fmaf(p, r, 1.0f);
    return p * s;
}
__device__ __forceinline__ void mma8(float c[4], const float a[4], const float b[2]) {
    asm volatile(
        "mma.sync.aligned.m16n8k8.row.col.f32.tf32.tf32.f32 "
        "{%0,%1,%2,%3}, {%4,%5,%6,%7}, {%8,%9}, {%0,%1,%2,%3};\n"
        : "+f"(c[0]), "+f"(c[1]), "+f"(c[2]), "+f"(c[3])
        : "r"(__float_as_uint(a[0])), "r"(__float_as_uint(a[1])),
          "r"(__float_as_uint(a[2])), "r"(__float_as_uint(a[3])),
          "r"(__float_as_uint(b[0])), "r"(__float_as_uint(b[1])));
}
__device__ __forceinline__ void cp16(float* dst_smem, const float* src) {
    uint32_t d = (uint32_t)__cvta_generic_to_shared(dst_smem);
    asm volatile("cp.async.cg.shared.global [%0], [%1], 16;" :: "r"(d), "l"(src));
}
__device__ __forceinline__ void cp4(float* dst_smem, const float* src) {
    uint32_t d = (uint32_t)__cvta_generic_to_shared(dst_smem);
    asm volatile("cp.async.ca.shared.global [%0], [%1], 4;" :: "r"(d), "l"(src));
}
#define CP_COMMIT()  asm volatile("cp.async.commit_group;")
#define CP_WAIT0()   asm volatile("cp.async.wait_group 0;")
#define CP_WAIT1()   asm volatile("cp.async.wait_group 1;")

// ------------- prep: tf32-round feat; concat+round Wq|Wk|Wv ----------------
__global__ __launch_bounds__(256)
void prep_round(const float* __restrict__ feat, const float* __restrict__ Wq,
                const float* __restrict__ Wk, const float* __restrict__ Wv,
                float* __restrict__ featr, float* __restrict__ wcat) {
    const int NF4 = MTOK * INDIM / 4;
    int idx = blockIdx.x * 256 + threadIdx.x;
    if (idx < NF4) {
        ((float4*)featr)[idx] = cvt4(((const float4*)feat)[idx]);
    } else {
        int j = idx - NF4;
        int k  = j / 384;
        int c4 = (j % 384) * 4;
        const float* src = (c4 < 512)  ? &Wq[k*512 + c4] :
                           (c4 < 1024) ? &Wk[k*512 + c4 - 512] :
                                         &Wv[k*512 + c4 - 1024];
        ((float4*)wcat)[j] = cvt4(*(const float4*)src);
    }
}

// ------ QKV GEMM v2: BM=128 BN=128 BK=32, 8 warps (2x4), warp tile 64x32 ---
#define GAS 36
#define GBS 136
#define GA_BUF (128*GAS)
#define GB_BUF (32*GBS)
#define GEMM_FLOATS (2*(GA_BUF+GB_BUF))

__global__ __launch_bounds__(256, 2)
void qkv_gemm2(const float* __restrict__ A, const float* __restrict__ B,
               float* __restrict__ C) {
    extern __shared__ float smg[];
    float* As = smg;
    float* Bs = smg + 2*GA_BUF;
    const int t = threadIdx.x;
    const int w = t >> 5, l = t & 31, g = l >> 2, ti = l & 3;
    const int wrow = (w >> 2) * 64;
    const int wcol = (w & 3) * 32;
    const int bm = blockIdx.y * 128, bn = blockIdx.x * 128;

    {   // prologue chunk 0
        #pragma unroll
        for (int j = 0; j < 4; j++) {
            int i = t + 256*j; int r = i >> 3, c4 = (i & 7) * 4;
            cp16(&As[r*GAS + c4], &A[(size_t)(bm + r)*INDIM + c4]);
        }
        #pragma unroll
        for (int j = 0; j < 4; j++) {
            int i = t + 256*j; int r = i >> 5, c4 = (i & 31) * 4;
            cp16(&Bs[r*GBS + c4], &B[(size_t)r*1536 + bn + c4]);
        }
        CP_COMMIT();
    }

    float acc[4][4][4] = {};
    for (int kt = 0; kt < INDIM; kt += 32) {
        CP_WAIT0();
        __syncthreads();
        const int buf = (kt >> 5) & 1;
        if (kt + 32 < INDIM) {
            float* Ad = As + (buf ^ 1) * GA_BUF;
            float* Bd = Bs + (buf ^ 1) * GB_BUF;
            #pragma unroll
            for (int j = 0; j < 4; j++) {
                int i = t + 256*j; int r = i >> 3, c4 = (i & 7) * 4;
                cp16(&Ad[r*GAS + c4], &A[(size_t)(bm + r)*INDIM + kt + 32 + c4]);
            }
            #pragma unroll
            for (int j = 0; j < 4; j++) {
                int i = t + 256*j; int r = i >> 5, c4 = (i & 31) * 4;
                cp16(&Bd[r*GBS + c4], &B[(size_t)(kt + 32 + r)*1536 + bn + c4]);
            }
            CP_COMMIT();
        }
        const float* Af = As + buf * GA_BUF;
        const float* Bf = Bs + buf * GB_BUF;
        #pragma unroll
        for (int ks = 0; ks < 4; ks++) {
            float a[4][4], bfr[4][2];
            #pragma unroll
            for (int mt = 0; mt < 4; mt++) {
                int r = wrow + mt*16;
                a[mt][0] = Af[(r + g)     * GAS + ks*8 + ti];
                a[mt][1] = Af[(r + g + 8) * GAS + ks*8 + ti];
                a[mt][2] = Af[(r + g)     * GAS + ks*8 + ti + 4];
                a[mt][3] = Af[(r + g + 8) * GAS + ks*8 + ti + 4];
            }
            #pragma unroll
            for (int nt = 0; nt < 4; nt++) {
                int cc = wcol + nt*8 + g;
                bfr[nt][0] = Bf[(ks*8 + ti)     * GBS + cc];
                bfr[nt][1] = Bf[(ks*8 + ti + 4) * GBS + cc];
            }
            #pragma unroll
            for (int mt = 0; mt < 4; mt++)
                #pragma unroll
                for (int nt = 0; nt < 4; nt++)
                    mma8(acc[mt][nt], a[mt], bfr[nt]);
        }
    }
    #pragma unroll
    for (int mt = 0; mt < 4; mt++)
        #pragma unroll
        for (int nt = 0; nt < 4; nt++) {
            int row = bm + wrow + mt*16 + g;
            int col = bn + wcol + nt*8 + 2*ti;
            *(float2*)&C[(size_t)row*1536 + col] =
                make_float2(totf32(acc[mt][nt][0]), totf32(acc[mt][nt][1]));
            *(float2*)&C[(size_t)(row+8)*1536 + col] =
                make_float2(totf32(acc[mt][nt][2]), totf32(acc[mt][nt][3]));
        }
}

// ---------------- flash attention (dist recomputed in-register) ------------
#define QSS 68
#define PSS 68
#define KSS 68
#define VSS 72
#define AOFS_P  (64*QSS)
#define AOFS_K  (AOFS_P + 64*PSS)
#define AOFS_V  (AOFS_K + 2*64*KSS)
#define AOFS_PQ (AOFS_V + 2*64*VSS)
#define AOFS_PK (AOFS_PQ + 192)
#define AOFS_RS (AOFS_PK + 384)
#define AOFS_RT (AOFS_RS + 256)
#define ATT_FLOATS (AOFS_RT + 64)

__global__ __launch_bounds__(512, 2)
void attn_kernel(const float* __restrict__ pos, const float* __restrict__ qkv,
                 float* __restrict__ upd) {
    extern __shared__ float sm[];
    float* Qs  = sm;
    float* P   = sm + AOFS_P;
    float* Kb  = sm + AOFS_K;
    float* Vb  = sm + AOFS_V;
    float* pq  = sm + AOFS_PQ;
    float* pk  = sm + AOFS_PK;
    float* rsP = sm + AOFS_RS;
    float* rsum= sm + AOFS_RT;

    const int t = threadIdx.x;
    const int w = t >> 5, l = t & 31, g = l >> 2, ti = l & 3;
    const int wm = w >> 2, wn = w & 3;
    const int qt = blockIdx.x, h = blockIdx.y, b = blockIdx.z;
    const int q0g = qt * 64, tokbase = b * SEQ;

    #pragma unroll
    for (int i = t; i < 64 * 16; i += 512) {
        int q = i >> 4, d4 = (i & 15) * 4;
        cp16(&Qs[q*QSS + d4], &qkv[(size_t)(tokbase + q0g + q)*1536 + h*64 + d4]);
    }
    #pragma unroll
    for (int i = t; i < 64 * 16; i += 512) {
        int k = i >> 4, d4 = (i & 15) * 4;
        cp16(&Kb[k*KSS + d4], &qkv[(size_t)(tokbase + k)*1536 + 512 + h*64 + d4]);
    }
    #pragma unroll
    for (int i = t; i < 64 * 16; i += 512) {
        int k = i >> 4, d4 = (i & 15) * 4;
        cp16(&Vb[k*VSS + d4], &qkv[(size_t)(tokbase + k)*1536 + 1024 + h*64 + d4]);
    }
    if (t < 192) cp4(&pq[t], &pos[(size_t)(tokbase + q0g)*3 + t]);
    else if (t < 384) cp4(&pk[t-192], &pos[(size_t)tokbase*3 + (t-192)]);
    CP_COMMIT();

    const float K1 = (float)(1.4426950408889634 * 0.08838834764831845);
    const float C2 = (float)(1.4142135623730951 * 1.4426950408889634);
    float cO[2][4] = {};
    float rs0 = 0.f, rs1 = 0.f;

    for (int c = 0; c < 8; c++) {
        CP_WAIT0();
        __syncthreads();
        if (c < 7) {
            const int nx = (c + 1) & 1;
            #pragma unroll
            for (int i = t; i < 64 * 16; i += 512) {
                int k = i >> 4, d4 = (i & 15) * 4;
                cp16(&Kb[nx*64*KSS + k*KSS + d4],
                     &qkv[(size_t)(tokbase + (c+1)*64 + k)*1536 + 512 + h*64 + d4]);
            }
            #pragma unroll
            for (int i = t; i < 64 * 16; i += 512) {
                int k = i >> 4, d4 = (i & 15) * 4;
                cp16(&Vb[nx*64*VSS + k*VSS + d4],
                     &qkv[(size_t)(tokbase + (c+1)*64 + k)*1536 + 1024 + h*64 + d4]);
            }
            if (t < 192) cp4(&pk[nx*192 + t], &pos[(size_t)(tokbase + (c+1)*64)*3 + t]);
            CP_COMMIT();
        }
        const float* Kc = Kb + (c & 1) * 64 * KSS;

        float cS[2][4] = {};
        #pragma unroll
        for (int ks = 0; ks < 8; ks++) {
            float a[4], bf[2][2];
            a[0] = Qs[(wm*16 + g)     * QSS + ks*8 + ti];
            a[1] = Qs[(wm*16 + g + 8) * QSS + ks*8 + ti];
            a[2] = Qs[(wm*16 + g)     * QSS + ks*8 + ti + 4];
            a[3] = Qs[(wm*16 + g + 8) * QSS + ks*8 + ti + 4];
            #pragma unroll
            for (int nt = 0; nt < 2; nt++) {
                int key = wn*16 + nt*8 + g;
                bf[nt][0] = Kc[key*KSS + ks*8 + ti];
                bf[nt][1] = Kc[key*KSS + ks*8 + ti + 4];
            }
            mma8(cS[0], a, bf[0]);
            mma8(cS[1], a, bf[1]);
        }

        {
            const int r0 = wm*16 + g;
            float qx0 = pq[r0*3],     qy0 = pq[r0*3+1],     qz0 = pq[r0*3+2];
            float qx1 = pq[(r0+8)*3], qy1 = pq[(r0+8)*3+1], qz1 = pq[(r0+8)*3+2];
            const float* pkc = pk + (c & 1) * 192;
            #pragma unroll
            for (int nt = 0; nt < 2; nt++) {
                int kl = wn*16 + nt*8 + 2*ti;
                float kx0 = pkc[kl*3],   ky0 = pkc[kl*3+1], kz0 = pkc[kl*3+2];
                float kx1 = pkc[kl*3+3], ky1 = pkc[kl*3+4], kz1 = pkc[kl*3+5];
                float dx, dy, dz;
                dx = qx0-kx0; dy = qy0-ky0; dz = qz0-kz0;
                float e00 = fsqrt_fast(fmaf(dx,dx,fmaf(dy,dy,dz*dz))) * C2;
                dx = qx0-kx1; dy = qy0-ky1; dz = qz0-kz1;
                float e01 = fsqrt_fast(fmaf(dx,dx,fmaf(dy,dy,dz*dz))) * C2;
                dx = qx1-kx0; dy = qy1-ky0; dz = qz1-kz0;
                float e10 = fsqrt_fast(fmaf(dx,dx,fmaf(dy,dy,dz*dz))) * C2;
                dx = qx1-kx1; dy = qy1-ky1; dz = qz1-kz1;
                float e11 = fsqrt_fast(fmaf(dx,dx,fmaf(dy,dy,dz*dz))) * C2;
                float2 u0, u1;
                u0.x = totf32(exp2_fast(fmaf(cS[nt][0], K1, e00)));
                u0.y = totf32(exp2_fast(fmaf(cS[nt][1], K1, e01)));
                u1.x = totf32(exp2_fast(fmaf(cS[nt][2], K1, e10)));
                u1.y = totf32(exp2_fast(fmaf(cS[nt][3], K1, e11)));
                *(float2*)&P[r0*PSS + kl]     = u0;
                *(float2*)&P[(r0+8)*PSS + kl] = u1;
                rs0 += u0.x + u0.y;
                rs1 += u1.x + u1.y;
            }
        }
        __syncthreads();

        const float* Vc = Vb + (c & 1) * 64 * VSS;
        #pragma unroll
        for (int ks = 0; ks < 8; ks++) {
            float a[4], bf[2][2];
            a[0] = P[(wm*16 + g)     * PSS + ks*8 + ti];
            a[1] = P[(wm*16 + g + 8) * PSS + ks*8 + ti];
            a[2] = P[(wm*16 + g)     * PSS + ks*8 + ti + 4];
            a[3] = P[(wm*16 + g + 8) * PSS + ks*8 + ti + 4];
            #pragma unroll
            for (int nt = 0; nt < 2; nt++) {
                int dc = wn*16 + nt*8 + g;
                bf[nt][0] = Vc[(ks*8 + ti)     * VSS + dc];
                bf[nt][1] = Vc[(ks*8 + ti + 4) * VSS + dc];
            }
            mma8(cO[0], a, bf[0]);
            mma8(cO[1], a, bf[1]);
        }
    }

    rs0 += __shfl_xor_sync(0xffffffffu, rs0, 1);
    rs0 += __shfl_xor_sync(0xffffffffu, rs0, 2);
    rs1 += __shfl_xor_sync(0xffffffffu, rs1, 1);
    rs1 += __shfl_xor_sync(0xffffffffu, rs1, 2);
    __syncthreads();
    if (ti == 0) {
        rsP[wn*64 + wm*16 + g]     = rs0;
        rsP[wn*64 + wm*16 + g + 8] = rs1;
    }
    __syncthreads();
    if (t < 64) rsum[t] = 1.f / (rsP[t] + rsP[64 + t] + rsP[128 + t] + rsP[192 + t]);
    __syncthreads();

    {
        float inv0 = rsum[wm*16 + g];
        float inv1 = rsum[wm*16 + g + 8];
        #pragma unroll
        for (int nt = 0; nt < 2; nt++) {
            int r = tokbase + q0g + wm*16 + g;
            int col = h*64 + wn*16 + nt*8 + 2*ti;
            *(float2*)&upd[(size_t)r * HDIM + col] =
                make_float2(totf32(cO[nt][0]*inv0), totf32(cO[nt][1]*inv0));
            *(float2*)&upd[(size_t)(r + 8) * HDIM + col] =
                make_float2(totf32(cO[nt][2]*inv1), totf32(cO[nt][3]*inv1));
        }
    }
}

// ---------------- fused 3-layer MLP ---------------------
#define MH1S 132
#define MH2S 68
#define MAS  36
#define MBS  136
#define MW2S 72
#define MW3S 264
#define MOFS_H2 (128*MH1S)
#define MOFS_ST (MOFS_H2 + 128*MH2S)
#define MOFS_BS (MOFS_ST + 128*MAS)
#define MOFS_W2 (MOFS_ST + 64*MW3S)
#define MLP_FLOATS (MOFS_W2 + 128*MW2S)

__global__ __launch_bounds__(512, 1)
void mlp_fused(const float* __restrict__ X,
               const float* __restrict__ W1, const float* __restrict__ b1,
               const float* __restrict__ W2, const float* __restrict__ b2,
               const float* __restrict__ W3, const float* __restrict__ b3,
               float* __restrict__ out) {
    extern __shared__ float sm[];
    float* H1  = sm;
    float* H2  = sm + MOFS_H2;
    float* As  = sm + MOFS_ST;
    float* Bs  = sm + MOFS_BS;
    float* W3s = sm + MOFS_ST;
    float* W2s = sm + MOFS_W2;

    const int t = threadIdx.x;
    const int w = t >> 5, l = t & 31, g = l >> 2, ti = l & 3;
    const int wm = w >> 2, wn = w & 3;
    const int bm = blockIdx.x * 128;

    #pragma unroll
    for (int j = 0; j < 4; j++) {
        int i = t + 512*j; int kr = i >> 4, n4 = (i & 15) * 4;
        cp16(&W2s[kr*MW2S + n4], &W2[kr*64 + n4]);
    }
    CP_COMMIT();

    const float* A = X + (size_t)bm * HDIM;
    float4 ra[2], rb[2];
    #pragma unroll
    for (int j = 0; j < 2; j++) { int i = t + 512*j;
        ra[j] = *(const float4*)&A[(size_t)(i>>3) * HDIM + (i&7)*4]; }
    #pragma unroll
    for (int j = 0; j < 2; j++) { int i = t + 512*j;
        rb[j] = *(const float4*)&W1[(size_t)(i>>5) * 128 + (i&31)*4]; }

    float c1[2][4][4] = {};
    for (int kt = 0; kt < HDIM; kt += 32) {
        #pragma unroll
        for (int j = 0; j < 2; j++) { int i = t + 512*j;
            *(float4*)&As[(i>>3)*MAS + (i&7)*4] = ra[j]; }
        #pragma unroll
        for (int j = 0; j < 2; j++) { int i = t + 512*j;
            *(float4*)&Bs[(i>>5)*MBS + (i&31)*4] = cvt4(rb[j]); }
        __syncthreads();
        if (kt + 32 < HDIM) {
            #pragma unroll
            for (int j = 0; j < 2; j++) { int i = t + 512*j;
                ra[j] = *(const float4*)&A[(size_t)(i>>3) * HDIM + kt + 32 + (i&7)*4]; }
            #pragma unroll
            for (int j = 0; j < 2; j++) { int i = t + 512*j;
                rb[j] = *(const float4*)&W1[(size_t)(kt + 32 + (i>>5)) * 128 + (i&31)*4]; }
        }
        #pragma unroll
        for (int ks = 0; ks < 4; ks++) {
            float a[2][4], bfr[4][2];
            #pragma unroll
            for (int mt = 0; mt < 2; mt++) {
                int r = wm*32 + mt*16;
                a[mt][0] = As[(r + g)     * MAS + ks*8 + ti];
                a[mt][1] = As[(r + g + 8) * MAS + ks*8 + ti];
                a[mt][2] = As[(r + g)     * MAS + ks*8 + ti + 4];
                a[mt][3] = As[(r + g + 8) * MAS + ks*8 + ti + 4];
            }
            #pragma unroll
            for (int nt = 0; nt < 4; nt++) {
                int cc = wn*32 + nt*8 + g;
                bfr[nt][0] = Bs[(ks*8 + ti)     * MBS + cc];
                bfr[nt][1] = Bs[(ks*8 + ti + 4) * MBS + cc];
            }
            #pragma unroll
            for (int mt = 0; mt < 2; mt++)
                #pragma unroll
                for (int nt = 0; nt < 4; nt++)
                    mma8(c1[mt][nt], a[mt], bfr[nt]);
        }
        __syncthreads();
    }
    #pragma unroll
    for (int mt = 0; mt < 2; mt++)
        #pragma unroll
        for (int nt = 0; nt < 4; nt++) {
            int row = wm*32 + mt*16 + g;
            int col = wn*32 + nt*8 + 2*ti;
            float bb0 = b1[col], bb1 = b1[col+1];
            float v0 = c1[mt][nt][0] + bb0, v1 = c1[mt][nt][1] + bb1;
            float v2 = c1[mt][nt][2] + bb0, v3 = c1[mt][nt][3] + bb1;
            v0 = totf32(v0 / (1.f + __expf(-v0))); v1 = totf32(v1 / (1.f + __expf(-v1)));
            v2 = totf32(v2 / (1.f + __expf(-v2))); v3 = totf32(v3 / (1.f + __expf(-v3)));
            *(float2*)&H1[row*MH1S + col]     = make_float2(v0, v1);
            *(float2*)&H1[(row+8)*MH1S + col] = make_float2(v2, v3);
        }
    __syncthreads();

    #pragma unroll
    for (int j = 0; j < 8; j++) {
        int i = t + 512*j; int kr = i >> 6, n4 = (i & 63) * 4;
        cp16(&W3s[kr*MW3S + n4], &W3[kr*256 + n4]);
    }
    CP_COMMIT();
    CP_WAIT1();
    __syncthreads();

    float c2[2][2][4] = {};
    #pragma unroll
    for (int ks = 0; ks < 16; ks++) {
        float a[2][4], bfr[2][2];
        #pragma unroll
        for (int mt = 0; mt < 2; mt++) {
            int r = wm*32 + mt*16;
            a[mt][0] = H1[(r + g)     * MH1S + ks*8 + ti];
            a[mt][1] = H1[(r + g + 8) * MH1S + ks*8 + ti];
            a[mt][2] = H1[(r + g)     * MH1S + ks*8 + ti + 4];
            a[mt][3] = H1[(r + g + 8) * MH1S + ks*8 + ti + 4];
        }
        #pragma unroll
        for (int nt = 0; nt < 2; nt++) {
            int cc = wn*16 + nt*8 + g;
            bfr[nt][0] = totf32(W2s[(ks*8 + ti)     * MW2S + cc]);
            bfr[nt][1] = totf32(W2s[(ks*8 + ti + 4) * MW2S + cc]);
        }
        #pragma unroll
        for (int mt = 0; mt < 2; mt++)
            #pragma unroll
            for (int nt = 0; nt < 2; nt++)
                mma8(c2[mt][nt], a[mt], bfr[nt]);
    }
    #pragma unroll
    for (int mt = 0; mt < 2; mt++)
        #pragma unroll
        for (int nt = 0; nt < 2; nt++) {
            int row = wm*32 + mt*16 + g;
            int col = wn*16 + nt*8 + 2*ti;
            float bb0 = b2[col], bb1 = b2[col+1];
            float v0 = c2[mt][nt][0] + bb0, v1 = c2[mt][nt][1] + bb1;
            float v2 = c2[mt][nt][2] + bb0, v3 = c2[mt][nt][3] + bb1;
            v0 = totf32(v0 / (1.f + __expf(-v0))); v1 = totf32(v1 / (1.f + __expf(-v1)));
            v2 = totf32(v2 / (1.f + __expf(-v2))); v3 = totf32(v3 / (1.f + __expf(-v3)));
            *(float2*)&H2[row*MH2S + col]     = make_float2(v0, v1);
            *(float2*)&H2[(row+8)*MH2S + col] = make_float2(v2, v3);
        }
    CP_WAIT0();
    __syncthreads();

    float c3[2][8][4] = {};
    #pragma unroll
    for (int ks = 0; ks < 8; ks++) {
        float a[2][4];
        #pragma unroll
        for (int mt = 0; mt < 2; mt++) {
            int r = wm*32 + mt*16;
            a[mt][0] = H2[(r + g)     * MH2S + ks*8 + ti];
            a[mt][1] = H2[(r + g + 8) * MH2S + ks*8 + ti];
            a[mt][2] = H2[(r + g)     * MH2S + ks*8 + ti + 4];
            a[mt][3] = H2[(r + g + 8) * MH2S + ks*8 + ti + 4];
        }
        #pragma unroll
        for (int nt = 0; nt < 8; nt++) {
            float bfr[2];
            int cc = wn*64 + nt*8 + g;
            bfr[0] = totf32(W3s[(ks*8 + ti)     * MW3S + cc]);
            bfr[1] = totf32(W3s[(ks*8 + ti + 4) * MW3S + cc]);
            mma8(c3[0][nt], a[0], bfr);
            mma8(c3[1][nt], a[1], bfr);
        }
    }
    #pragma unroll
    for (int mt = 0; mt < 2; mt++)
        #pragma unroll
        for (int nt = 0; nt < 8; nt++) {
            int row = bm + wm*32 + mt*16 + g;
            int col = wn*64 + nt*8 + 2*ti;
            float bb0 = b3[col], bb1 = b3[col+1];
            float v0 = c3[mt][nt][0] + bb0, v1 = c3[mt][nt][1] + bb1;
            float v2 = c3[mt][nt][2] + bb0, v3 = c3[mt][nt][3] + bb1;
            v0 = v0 / (1.f + __expf(-v0)); v1 = v1 / (1.f + __expf(-v1));
            v2 = v2 / (1.f + __expf(-v2)); v3 = v3 / (1.f + __expf(-v3));
            *(float2*)&out[(size_t)row * INDIM + col]     = make_float2(v0, v1);
            *(float2*)&out[(size_t)(row+8) * INDIM + col] = make_float2(v2, v3);
        }
}

// ---------------- launch ----------------
extern "C" void kernel_launch(void* const* d_in, const int* in_sizes, int n_in,
                              void* d_out, int out_size) {
    const float* pos  = (const float*)d_in[0];
    const float* feat = (const float*)d_in[1];
    const float* Wk   = (const float*)d_in[2];
    const float* Wq   = (const float*)d_in[3];
    const float* Wv   = (const float*)d_in[4];
    const float* W1   = (const float*)d_in[5];
    const float* b1   = (const float*)d_in[6];
    const float* W2   = (const float*)d_in[7];
    const float* b2   = (const float*)d_in[8];
    const float* W3   = (const float*)d_in[9];
    const float* b3   = (const float*)d_in[10];
    float* out = (float*)d_out;

    void* p;
    cudaGetSymbolAddress(&p, g_qkv);   float* qkv   = (float*)p;
    cudaGetSymbolAddress(&p, g_upd);   float* upd   = (float*)p;
    cudaGetSymbolAddress(&p, g_featr); float* featr = (float*)p;
    cudaGetSymbolAddress(&p, g_wcat);  float* wcat  = (float*)p;

    prep_round<<<(MTOK*INDIM/4 + INDIM*1536/4 + 255)/256, 256>>>(feat, Wq, Wk, Wv, featr, wcat);

    size_t gsh = (size_t)GEMM_FLOATS * sizeof(float);
    cudaFuncSetAttribute(qkv_gemm2, cudaFuncAttributeMaxDynamicSharedMemorySize, (int)gsh);
    qkv_gemm2<<<dim3(12, MTOK/128), 256, gsh>>>(featr, wcat, qkv);

    size_t ash = (size_t)ATT_FLOATS * sizeof(float);
    cudaFuncSetAttribute(attn_kernel, cudaFuncAttributeMaxDynamicSharedMemorySize, (int)ash);
    attn_kernel<<<dim3(SEQ/64, NHEADS, BATCH), 512, ash>>>(pos, qkv, upd);

    size_t msh = (size_t)MLP_FLOATS * sizeof(float);
    cudaFuncSetAttribute(mlp_fused, cudaFuncAttributeMaxDynamicSharedMemorySize, (int)msh);
    mlp_fused<<<MTOK/128, 512, msh>>>(upd, W1, b1, W2, b2, W3, b3, out);
}